// round 3
// baseline (speedup 1.0000x reference)
#include <cuda_runtime.h>
#include <cuda_bf16.h>
#include <cstdint>

// Problem constants
#define BB   4
#define CC   128
#define HH   128
#define WW   128
#define OO   256
#define KKK  9          // 3x3
#define KDIM 1152       // C*KK
#define HW   16384      // H*W

typedef unsigned long long ull;

// ---------------- scratch (no allocations allowed) ----------------
__device__ float g_xT[BB * HH * WW * CC];          // NHWC transposed x (33.5 MB)
__device__ float g_wT[KDIM * OO];                  // weight transposed [k][oc]
__device__ float g_w27[KDIM * 28];                 // combined offset+mod weights [k][28(pad)]
__device__ float g_posy[BB * HH * WW * KKK];
__device__ float g_posx[BB * HH * WW * KKK];
__device__ float g_mask[BB * HH * WW * KKK];

// ---------------- f32x2 helpers (sm_100+) ----------------
__device__ __forceinline__ ull pack2(float lo, float hi) {
    ull r; asm("mov.b64 %0, {%1, %2};" : "=l"(r) : "f"(lo), "f"(hi)); return r;
}
__device__ __forceinline__ float2 unpack2(ull v) {
    float2 r; asm("mov.b64 {%0, %1}, %2;" : "=f"(r.x), "=f"(r.y) : "l"(v)); return r;
}
__device__ __forceinline__ ull fma2(ull a, ull b, ull c) {
    ull d; asm("fma.rn.f32x2 %0, %1, %2, %3;" : "=l"(d) : "l"(a), "l"(b), "l"(c)); return d;
}

// ---------------- K0: NCHW -> NHWC transpose of x ----------------
__global__ void k_tx(const float* __restrict__ x) {
    __shared__ float t[32][33];
    int b  = blockIdx.z;
    int c0 = blockIdx.y * 32;
    int p0 = blockIdx.x * 32;
    int tx = threadIdx.x, ty = threadIdx.y;
#pragma unroll
    for (int i = 0; i < 32; i += 8)
        t[ty + i][tx] = x[(size_t)(b * CC + c0 + ty + i) * HW + p0 + tx];
    __syncthreads();
#pragma unroll
    for (int i = 0; i < 32; i += 8)
        g_xT[(size_t)(b * HW + p0 + ty + i) * CC + c0 + tx] = t[tx][ty + i];
}

// ---------------- K0b: weight prep ----------------
__global__ void k_prep(const float* __restrict__ ow, const float* __restrict__ mw,
                       const float* __restrict__ w) {
    int stride = gridDim.x * blockDim.x;
    for (int i = blockIdx.x * blockDim.x + threadIdx.x; i < KDIM * OO; i += stride) {
        int k = i >> 8; int oc = i & 255;
        g_wT[i] = w[oc * KDIM + k];
    }
    for (int i = blockIdx.x * blockDim.x + threadIdx.x; i < KDIM * 28; i += stride) {
        int k = i / 28; int oc = i - k * 28;
        float v = 0.f;
        if (oc < 18)      v = ow[oc * KDIM + k];
        else if (oc < 27) v = mw[(oc - 18) * KDIM + k];
        g_w27[i] = v;
    }
}

// ---------------- K1: offset/modulator conv -> positions & mask ----------------
__global__ void __launch_bounds__(128) k_stage1(const float* __restrict__ x,
                                                const float* __restrict__ ob,
                                                const float* __restrict__ mb) {
    __shared__ float xs[8 * 3 * 130];            // [ci][r][j], j = wx+1
    __shared__ __align__(16) float ws[8 * 9 * 28];
    int bi = blockIdx.x;
    int b  = bi >> 7;
    int ho = bi & 127;
    int wo = threadIdx.x;

    ull acc[14];
#pragma unroll
    for (int j = 0; j < 14; j++) acc[j] = pack2(0.f, 0.f);

    for (int cc = 0; cc < CC; cc += 8) {
        __syncthreads();
        for (int i = threadIdx.x; i < 2016; i += 128)
            ws[i] = g_w27[cc * 9 * 28 + i];
        for (int i = threadIdx.x; i < 3120; i += 128) {
            int ci = i / 390; int rem = i - ci * 390;
            int r = rem / 130; int j = rem - r * 130;
            int hy = ho - 1 + r; int wx = j - 1;
            float v = 0.f;
            if ((unsigned)hy < 128u && (unsigned)wx < 128u)
                v = x[(size_t)((b * CC + cc + ci) * HH + hy) * WW + wx];
            xs[i] = v;
        }
        __syncthreads();

        for (int ci = 0; ci < 8; ci++) {
            float xv[9];
#pragma unroll
            for (int r = 0; r < 3; r++)
#pragma unroll
                for (int kx = 0; kx < 3; kx++)
                    xv[r * 3 + kx] = xs[ci * 390 + r * 130 + wo + kx];
#pragma unroll
            for (int kk = 0; kk < 9; kk++) {
                ull xd = pack2(xv[kk], xv[kk]);
                const ulonglong2* wr = (const ulonglong2*)(ws + (ci * 9 + kk) * 28);
#pragma unroll
                for (int j = 0; j < 7; j++) {
                    ulonglong2 wp = wr[j];
                    acc[2 * j]     = fma2(wp.x, xd, acc[2 * j]);
                    acc[2 * j + 1] = fma2(wp.y, xd, acc[2 * j + 1]);
                }
            }
        }
    }

    float v27[28];
#pragma unroll
    for (int j = 0; j < 14; j++) {
        float2 p = unpack2(acc[j]);
        v27[2 * j] = p.x; v27[2 * j + 1] = p.y;
    }

    int pixbase = ((b * HH + ho) * WW + wo) * KKK;
#pragma unroll
    for (int kk = 0; kk < 9; kk++) {
        int ky = kk / 3, kx = kk % 3;
        float offy = v27[2 * kk]     + ob[2 * kk];
        float offx = v27[2 * kk + 1] + ob[2 * kk + 1];
        float mm   = v27[18 + kk]    + mb[kk];
        mm = 2.0f / (1.0f + expf(-mm));
        g_posy[pixbase + kk] = (float)(ho - 1 + ky) + offy;
        g_posx[pixbase + kk] = (float)(wo - 1 + kx) + offx;
        g_mask[pixbase + kk] = mm;
    }
}

// ---------------- K2: deformable gather + register-blocked GEMM ----------------
// block = 256 threads, M-tile = 32 pixels, N = 256, K = 1152, thread tile 4m x 8oc
#define MT    32
#define CS    36                      // col row stride (padded, 16B-aligned)
#define KC    32                      // weight chunk
#define COL_F (KDIM * CS)             // 41472 floats
#define WS_F  (KC * 256)              // 8192 floats
#define NTAP  (MT * KKK)              // 288
#define SMEM_BYTES ((COL_F + WS_F) * 4 + NTAP * 32)

__global__ void __launch_bounds__(256, 1) k_stage2(float* __restrict__ out) {
    extern __shared__ float smem[];
    float* col = smem;                          // [1152][36]
    float* ws  = smem + COL_F;                  // [KC][256]
    int4*   sIdx = (int4*)(smem + COL_F + WS_F);
    float4* sW   = (float4*)((char*)sIdx + NTAP * 16);

    int bi  = blockIdx.x;
    int b   = bi >> 9;
    int ho  = (bi >> 2) & 127;
    int wo0 = (bi & 3) << 5;
    int tid = threadIdx.x;

    // ---- phase 0: per-(m,kk) tap indices + premultiplied bilinear weights ----
    for (int tap = tid; tap < NTAP; tap += 256) {
        int m = tap / 9, kk = tap - m * 9;
        int wo = wo0 + m;
        int pix = ((b * HH + ho) * WW + wo) * KKK + kk;
        float py = g_posy[pix], px = g_posx[pix], mk = g_mask[pix];
        float y0f = floorf(py), x0f = floorf(px);
        float wy = py - y0f, wx = px - x0f;
        int iy0 = (int)y0f, ix0 = (int)x0f;
        int iy1 = iy0 + 1,  ix1 = ix0 + 1;
        bool vy0 = (unsigned)iy0 < 128u, vy1 = (unsigned)iy1 < 128u;
        bool vx0 = (unsigned)ix0 < 128u, vx1 = (unsigned)ix1 < 128u;
        int cy0 = min(max(iy0, 0), 127), cy1 = min(max(iy1, 0), 127);
        int cx0 = min(max(ix0, 0), 127), cx1 = min(max(ix1, 0), 127);
        float w00 = mk * (1.f - wy) * (1.f - wx) * ((vy0 && vx0) ? 1.f : 0.f);
        float w01 = mk * (1.f - wy) * wx         * ((vy0 && vx1) ? 1.f : 0.f);
        float w10 = mk * wy * (1.f - wx)         * ((vy1 && vx0) ? 1.f : 0.f);
        float w11 = mk * wy * wx                 * ((vy1 && vx1) ? 1.f : 0.f);
        sIdx[tap] = make_int4(((b * HH + cy0) * WW + cx0) * CC,
                              ((b * HH + cy0) * WW + cx1) * CC,
                              ((b * HH + cy1) * WW + cx0) * CC,
                              ((b * HH + cy1) * WW + cx1) * CC);
        sW[tap] = make_float4(w00, w01, w10, w11);
    }
    __syncthreads();

    // ---- phase 1: gather into col[k][m], k = c*9+kk ----
    for (int it = tid; it < NTAP * 8; it += 256) {
        int tap = it >> 3;
        int oct = it & 7;
        int c0  = oct << 4;             // 16 channels per item
        int m = tap / 9, kk = tap - (tap / 9) * 9;
        int4   ti = sIdx[tap];
        float4 tw = sW[tap];
        const float4* P0 = (const float4*)(g_xT + ti.x + c0);
        const float4* P1 = (const float4*)(g_xT + ti.y + c0);
        const float4* P2 = (const float4*)(g_xT + ti.z + c0);
        const float4* P3 = (const float4*)(g_xT + ti.w + c0);
        float* cw = col + (c0 * 9 + kk) * CS + m;   // k0 = c0*9+kk
#pragma unroll
        for (int q = 0; q < 4; q++) {
            float4 a = P0[q], e = P1[q], f = P2[q], g = P3[q];
            float4 r;
            r.x = fmaf(g.x, tw.w, fmaf(f.x, tw.z, fmaf(e.x, tw.y, a.x * tw.x)));
            r.y = fmaf(g.y, tw.w, fmaf(f.y, tw.z, fmaf(e.y, tw.y, a.y * tw.x)));
            r.z = fmaf(g.z, tw.w, fmaf(f.z, tw.z, fmaf(e.z, tw.y, a.z * tw.x)));
            r.w = fmaf(g.w, tw.w, fmaf(f.w, tw.z, fmaf(e.w, tw.y, a.w * tw.x)));
            // c = c0 + 4q + j  ->  k advances by 9 per channel -> 9*CS floats
            float* cq = cw + (4 * q) * 9 * CS;
            cq[0 * 9 * CS] = r.x;
            cq[1 * 9 * CS] = r.y;
            cq[2 * 9 * CS] = r.z;
            cq[3 * 9 * CS] = r.w;
        }
    }

    // ---- phase 2: GEMM, thread tile 4m x 8oc ----
    int tn  = tid >> 3;          // 0..31 -> oc0 = tn*8
    int tm  = tid & 7;           // 0..7  -> m0 = tm*4
    int oc0 = tn << 3;
    int m4  = tm << 2;

    ull acc[16];
#pragma unroll
    for (int j = 0; j < 16; j++) acc[j] = pack2(0.f, 0.f);

    // preload chunk 0 of weights into registers
    float4 pre[8];
    {
        const float4* src = (const float4*)g_wT;
#pragma unroll
        for (int j = 0; j < 8; j++) pre[j] = src[tid + 256 * j];
    }

    for (int kc = 0; kc < KDIM; kc += KC) {
        __syncthreads();                    // prev chunk consumed / col ready
        {
            float4* dst = (float4*)ws;
#pragma unroll
            for (int j = 0; j < 8; j++) dst[tid + 256 * j] = pre[j];
        }
        __syncthreads();
        if (kc + KC < KDIM) {
            const float4* src = (const float4*)(g_wT + (kc + KC) * 256);
#pragma unroll
            for (int j = 0; j < 8; j++) pre[j] = src[tid + 256 * j];
        }
#pragma unroll 4
        for (int kl = 0; kl < KC; kl++) {
            float4 cv = *(const float4*)(col + (kc + kl) * CS + m4);
            const ull* wrow = (const ull*)(ws + (kl << 8) + oc0);
            ull w0 = wrow[0], w1 = wrow[1], w2 = wrow[2], w3 = wrow[3];
            ull cm;
            cm = pack2(cv.x, cv.x);
            acc[0]  = fma2(w0, cm, acc[0]);  acc[1]  = fma2(w1, cm, acc[1]);
            acc[2]  = fma2(w2, cm, acc[2]);  acc[3]  = fma2(w3, cm, acc[3]);
            cm = pack2(cv.y, cv.y);
            acc[4]  = fma2(w0, cm, acc[4]);  acc[5]  = fma2(w1, cm, acc[5]);
            acc[6]  = fma2(w2, cm, acc[6]);  acc[7]  = fma2(w3, cm, acc[7]);
            cm = pack2(cv.z, cv.z);
            acc[8]  = fma2(w0, cm, acc[8]);  acc[9]  = fma2(w1, cm, acc[9]);
            acc[10] = fma2(w2, cm, acc[10]); acc[11] = fma2(w3, cm, acc[11]);
            cm = pack2(cv.w, cv.w);
            acc[12] = fma2(w0, cm, acc[12]); acc[13] = fma2(w1, cm, acc[13]);
            acc[14] = fma2(w2, cm, acc[14]); acc[15] = fma2(w3, cm, acc[15]);
        }
    }

    // ---- epilogue: transpose through smem for coalesced stores ----
    __syncthreads();
    float* so = col;                 // reuse: needs 256*33 = 8448 floats
#pragma unroll
    for (int mi = 0; mi < 4; mi++) {
        int m = m4 + mi;
#pragma unroll
        for (int oj = 0; oj < 4; oj++) {
            float2 p = unpack2(acc[mi * 4 + oj]);
            so[(oc0 + 2 * oj)     * 33 + m] = p.x;
            so[(oc0 + 2 * oj + 1) * 33 + m] = p.y;
        }
    }
    __syncthreads();
    size_t obase = (size_t)b * OO * HW + (size_t)ho * WW + wo0;
    for (int t = 0; t < 32; t++) {
        int idx = tid + 256 * t;
        int oc = idx >> 5, mm = idx & 31;
        out[obase + (size_t)oc * HW + mm] = so[oc * 33 + mm];
    }
}

// ---------------- host launcher ----------------
extern "C" void kernel_launch(void* const* d_in, const int* in_sizes, int n_in,
                              void* d_out, int out_size) {
    (void)in_sizes; (void)n_in; (void)out_size;
    const float* x  = (const float*)d_in[0];
    const float* ow = (const float*)d_in[1];
    const float* ob = (const float*)d_in[2];
    const float* mw = (const float*)d_in[3];
    const float* mb = (const float*)d_in[4];
    const float* w  = (const float*)d_in[5];
    float* out = (float*)d_out;

    cudaFuncSetAttribute(k_stage2, cudaFuncAttributeMaxDynamicSharedMemorySize, SMEM_BYTES);

    k_tx<<<dim3(HW / 32, CC / 32, BB), dim3(32, 8)>>>(x);
    k_prep<<<512, 256>>>(ow, mw, w);
    k_stage1<<<BB * HH, 128>>>(x, ob, mb);
    k_stage2<<<BB * HH * (WW / 32), 256, SMEM_BYTES>>>(out);
}

// round 6
// speedup vs baseline: 2.3622x; 2.3622x over previous
#include <cuda_runtime.h>
#include <cuda_bf16.h>
#include <cstdint>

#define BB 4
#define CC 128
#define HH 128
#define WW 128
#define OO 256
#define KKK 9
#define KDIM 1152
#define HW 16384

typedef unsigned long long ull;

__device__ float g_xT[BB * HW * CC];                    // NHWC x
__device__ __align__(1024) float g_wB36[36 * 8192];     // B frag image: [chunk][n=256][32 k] swizzled tf32
__device__ float g_w27[KDIM * 28];
__device__ float g_posy[BB * HW * KKK];
__device__ float g_posx[BB * HW * KKK];
__device__ float g_mask[BB * HW * KKK];

__device__ __forceinline__ ull pack2(float lo, float hi) {
    ull r; asm("mov.b64 %0, {%1, %2};" : "=l"(r) : "f"(lo), "f"(hi)); return r;
}
__device__ __forceinline__ float2 unpack2(ull v) {
    float2 r; asm("mov.b64 {%0, %1}, %2;" : "=f"(r.x), "=f"(r.y) : "l"(v)); return r;
}
__device__ __forceinline__ ull fma2(ull a, ull b, ull c) {
    ull d; asm("fma.rn.f32x2 %0, %1, %2, %3;" : "=l"(d) : "l"(a), "l"(b), "l"(c)); return d;
}
__device__ __forceinline__ uint32_t tf32r(float x) {
    uint32_t u; asm("cvt.rna.tf32.f32 %0, %1;" : "=r"(u) : "f"(x)); return u;
}
__device__ __forceinline__ uint32_t smem_u32(const void* p) {
    uint32_t a;
    asm("{ .reg .u64 t; cvta.to.shared.u64 t, %1; cvt.u32.u64 %0, t; }" : "=r"(a) : "l"(p));
    return a;
}

#define MBAR_INIT(mb, c) asm volatile("mbarrier.init.shared.b64 [%0], %1;" :: "r"(mb), "r"((uint32_t)(c)) : "memory")
#define MBAR_EXPECT_TX(mb, by) asm volatile("mbarrier.arrive.expect_tx.shared.b64 _, [%0], %1;" :: "r"(mb), "r"((uint32_t)(by)) : "memory")
#define MBAR_WAIT(mb, par) do {                                                   \
    uint32_t _m = (mb); uint32_t _p = (par); uint32_t _d;                         \
    asm volatile("{\n\t.reg .pred p;\n\t"                                         \
        "mbarrier.try_wait.parity.acquire.cta.shared::cta.b64 p, [%1], %2;\n\t"   \
        "selp.b32 %0, 1, 0, p;\n\t}" : "=r"(_d) : "r"(_m), "r"(_p) : "memory");   \
    if (!_d) {                                                                    \
        asm volatile("{\n\t.reg .pred P1;\n\t"                                    \
            "WL_%=:\n\t"                                                          \
            "mbarrier.try_wait.parity.acquire.cta.shared::cta.b64 P1, [%0], %1, 0x989680;\n\t" \
            "@P1 bra.uni WD_%=;\n\t"                                              \
            "bra.uni WL_%=;\n\t"                                                  \
            "WD_%=:\n\t}" :: "r"(_m), "r"(_p) : "memory");                        \
    }                                                                             \
} while (0)

__device__ __forceinline__ void bulk_g2s(uint32_t dst, const void* src, uint32_t bytes, uint32_t mb) {
    uint64_t g = (uint64_t)__cvta_generic_to_global(src);
    asm volatile("cp.async.bulk.shared::cta.global.mbarrier::complete_tx::bytes [%0], [%1], %2, [%3];"
                 :: "r"(dst), "l"(g), "r"(bytes), "r"(mb) : "memory");
}
__device__ __forceinline__ void ldsm_x4(uint32_t& r0, uint32_t& r1, uint32_t& r2, uint32_t& r3, uint32_t addr) {
    asm volatile("ldmatrix.sync.aligned.m8n8.x4.shared.b16 {%0,%1,%2,%3}, [%4];"
                 : "=r"(r0), "=r"(r1), "=r"(r2), "=r"(r3) : "r"(addr));
}
__device__ __forceinline__ void mma_tf32(float* c, const uint32_t* a, uint32_t b0, uint32_t b1) {
    asm volatile("mma.sync.aligned.m16n8k8.row.col.f32.tf32.tf32.f32 "
                 "{%0,%1,%2,%3}, {%4,%5,%6,%7}, {%8,%9}, {%0,%1,%2,%3};"
                 : "+f"(c[0]), "+f"(c[1]), "+f"(c[2]), "+f"(c[3])
                 : "r"(a[0]), "r"(a[1]), "r"(a[2]), "r"(a[3]), "r"(b0), "r"(b1));
}

// ---------------- K0: NCHW -> NHWC ----------------
__global__ void k_tx(const float* __restrict__ x) {
    __shared__ float t[32][33];
    int b = blockIdx.z, c0 = blockIdx.y * 32, p0 = blockIdx.x * 32;
    int tx = threadIdx.x, ty = threadIdx.y;
#pragma unroll
    for (int i = 0; i < 32; i += 8)
        t[ty + i][tx] = x[(size_t)(b * CC + c0 + ty + i) * HW + p0 + tx];
    __syncthreads();
#pragma unroll
    for (int i = 0; i < 32; i += 8)
        g_xT[(size_t)(b * HW + p0 + ty + i) * CC + c0 + tx] = t[tx][ty + i];
}

// ---------------- K0b: weight prep ----------------
// g_wB36: chunk ch (kk=ch>>2, c = (ch&3)*32 + kl): value tf32(w[n][c][kk]) stored at
//   ch*8192 + n*32 + ((kl>>2)^(n&7))*4 + (kl&3)     (floats; 16B-unit XOR swizzle)
__global__ void k_prep(const float* __restrict__ ow, const float* __restrict__ mw,
                       const float* __restrict__ w) {
    int stride = gridDim.x * blockDim.x;
    for (int i = blockIdx.x * blockDim.x + threadIdx.x; i < 36 * 8192; i += stride) {
        int ch = i >> 13, r = i & 8191;
        int n = r >> 5, kl = r & 31;
        int kk = ch >> 2;
        int c = ((ch & 3) << 5) + kl;
        float v = w[(n * CC + c) * KKK + kk];
        int fidx = (ch << 13) + (n << 5) + ((((kl >> 2) ^ (n & 7))) << 2) + (kl & 3);
        g_wB36[fidx] = __uint_as_float(tf32r(v));
    }
    for (int i = blockIdx.x * blockDim.x + threadIdx.x; i < KDIM * 28; i += stride) {
        int k = i / 28, oc = i - k * 28;
        float v = 0.f;
        if (oc < 18) v = ow[oc * KDIM + k];
        else if (oc < 27) v = mw[(oc - 18) * KDIM + k];
        g_w27[i] = v;
    }
}

// ---------------- K1: offset/modulator conv ----------------
__global__ void __launch_bounds__(128) k_stage1(const float* __restrict__ x,
                                                const float* __restrict__ ob,
                                                const float* __restrict__ mb) {
    __shared__ float xs[8 * 3 * 130];
    __shared__ __align__(16) float ws[8 * 9 * 28];
    int bi = blockIdx.x, b = bi >> 7, ho = bi & 127, wo = threadIdx.x;
    ull acc[14];
#pragma unroll
    for (int j = 0; j < 14; j++) acc[j] = pack2(0.f, 0.f);
    for (int cc = 0; cc < CC; cc += 8) {
        __syncthreads();
        for (int i = threadIdx.x; i < 2016; i += 128) ws[i] = g_w27[cc * 9 * 28 + i];
        for (int i = threadIdx.x; i < 3120; i += 128) {
            int ci = i / 390, rem = i - ci * 390;
            int r = rem / 130, j = rem - r * 130;
            int hy = ho - 1 + r, wx = j - 1;
            float v = 0.f;
            if ((unsigned)hy < 128u && (unsigned)wx < 128u)
                v = x[(size_t)((b * CC + cc + ci) * HH + hy) * WW + wx];
            xs[i] = v;
        }
        __syncthreads();
        for (int ci = 0; ci < 8; ci++) {
            float xv[9];
#pragma unroll
            for (int r = 0; r < 3; r++)
#pragma unroll
                for (int kx = 0; kx < 3; kx++)
                    xv[r * 3 + kx] = xs[ci * 390 + r * 130 + wo + kx];
#pragma unroll
            for (int kk = 0; kk < 9; kk++) {
                ull xd = pack2(xv[kk], xv[kk]);
                const ulonglong2* wr = (const ulonglong2*)(ws + (ci * 9 + kk) * 28);
#pragma unroll
                for (int j = 0; j < 7; j++) {
                    ulonglong2 wp = wr[j];
                    acc[2 * j]     = fma2(wp.x, xd, acc[2 * j]);
                    acc[2 * j + 1] = fma2(wp.y, xd, acc[2 * j + 1]);
                }
            }
        }
    }
    float v27[28];
#pragma unroll
    for (int j = 0; j < 14; j++) {
        float2 p = unpack2(acc[j]);
        v27[2 * j] = p.x; v27[2 * j + 1] = p.y;
    }
    int pixbase = ((b * HH + ho) * WW + wo) * KKK;
#pragma unroll
    for (int kk = 0; kk < 9; kk++) {
        int ky = kk / 3, kx = kk % 3;
        float offy = v27[2 * kk] + ob[2 * kk];
        float offx = v27[2 * kk + 1] + ob[2 * kk + 1];
        float mm = v27[18 + kk] + mb[kk];
        mm = 2.0f / (1.0f + expf(-mm));
        g_posy[pixbase + kk] = (float)(ho - 1 + ky) + offy;
        g_posx[pixbase + kk] = (float)(wo - 1 + kx) + offx;
        g_mask[pixbase + kk] = mm;
    }
}

// ---------------- K2: mma.sync tf32 deformable GEMM ----------------
// CTA = one (b,ho) row: M=128, N=256, K=1152 in 36 chunks of 32.
// 16 warps = 4(m) x 4(n); warp tile m32 x n64.
#define SM_A0 0
#define SM_A1 16384
#define SM_B0 32768
#define SM_B1 65536
#define SM_POS 98304
#define SM_MBAR 112128
#define SM_TOTAL 112192

__global__ void __launch_bounds__(512, 1) k_stage2(float* __restrict__ out) {
    extern __shared__ __align__(16) char smem[];
    uint32_t sb = smem_u32(smem);
    int tid = threadIdx.x, wid = tid >> 5, lid = tid & 31;
    int bi = blockIdx.x, b = bi >> 7, ho = bi & 127;

    uint32_t mbar0 = sb + SM_MBAR, mbar1 = sb + SM_MBAR + 8;

    if (tid == 0) { MBAR_INIT(mbar0, 1); MBAR_INIT(mbar1, 1); }
    {   // stage pos/mask: tap = m*9+kk
        int rowbase = bi * 1152;
        float* sPY = (float*)(smem + SM_POS);
        float* sPX = sPY + 1152;
        float* sMK = sPX + 1152;
        for (int i = tid; i < 1152; i += 512) {
            sPY[i] = g_posy[rowbase + i];
            sPX[i] = g_posx[rowbase + i];
            sMK[i] = g_mask[rowbase + i];
        }
    }
    __syncthreads();
    if (tid == 0) {
        MBAR_EXPECT_TX(mbar0, 32768); bulk_g2s(sb + SM_B0, g_wB36, 32768, mbar0);
        MBAR_EXPECT_TX(mbar1, 32768); bulk_g2s(sb + SM_B1, g_wB36 + 8192, 32768, mbar1);
    }

    const float* sPY = (const float*)(smem + SM_POS);
    const float* sPX = sPY + 1152;
    const float* sMK = sPX + 1152;
    const float* xb = g_xT + (size_t)b * HW * CC;

    int gm = tid >> 2;            // gather pixel 0..127
    int cg = tid & 3;             // channel group (8 ch)
    int cg2 = cg << 1;

    // gather one chunk into A slot
    auto gather = [&](int ch, uint32_t aslot) {
        int kk = ch >> 2;
        int cA = ((ch & 3) << 5) + (cg << 3);
        int tap = gm * 9 + kk;
        float py = sPY[tap], px = sPX[tap], mk = sMK[tap];
        float y0f = floorf(py), x0f = floorf(px);
        float fy = py - y0f, fx = px - x0f;
        int iy0 = (int)y0f, ix0 = (int)x0f;
        int iy1 = iy0 + 1, ix1 = ix0 + 1;
        bool vy0 = (unsigned)iy0 < 128u, vy1 = (unsigned)iy1 < 128u;
        bool vx0 = (unsigned)ix0 < 128u, vx1 = (unsigned)ix1 < 128u;
        int cy0 = min(max(iy0, 0), 127), cy1 = min(max(iy1, 0), 127);
        int cx0 = min(max(ix0, 0), 127), cx1 = min(max(ix1, 0), 127);
        float w00 = mk * (1.f - fy) * (1.f - fx) * ((vy0 && vx0) ? 1.f : 0.f);
        float w01 = mk * (1.f - fy) * fx         * ((vy0 && vx1) ? 1.f : 0.f);
        float w10 = mk * fy * (1.f - fx)         * ((vy1 && vx0) ? 1.f : 0.f);
        float w11 = mk * fy * fx                 * ((vy1 && vx1) ? 1.f : 0.f);
        const float4* P0 = (const float4*)(xb + (((cy0 << 7) + cx0) << 7) + cA);
        const float4* P1 = (const float4*)(xb + (((cy0 << 7) + cx1) << 7) + cA);
        const float4* P2 = (const float4*)(xb + (((cy1 << 7) + cx0) << 7) + cA);
        const float4* P3 = (const float4*)(xb + (((cy1 << 7) + cx1) << 7) + cA);
#pragma unroll
        for (int h = 0; h < 2; h++) {
            float4 a = P0[h], e = P1[h], f = P2[h], g = P3[h];
            float4 r;
            r.x = fmaf(g.x, w11, fmaf(f.x, w10, fmaf(e.x, w01, a.x * w00)));
            r.y = fmaf(g.y, w11, fmaf(f.y, w10, fmaf(e.y, w01, a.y * w00)));
            r.z = fmaf(g.z, w11, fmaf(f.z, w10, fmaf(e.z, w01, a.z * w00)));
            r.w = fmaf(g.w, w11, fmaf(f.w, w10, fmaf(e.w, w01, a.w * w00)));
            uint32_t u0 = tf32r(r.x), u1 = tf32r(r.y), u2 = tf32r(r.z), u3 = tf32r(r.w);
            uint32_t ad = aslot + (gm << 7) + (((cg2 + h) ^ (gm & 7)) << 4);
            asm volatile("st.shared.v4.b32 [%0], {%1, %2, %3, %4};"
                         :: "r"(ad), "r"(u0), "r"(u1), "r"(u2), "r"(u3) : "memory");
        }
    };

    float acc[2][8][4];
#pragma unroll
    for (int i = 0; i < 2; i++)
#pragma unroll
        for (int j = 0; j < 8; j++)
#pragma unroll
            for (int q = 0; q < 4; q++) acc[i][j][q] = 0.f;

    int warp_m = wid & 3, warp_n = wid >> 2;
    int l15 = lid & 15, lhi = lid >> 4;

    // prologue: gather chunk 0, wait B0
    gather(0, sb + SM_A0);
    __syncthreads();
    MBAR_WAIT(mbar0, 0);

    for (int j = 0; j < 36; j++) {
        uint32_t Ab = sb + ((j & 1) ? SM_A1 : SM_A0);
        uint32_t Bb = sb + ((j & 1) ? SM_B1 : SM_B0);
        if (j < 35) gather(j + 1, sb + (((j + 1) & 1) ? SM_A1 : SM_A0));
        // GEMM chunk j
#pragma unroll
        for (int s = 0; s < 4; s++) {
            int u = (s << 1) + lhi;
            uint32_t afr[2][4];
#pragma unroll
            for (int mf = 0; mf < 2; mf++) {
                int r = (warp_m << 5) + (mf << 4) + l15;
                uint32_t ad = Ab + (r << 7) + ((u ^ (r & 7)) << 4);
                ldsm_x4(afr[mf][0], afr[mf][1], afr[mf][2], afr[mf][3], ad);
            }
            uint32_t bfr[4][4];
#pragma unroll
            for (int g = 0; g < 4; g++) {
                int r = (warp_n << 6) + (g << 4) + l15;
                uint32_t bd = Bb + (r << 7) + ((u ^ (r & 7)) << 4);
                ldsm_x4(bfr[g][0], bfr[g][1], bfr[g][2], bfr[g][3], bd);
            }
#pragma unroll
            for (int mf = 0; mf < 2; mf++)
#pragma unroll
                for (int g = 0; g < 4; g++) {
                    mma_tf32(acc[mf][2 * g],     afr[mf], bfr[g][0], bfr[g][2]);
                    mma_tf32(acc[mf][2 * g + 1], afr[mf], bfr[g][1], bfr[g][3]);
                }
        }
        __syncthreads();
        if (j + 2 < 36 && tid == 0) {
            uint32_t mb = (j & 1) ? mbar1 : mbar0;
            MBAR_EXPECT_TX(mb, 32768);
            bulk_g2s(sb + ((j & 1) ? SM_B1 : SM_B0), g_wB36 + (size_t)(j + 2) * 8192, 32768, mb);
        }
        if (j < 35) {
            uint32_t mb = ((j + 1) & 1) ? mbar1 : mbar0;
            MBAR_WAIT(mb, (uint32_t)(((j + 1) >> 1) & 1));
        }
    }

    // epilogue: direct STG
    int grp = lid >> 2, tig = lid & 3;
#pragma unroll
    for (int mf = 0; mf < 2; mf++) {
#pragma unroll
        for (int nb = 0; nb < 8; nb++) {
            int mrow = (warp_m << 5) + (mf << 4) + grp;
            int n = (warp_n << 6) + (nb << 3) + (tig << 1);
            size_t o0 = ((size_t)(b * OO + n)) * HW + (ho << 7);
            out[o0 + mrow]           = acc[mf][nb][0];
            out[o0 + HW + mrow]      = acc[mf][nb][1];
            out[o0 + mrow + 8]       = acc[mf][nb][2];
            out[o0 + HW + mrow + 8]  = acc[mf][nb][3];
        }
    }
}

// ---------------- host ----------------
extern "C" void kernel_launch(void* const* d_in, const int* in_sizes, int n_in,
                              void* d_out, int out_size) {
    (void)in_sizes; (void)n_in; (void)out_size;
    const float* x  = (const float*)d_in[0];
    const float* ow = (const float*)d_in[1];
    const float* ob = (const float*)d_in[2];
    const float* mw = (const float*)d_in[3];
    const float* mb = (const float*)d_in[4];
    const float* w  = (const float*)d_in[5];
    float* out = (float*)d_out;

    cudaFuncSetAttribute(k_stage2, cudaFuncAttributeMaxDynamicSharedMemorySize, SM_TOTAL);

    k_tx<<<dim3(HW / 32, CC / 32, BB), dim3(32, 8)>>>(x);
    k_prep<<<512, 256>>>(ow, mw, w);
    k_stage1<<<BB * HH, 128>>>(x, ob, mb);
    k_stage2<<<BB * HH, 512, SM_TOTAL>>>(out);
}

// round 7
// speedup vs baseline: 2.7910x; 1.1815x over previous
#include <cuda_runtime.h>
#include <cuda_bf16.h>
#include <cstdint>

#define BB 4
#define CC 128
#define HH 128
#define WW 128
#define OO 256
#define KKK 9
#define KDIM 1152
#define HW 16384

typedef unsigned long long ull;

__device__ float g_xT[BB * HW * CC];                    // NHWC x
__device__ __align__(1024) float g_wB36[36 * 8192];     // stage2 B frag image (tf32, swizzled)
__device__ __align__(1024) float g_wS1[36 * 1024];      // stage1 B frag image (tf32, swizzled)
__device__ float g_posy[BB * HW * KKK];
__device__ float g_posx[BB * HW * KKK];
__device__ float g_mask[BB * HW * KKK];

__device__ __forceinline__ uint32_t tf32r(float x) {
    uint32_t u; asm("cvt.rna.tf32.f32 %0, %1;" : "=r"(u) : "f"(x)); return u;
}
__device__ __forceinline__ uint32_t smem_u32(const void* p) {
    uint32_t a;
    asm("{ .reg .u64 t; cvta.to.shared.u64 t, %1; cvt.u32.u64 %0, t; }" : "=r"(a) : "l"(p));
    return a;
}

#define MBAR_INIT(mb, c) asm volatile("mbarrier.init.shared.b64 [%0], %1;" :: "r"(mb), "r"((uint32_t)(c)) : "memory")
#define MBAR_EXPECT_TX(mb, by) asm volatile("mbarrier.arrive.expect_tx.shared.b64 _, [%0], %1;" :: "r"(mb), "r"((uint32_t)(by)) : "memory")
#define MBAR_WAIT(mb, par) do {                                                   \
    uint32_t _m = (mb); uint32_t _p = (par); uint32_t _d;                         \
    asm volatile("{\n\t.reg .pred p;\n\t"                                         \
        "mbarrier.try_wait.parity.acquire.cta.shared::cta.b64 p, [%1], %2;\n\t"   \
        "selp.b32 %0, 1, 0, p;\n\t}" : "=r"(_d) : "r"(_m), "r"(_p) : "memory");   \
    if (!_d) {                                                                    \
        asm volatile("{\n\t.reg .pred P1;\n\t"                                    \
            "WL_%=:\n\t"                                                          \
            "mbarrier.try_wait.parity.acquire.cta.shared::cta.b64 P1, [%0], %1, 0x989680;\n\t" \
            "@P1 bra.uni WD_%=;\n\t"                                              \
            "bra.uni WL_%=;\n\t"                                                  \
            "WD_%=:\n\t}" :: "r"(_m), "r"(_p) : "memory");                        \
    }                                                                             \
} while (0)

__device__ __forceinline__ void bulk_g2s(uint32_t dst, const void* src, uint32_t bytes, uint32_t mb) {
    uint64_t g = (uint64_t)__cvta_generic_to_global(src);
    asm volatile("cp.async.bulk.shared::cta.global.mbarrier::complete_tx::bytes [%0], [%1], %2, [%3];"
                 :: "r"(dst), "l"(g), "r"(bytes), "r"(mb) : "memory");
}
__device__ __forceinline__ void ldsm_x4(uint32_t& r0, uint32_t& r1, uint32_t& r2, uint32_t& r3, uint32_t addr) {
    asm volatile("ldmatrix.sync.aligned.m8n8.x4.shared.b16 {%0,%1,%2,%3}, [%4];"
                 : "=r"(r0), "=r"(r1), "=r"(r2), "=r"(r3) : "r"(addr));
}
__device__ __forceinline__ void mma_tf32(float* c, const uint32_t* a, uint32_t b0, uint32_t b1) {
    asm volatile("mma.sync.aligned.m16n8k8.row.col.f32.tf32.tf32.f32 "
                 "{%0,%1,%2,%3}, {%4,%5,%6,%7}, {%8,%9}, {%0,%1,%2,%3};"
                 : "+f"(c[0]), "+f"(c[1]), "+f"(c[2]), "+f"(c[3])
                 : "r"(a[0]), "r"(a[1]), "r"(a[2]), "r"(a[3]), "r"(b0), "r"(b1));
}

// ---------------- K0: NCHW -> NHWC ----------------
__global__ void k_tx(const float* __restrict__ x) {
    __shared__ float t[32][33];
    int b = blockIdx.z, c0 = blockIdx.y * 32, p0 = blockIdx.x * 32;
    int tx = threadIdx.x, ty = threadIdx.y;
#pragma unroll
    for (int i = 0; i < 32; i += 8)
        t[ty + i][tx] = x[(size_t)(b * CC + c0 + ty + i) * HW + p0 + tx];
    __syncthreads();
#pragma unroll
    for (int i = 0; i < 32; i += 8)
        g_xT[(size_t)(b * HW + p0 + ty + i) * CC + c0 + tx] = t[tx][ty + i];
}

// ---------------- K0b: weight prep ----------------
// Chunk ch: kk = ch>>2, c = (ch&3)*32 + kl.
// swizzled float index within a [rows][32k] tile: row*32 + ((kl>>2)^(row&7))*4 + (kl&3)
__global__ void k_prep(const float* __restrict__ ow, const float* __restrict__ mw,
                       const float* __restrict__ w) {
    int stride = gridDim.x * blockDim.x;
    for (int i = blockIdx.x * blockDim.x + threadIdx.x; i < 36 * 8192; i += stride) {
        int ch = i >> 13, r = i & 8191;
        int n = r >> 5, kl = r & 31;
        int kk = ch >> 2;
        int c = ((ch & 3) << 5) + kl;
        float v = w[(n * CC + c) * KKK + kk];
        int fidx = (ch << 13) + (n << 5) + ((((kl >> 2) ^ (n & 7))) << 2) + (kl & 3);
        g_wB36[fidx] = __uint_as_float(tf32r(v));
    }
    for (int i = blockIdx.x * blockDim.x + threadIdx.x; i < 36 * 1024; i += stride) {
        int ch = i >> 10, r = i & 1023;
        int n = r >> 5, kl = r & 31;
        int kk = ch >> 2;
        int c = ((ch & 3) << 5) + kl;
        float v = 0.f;
        if (n < 18)      v = ow[n * KDIM + c * KKK + kk];
        else if (n < 27) v = mw[(n - 18) * KDIM + c * KKK + kk];
        int fidx = (ch << 10) + (n << 5) + ((((kl >> 2) ^ (n & 7))) << 2) + (kl & 3);
        g_wS1[fidx] = __uint_as_float(tf32r(v));
    }
}

// ---------------- K1: tensorized offset/modulator conv ----------------
// CTA = one (b,ho) row: M=128 pixels, N=32 (27 used), K=1152 in 36 chunks of 32.
// 8 warps, warp tile m16 x n32. B fully smem-resident (144KB, one bulk copy).
#define S1_B    0
#define S1_A0   147456
#define S1_A1   163840
#define S1_OUT  180224
#define S1_MBAR 197120
#define S1_TOTAL 197152

__global__ void __launch_bounds__(256, 1) k_stage1t(const float* __restrict__ ob_,
                                                    const float* __restrict__ mb_) {
    extern __shared__ __align__(16) char smem[];
    uint32_t sb = smem_u32(smem);
    int tid = threadIdx.x, wid = tid >> 5, lid = tid & 31;
    int bi = blockIdx.x, b = bi >> 7, ho = bi & 127;

    uint32_t mbar = sb + S1_MBAR;
    if (tid == 0) MBAR_INIT(mbar, 1);
    __syncthreads();
    if (tid == 0) { MBAR_EXPECT_TX(mbar, 147456); bulk_g2s(sb + S1_B, g_wS1, 147456, mbar); }

    const float* xb = g_xT + (size_t)b * HW * CC;
    int l15 = lid & 15, lhi = lid >> 4;
    int uu = lid & 7;           // 16B channel unit within chunk
    int rsub = lid >> 3;        // 0..3

    // coalesced im2col copy of one chunk into an A slot (each LDG.128 = 4 full 128B rows)
    auto gather1 = [&](int ch, uint32_t aslot) {
        int kk = ch >> 2;
        int ky = kk / 3, kx = kk - ky * 3;
        int c0 = (ch & 3) << 5;
        int hy = ho - 1 + ky;
        bool rowok = (unsigned)hy < 128u;
#pragma unroll
        for (int it = 0; it < 4; it++) {
            int m = (wid << 4) + (it << 2) + rsub;
            int wx = m - 1 + kx;
            bool ok = rowok && ((unsigned)wx < 128u);
            float4 v = make_float4(0.f, 0.f, 0.f, 0.f);
            if (ok) v = *(const float4*)(xb + (((hy << 7) + wx) << 7) + c0 + (uu << 2));
            uint32_t u0 = tf32r(v.x), u1 = tf32r(v.y), u2 = tf32r(v.z), u3 = tf32r(v.w);
            uint32_t ad = aslot + (m << 7) + ((uu ^ (m & 7)) << 4);
            asm volatile("st.shared.v4.b32 [%0], {%1, %2, %3, %4};"
                         :: "r"(ad), "r"(u0), "r"(u1), "r"(u2), "r"(u3) : "memory");
        }
    };

    float acc[4][4];
#pragma unroll
    for (int i = 0; i < 4; i++)
#pragma unroll
        for (int q = 0; q < 4; q++) acc[i][q] = 0.f;

    gather1(0, sb + S1_A0);
    __syncthreads();
    MBAR_WAIT(mbar, 0);

    for (int j = 0; j < 36; j++) {
        uint32_t Ab = sb + ((j & 1) ? S1_A1 : S1_A0);
        uint32_t Bb = sb + S1_B + (j << 12);
        if (j < 35) gather1(j + 1, sb + (((j + 1) & 1) ? S1_A1 : S1_A0));
#pragma unroll
        for (int s = 0; s < 4; s++) {
            int u = (s << 1) + lhi;
            uint32_t afr[4];
            {
                int r = (wid << 4) + l15;
                uint32_t ad = Ab + (r << 7) + ((u ^ (r & 7)) << 4);
                ldsm_x4(afr[0], afr[1], afr[2], afr[3], ad);
            }
            uint32_t bfr[2][4];
#pragma unroll
            for (int g = 0; g < 2; g++) {
                int r = (g << 4) + l15;
                uint32_t bd = Bb + (r << 7) + ((u ^ (r & 7)) << 4);
                ldsm_x4(bfr[g][0], bfr[g][1], bfr[g][2], bfr[g][3], bd);
            }
            mma_tf32(acc[0], afr, bfr[0][0], bfr[0][2]);
            mma_tf32(acc[1], afr, bfr[0][1], bfr[0][3]);
            mma_tf32(acc[2], afr, bfr[1][0], bfr[1][2]);
            mma_tf32(acc[3], afr, bfr[1][1], bfr[1][3]);
        }
        __syncthreads();
    }

    // epilogue: acc -> smem [32n][132m], then pos/mask math
    float* sOut = (float*)(smem + S1_OUT);
    int grp = lid >> 2, tig = lid & 3;
    int row0 = (wid << 4) + grp;
#pragma unroll
    for (int nb = 0; nb < 4; nb++) {
        int nb8 = nb << 3;
        sOut[(nb8 + (tig << 1)) * 132 + row0]         = acc[nb][0];
        sOut[(nb8 + (tig << 1) + 1) * 132 + row0]     = acc[nb][1];
        sOut[(nb8 + (tig << 1)) * 132 + row0 + 8]     = acc[nb][2];
        sOut[(nb8 + (tig << 1) + 1) * 132 + row0 + 8] = acc[nb][3];
    }
    __syncthreads();
    if (tid < 128) {
        int m = tid;
        int pixbase = (bi << 7) * 9 + m * 9;
#pragma unroll
        for (int kk = 0; kk < 9; kk++) {
            int ky = kk / 3, kx = kk - ky * 3;
            float vy = sOut[(2 * kk) * 132 + m] + ob_[2 * kk];
            float vx = sOut[(2 * kk + 1) * 132 + m] + ob_[2 * kk + 1];
            float vm = sOut[(18 + kk) * 132 + m] + mb_[kk];
            vm = 2.0f / (1.0f + expf(-vm));
            g_posy[pixbase + kk] = (float)(ho - 1 + ky) + vy;
            g_posx[pixbase + kk] = (float)(m - 1 + kx) + vx;
            g_mask[pixbase + kk] = vm;
        }
    }
}

// ---------------- K2: mma.sync tf32 deformable GEMM (unchanged from R6) ----------------
#define SM_A0 0
#define SM_A1 16384
#define SM_B0 32768
#define SM_B1 65536
#define SM_POS 98304
#define SM_MBAR 112128
#define SM_TOTAL 112192

__global__ void __launch_bounds__(512, 1) k_stage2(float* __restrict__ out) {
    extern __shared__ __align__(16) char smem[];
    uint32_t sb = smem_u32(smem);
    int tid = threadIdx.x, wid = tid >> 5, lid = tid & 31;
    int bi = blockIdx.x, b = bi >> 7, ho = bi & 127;

    uint32_t mbar0 = sb + SM_MBAR, mbar1 = sb + SM_MBAR + 8;

    if (tid == 0) { MBAR_INIT(mbar0, 1); MBAR_INIT(mbar1, 1); }
    {
        int rowbase = bi * 1152;
        float* sPY = (float*)(smem + SM_POS);
        float* sPX = sPY + 1152;
        float* sMK = sPX + 1152;
        for (int i = tid; i < 1152; i += 512) {
            sPY[i] = g_posy[rowbase + i];
            sPX[i] = g_posx[rowbase + i];
            sMK[i] = g_mask[rowbase + i];
        }
    }
    __syncthreads();
    if (tid == 0) {
        MBAR_EXPECT_TX(mbar0, 32768); bulk_g2s(sb + SM_B0, g_wB36, 32768, mbar0);
        MBAR_EXPECT_TX(mbar1, 32768); bulk_g2s(sb + SM_B1, g_wB36 + 8192, 32768, mbar1);
    }

    const float* sPY = (const float*)(smem + SM_POS);
    const float* sPX = sPY + 1152;
    const float* sMK = sPX + 1152;
    const float* xb = g_xT + (size_t)b * HW * CC;

    int gm = tid >> 2;
    int cg = tid & 3;
    int cg2 = cg << 1;

    auto gather = [&](int ch, uint32_t aslot) {
        int kk = ch >> 2;
        int cA = ((ch & 3) << 5) + (cg << 3);
        int tap = gm * 9 + kk;
        float py = sPY[tap], px = sPX[tap], mk = sMK[tap];
        float y0f = floorf(py), x0f = floorf(px);
        float fy = py - y0f, fx = px - x0f;
        int iy0 = (int)y0f, ix0 = (int)x0f;
        int iy1 = iy0 + 1, ix1 = ix0 + 1;
        bool vy0 = (unsigned)iy0 < 128u, vy1 = (unsigned)iy1 < 128u;
        bool vx0 = (unsigned)ix0 < 128u, vx1 = (unsigned)ix1 < 128u;
        int cy0 = min(max(iy0, 0), 127), cy1 = min(max(iy1, 0), 127);
        int cx0 = min(max(ix0, 0), 127), cx1 = min(max(ix1, 0), 127);
        float w00 = mk * (1.f - fy) * (1.f - fx) * ((vy0 && vx0) ? 1.f : 0.f);
        float w01 = mk * (1.f - fy) * fx         * ((vy0 && vx1) ? 1.f : 0.f);
        float w10 = mk * fy * (1.f - fx)         * ((vy1 && vx0) ? 1.f : 0.f);
        float w11 = mk * fy * fx                 * ((vy1 && vx1) ? 1.f : 0.f);
        const float4* P0 = (const float4*)(xb + (((cy0 << 7) + cx0) << 7) + cA);
        const float4* P1 = (const float4*)(xb + (((cy0 << 7) + cx1) << 7) + cA);
        const float4* P2 = (const float4*)(xb + (((cy1 << 7) + cx0) << 7) + cA);
        const float4* P3 = (const float4*)(xb + (((cy1 << 7) + cx1) << 7) + cA);
#pragma unroll
        for (int h = 0; h < 2; h++) {
            float4 a = P0[h], e = P1[h], f = P2[h], g = P3[h];
            float4 r;
            r.x = fmaf(g.x, w11, fmaf(f.x, w10, fmaf(e.x, w01, a.x * w00)));
            r.y = fmaf(g.y, w11, fmaf(f.y, w10, fmaf(e.y, w01, a.y * w00)));
            r.z = fmaf(g.z, w11, fmaf(f.z, w10, fmaf(e.z, w01, a.z * w00)));
            r.w = fmaf(g.w, w11, fmaf(f.w, w10, fmaf(e.w, w01, a.w * w00)));
            uint32_t u0 = tf32r(r.x), u1 = tf32r(r.y), u2 = tf32r(r.z), u3 = tf32r(r.w);
            uint32_t ad = aslot + (gm << 7) + (((cg2 + h) ^ (gm & 7)) << 4);
            asm volatile("st.shared.v4.b32 [%0], {%1, %2, %3, %4};"
                         :: "r"(ad), "r"(u0), "r"(u1), "r"(u2), "r"(u3) : "memory");
        }
    };

    float acc[2][8][4];
#pragma unroll
    for (int i = 0; i < 2; i++)
#pragma unroll
        for (int j = 0; j < 8; j++)
#pragma unroll
            for (int q = 0; q < 4; q++) acc[i][j][q] = 0.f;

    int warp_m = wid & 3, warp_n = wid >> 2;
    int l15 = lid & 15, lhi = lid >> 4;

    gather(0, sb + SM_A0);
    __syncthreads();
    MBAR_WAIT(mbar0, 0);

    for (int j = 0; j < 36; j++) {
        uint32_t Ab = sb + ((j & 1) ? SM_A1 : SM_A0);
        uint32_t Bb = sb + ((j & 1) ? SM_B1 : SM_B0);
        if (j < 35) gather(j + 1, sb + (((j + 1) & 1) ? SM_A1 : SM_A0));
#pragma unroll
        for (int s = 0; s < 4; s++) {
            int u = (s << 1) + lhi;
            uint32_t afr[2][4];
#pragma unroll
            for (int mf = 0; mf < 2; mf++) {
                int r = (warp_m << 5) + (mf << 4) + l15;
                uint32_t ad = Ab + (r << 7) + ((u ^ (r & 7)) << 4);
                ldsm_x4(afr[mf][0], afr[mf][1], afr[mf][2], afr[mf][3], ad);
            }
            uint32_t bfr[4][4];
#pragma unroll
            for (int g = 0; g < 4; g++) {
                int r = (warp_n << 6) + (g << 4) + l15;
                uint32_t bd = Bb + (r << 7) + ((u ^ (r & 7)) << 4);
                ldsm_x4(bfr[g][0], bfr[g][1], bfr[g][2], bfr[g][3], bd);
            }
#pragma unroll
            for (int mf = 0; mf < 2; mf++)
#pragma unroll
                for (int g = 0; g < 4; g++) {
                    mma_tf32(acc[mf][2 * g],     afr[mf], bfr[g][0], bfr[g][2]);
                    mma_tf32(acc[mf][2 * g + 1], afr[mf], bfr[g][1], bfr[g][3]);
                }
        }
        __syncthreads();
        if (j + 2 < 36 && tid == 0) {
            uint32_t mb = (j & 1) ? mbar1 : mbar0;
            MBAR_EXPECT_TX(mb, 32768);
            bulk_g2s(sb + ((j & 1) ? SM_B1 : SM_B0), g_wB36 + (size_t)(j + 2) * 8192, 32768, mb);
        }
        if (j < 35) {
            uint32_t mb = ((j + 1) & 1) ? mbar1 : mbar0;
            MBAR_WAIT(mb, (uint32_t)(((j + 1) >> 1) & 1));
        }
    }

    int grp = lid >> 2, tig = lid & 3;
#pragma unroll
    for (int mf = 0; mf < 2; mf++) {
#pragma unroll
        for (int nb = 0; nb < 8; nb++) {
            int mrow = (warp_m << 5) + (mf << 4) + grp;
            int n = (warp_n << 6) + (nb << 3) + (tig << 1);
            size_t o0 = ((size_t)(b * OO + n)) * HW + (ho << 7);
            out[o0 + mrow]           = acc[mf][nb][0];
            out[o0 + HW + mrow]      = acc[mf][nb][1];
            out[o0 + mrow + 8]       = acc[mf][nb][2];
            out[o0 + HW + mrow + 8]  = acc[mf][nb][3];
        }
    }
}

// ---------------- host ----------------
extern "C" void kernel_launch(void* const* d_in, const int* in_sizes, int n_in,
                              void* d_out, int out_size) {
    (void)in_sizes; (void)n_in; (void)out_size;
    const float* x  = (const float*)d_in[0];
    const float* ow = (const float*)d_in[1];
    const float* ob = (const float*)d_in[2];
    const float* mw = (const float*)d_in[3];
    const float* mb = (const float*)d_in[4];
    const float* w  = (const float*)d_in[5];
    float* out = (float*)d_out;

    cudaFuncSetAttribute(k_stage1t, cudaFuncAttributeMaxDynamicSharedMemorySize, S1_TOTAL);
    cudaFuncSetAttribute(k_stage2, cudaFuncAttributeMaxDynamicSharedMemorySize, SM_TOTAL);

    k_tx<<<dim3(HW / 32, CC / 32, BB), dim3(32, 8)>>>(x);
    k_prep<<<512, 256>>>(ow, mw, w);
    k_stage1t<<<BB * HH, 256, S1_TOTAL>>>(ob, mb);
    k_stage2<<<BB * HH, 512, SM_TOTAL>>>(out);
}

// round 8
// speedup vs baseline: 3.3927x; 1.2156x over previous
#include <cuda_runtime.h>
#include <cuda_bf16.h>
#include <cstdint>

#define BB 4
#define CC 128
#define HH 128
#define WW 128
#define OO 256
#define KKK 9
#define KDIM 1152
#define HW 16384

typedef unsigned long long ull;

__device__ float g_xT[BB * HW * CC];                    // NHWC x
__device__ __align__(1024) float g_wB36[36 * 8192];     // stage2 B frag image (tf32, swizzled)
__device__ __align__(1024) float g_wS1[36 * 1024];      // stage1 B frag image (tf32, swizzled)
__device__ float g_posy[BB * HW * KKK];
__device__ float g_posx[BB * HW * KKK];
__device__ float g_mask[BB * HW * KKK];

__device__ __forceinline__ uint32_t tf32r(float x) {
    uint32_t u; asm("cvt.rna.tf32.f32 %0, %1;" : "=r"(u) : "f"(x)); return u;
}
__device__ __forceinline__ uint32_t smem_u32(const void* p) {
    uint32_t a;
    asm("{ .reg .u64 t; cvta.to.shared.u64 t, %1; cvt.u32.u64 %0, t; }" : "=r"(a) : "l"(p));
    return a;
}

#define MBAR_INIT(mb, c) asm volatile("mbarrier.init.shared.b64 [%0], %1;" :: "r"(mb), "r"((uint32_t)(c)) : "memory")
#define MBAR_EXPECT_TX(mb, by) asm volatile("mbarrier.arrive.expect_tx.shared.b64 _, [%0], %1;" :: "r"(mb), "r"((uint32_t)(by)) : "memory")
#define MBAR_WAIT(mb, par) do {                                                   \
    uint32_t _m = (mb); uint32_t _p = (par); uint32_t _d;                         \
    asm volatile("{\n\t.reg .pred p;\n\t"                                         \
        "mbarrier.try_wait.parity.acquire.cta.shared::cta.b64 p, [%1], %2;\n\t"   \
        "selp.b32 %0, 1, 0, p;\n\t}" : "=r"(_d) : "r"(_m), "r"(_p) : "memory");   \
    if (!_d) {                                                                    \
        asm volatile("{\n\t.reg .pred P1;\n\t"                                    \
            "WL_%=:\n\t"                                                          \
            "mbarrier.try_wait.parity.acquire.cta.shared::cta.b64 P1, [%0], %1, 0x989680;\n\t" \
            "@P1 bra.uni WD_%=;\n\t"                                              \
            "bra.uni WL_%=;\n\t"                                                  \
            "WD_%=:\n\t}" :: "r"(_m), "r"(_p) : "memory");                        \
    }                                                                             \
} while (0)

__device__ __forceinline__ void bulk_g2s(uint32_t dst, const void* src, uint32_t bytes, uint32_t mb) {
    uint64_t g = (uint64_t)__cvta_generic_to_global(src);
    asm volatile("cp.async.bulk.shared::cta.global.mbarrier::complete_tx::bytes [%0], [%1], %2, [%3];"
                 :: "r"(dst), "l"(g), "r"(bytes), "r"(mb) : "memory");
}
__device__ __forceinline__ void ldsm_x4(uint32_t& r0, uint32_t& r1, uint32_t& r2, uint32_t& r3, uint32_t addr) {
    asm volatile("ldmatrix.sync.aligned.m8n8.x4.shared.b16 {%0,%1,%2,%3}, [%4];"
                 : "=r"(r0), "=r"(r1), "=r"(r2), "=r"(r3) : "r"(addr));
}
__device__ __forceinline__ void mma_tf32(float* c, const uint32_t* a, uint32_t b0, uint32_t b1) {
    asm volatile("mma.sync.aligned.m16n8k8.row.col.f32.tf32.tf32.f32 "
                 "{%0,%1,%2,%3}, {%4,%5,%6,%7}, {%8,%9}, {%0,%1,%2,%3};"
                 : "+f"(c[0]), "+f"(c[1]), "+f"(c[2]), "+f"(c[3])
                 : "r"(a[0]), "r"(a[1]), "r"(a[2]), "r"(a[3]), "r"(b0), "r"(b1));
}

// ---------------- K0: NCHW -> NHWC ----------------
__global__ void k_tx(const float* __restrict__ x) {
    __shared__ float t[32][33];
    int b = blockIdx.z, c0 = blockIdx.y * 32, p0 = blockIdx.x * 32;
    int tx = threadIdx.x, ty = threadIdx.y;
#pragma unroll
    for (int i = 0; i < 32; i += 8)
        t[ty + i][tx] = x[(size_t)(b * CC + c0 + ty + i) * HW + p0 + tx];
    __syncthreads();
#pragma unroll
    for (int i = 0; i < 32; i += 8)
        g_xT[(size_t)(b * HW + p0 + ty + i) * CC + c0 + tx] = t[tx][ty + i];
}

// ---------------- K0b: weight prep ----------------
__global__ void k_prep(const float* __restrict__ ow, const float* __restrict__ mw,
                       const float* __restrict__ w) {
    int stride = gridDim.x * blockDim.x;
    for (int i = blockIdx.x * blockDim.x + threadIdx.x; i < 36 * 8192; i += stride) {
        int ch = i >> 13, r = i & 8191;
        int n = r >> 5, kl = r & 31;
        int kk = ch >> 2;
        int c = ((ch & 3) << 5) + kl;
        float v = w[(n * CC + c) * KKK + kk];
        int fidx = (ch << 13) + (n << 5) + ((((kl >> 2) ^ (n & 7))) << 2) + (kl & 3);
        g_wB36[fidx] = __uint_as_float(tf32r(v));
    }
    for (int i = blockIdx.x * blockDim.x + threadIdx.x; i < 36 * 1024; i += stride) {
        int ch = i >> 10, r = i & 1023;
        int n = r >> 5, kl = r & 31;
        int kk = ch >> 2;
        int c = ((ch & 3) << 5) + kl;
        float v = 0.f;
        if (n < 18)      v = ow[n * KDIM + c * KKK + kk];
        else if (n < 27) v = mw[(n - 18) * KDIM + c * KKK + kk];
        int fidx = (ch << 10) + (n << 5) + ((((kl >> 2) ^ (n & 7))) << 2) + (kl & 3);
        g_wS1[fidx] = __uint_as_float(tf32r(v));
    }
}

// ---------------- K1: tensorized offset/modulator conv (unchanged from R7) ----------------
#define S1_B    0
#define S1_A0   147456
#define S1_A1   163840
#define S1_OUT  180224
#define S1_MBAR 197120
#define S1_TOTAL 197152

__global__ void __launch_bounds__(256, 1) k_stage1t(const float* __restrict__ ob_,
                                                    const float* __restrict__ mb_) {
    extern __shared__ __align__(16) char smem[];
    uint32_t sb = smem_u32(smem);
    int tid = threadIdx.x, wid = tid >> 5, lid = tid & 31;
    int bi = blockIdx.x, b = bi >> 7, ho = bi & 127;

    uint32_t mbar = sb + S1_MBAR;
    if (tid == 0) MBAR_INIT(mbar, 1);
    __syncthreads();
    if (tid == 0) { MBAR_EXPECT_TX(mbar, 147456); bulk_g2s(sb + S1_B, g_wS1, 147456, mbar); }

    const float* xb = g_xT + (size_t)b * HW * CC;
    int l15 = lid & 15, lhi = lid >> 4;
    int uu = lid & 7;
    int rsub = lid >> 3;

    auto gather1 = [&](int ch, uint32_t aslot) {
        int kk = ch >> 2;
        int ky = kk / 3, kx = kk - ky * 3;
        int c0 = (ch & 3) << 5;
        int hy = ho - 1 + ky;
        bool rowok = (unsigned)hy < 128u;
#pragma unroll
        for (int it = 0; it < 4; it++) {
            int m = (wid << 4) + (it << 2) + rsub;
            int wx = m - 1 + kx;
            bool ok = rowok && ((unsigned)wx < 128u);
            float4 v = make_float4(0.f, 0.f, 0.f, 0.f);
            if (ok) v = *(const float4*)(xb + (((hy << 7) + wx) << 7) + c0 + (uu << 2));
            uint32_t u0 = tf32r(v.x), u1 = tf32r(v.y), u2 = tf32r(v.z), u3 = tf32r(v.w);
            uint32_t ad = aslot + (m << 7) + ((uu ^ (m & 7)) << 4);
            asm volatile("st.shared.v4.b32 [%0], {%1, %2, %3, %4};"
                         :: "r"(ad), "r"(u0), "r"(u1), "r"(u2), "r"(u3) : "memory");
        }
    };

    float acc[4][4];
#pragma unroll
    for (int i = 0; i < 4; i++)
#pragma unroll
        for (int q = 0; q < 4; q++) acc[i][q] = 0.f;

    gather1(0, sb + S1_A0);
    __syncthreads();
    MBAR_WAIT(mbar, 0);

    for (int j = 0; j < 36; j++) {
        uint32_t Ab = sb + ((j & 1) ? S1_A1 : S1_A0);
        uint32_t Bb = sb + S1_B + (j << 12);
        if (j < 35) gather1(j + 1, sb + (((j + 1) & 1) ? S1_A1 : S1_A0));
#pragma unroll
        for (int s = 0; s < 4; s++) {
            int u = (s << 1) + lhi;
            uint32_t afr[4];
            {
                int r = (wid << 4) + l15;
                uint32_t ad = Ab + (r << 7) + ((u ^ (r & 7)) << 4);
                ldsm_x4(afr[0], afr[1], afr[2], afr[3], ad);
            }
            uint32_t bfr[2][4];
#pragma unroll
            for (int g = 0; g < 2; g++) {
                int r = (g << 4) + l15;
                uint32_t bd = Bb + (r << 7) + ((u ^ (r & 7)) << 4);
                ldsm_x4(bfr[g][0], bfr[g][1], bfr[g][2], bfr[g][3], bd);
            }
            mma_tf32(acc[0], afr, bfr[0][0], bfr[0][2]);
            mma_tf32(acc[1], afr, bfr[0][1], bfr[0][3]);
            mma_tf32(acc[2], afr, bfr[1][0], bfr[1][2]);
            mma_tf32(acc[3], afr, bfr[1][1], bfr[1][3]);
        }
        __syncthreads();
    }

    float* sOut = (float*)(smem + S1_OUT);
    int grp = lid >> 2, tig = lid & 3;
    int row0 = (wid << 4) + grp;
#pragma unroll
    for (int nb = 0; nb < 4; nb++) {
        int nb8 = nb << 3;
        sOut[(nb8 + (tig << 1)) * 132 + row0]         = acc[nb][0];
        sOut[(nb8 + (tig << 1) + 1) * 132 + row0]     = acc[nb][1];
        sOut[(nb8 + (tig << 1)) * 132 + row0 + 8]     = acc[nb][2];
        sOut[(nb8 + (tig << 1) + 1) * 132 + row0 + 8] = acc[nb][3];
    }
    __syncthreads();
    if (tid < 128) {
        int m = tid;
        int pixbase = (bi << 7) * 9 + m * 9;
#pragma unroll
        for (int kk = 0; kk < 9; kk++) {
            int ky = kk / 3, kx = kk - ky * 3;
            float vy = sOut[(2 * kk) * 132 + m] + ob_[2 * kk];
            float vx = sOut[(2 * kk + 1) * 132 + m] + ob_[2 * kk + 1];
            float vm = sOut[(18 + kk) * 132 + m] + mb_[kk];
            vm = 2.0f / (1.0f + expf(-vm));
            g_posy[pixbase + kk] = (float)(ho - 1 + ky) + vy;
            g_posx[pixbase + kk] = (float)(m - 1 + kx) + vx;
            g_mask[pixbase + kk] = vm;
        }
    }
}

// ---------------- K2: mma.sync tf32 deformable GEMM, M=64 tile, 2 CTAs/SM ----------------
// CTA = half a (b,ho) row: M=64, N=256, K=1152 in 36 chunks of 32.
// 8 warps = 2(m) x 4(n); warp tile m32 x n64. Tap tables precomputed in smem.
#define SM2_A0   0
#define SM2_A1   8192
#define SM2_B0   16384
#define SM2_B1   49152
#define SM2_TAP  81920                // int4[576] (9216B) + float4[576] (9216B)
#define SM2_MBAR 100352
#define SM2_TOTAL 100416

__global__ void __launch_bounds__(256, 2) k_stage2(float* __restrict__ out) {
    extern __shared__ __align__(16) char smem[];
    uint32_t sb = smem_u32(smem);
    int tid = threadIdx.x, wid = tid >> 5, lid = tid & 31;
    int bi = blockIdx.x;
    int b = bi >> 8, ho = (bi >> 1) & 127, wo0 = (bi & 1) << 6;

    uint32_t mbar0 = sb + SM2_MBAR, mbar1 = sb + SM2_MBAR + 8;
    if (tid == 0) { MBAR_INIT(mbar0, 1); MBAR_INIT(mbar1, 1); }

    // ---- precompute tap tables (64 pixels x 9 taps) ----
    int4*   sIdx = (int4*)(smem + SM2_TAP);
    float4* sW   = (float4*)(smem + SM2_TAP + 9216);
    for (int t = tid; t < 576; t += 256) {
        int m = t / 9, kk = t - m * 9;
        int wo = wo0 + m;
        int pix = ((b * HH + ho) * WW + wo) * KKK + kk;
        float py = g_posy[pix], px = g_posx[pix], mk = g_mask[pix];
        float y0f = floorf(py), x0f = floorf(px);
        float fy = py - y0f, fx = px - x0f;
        int iy0 = (int)y0f, ix0 = (int)x0f;
        int iy1 = iy0 + 1, ix1 = ix0 + 1;
        bool vy0 = (unsigned)iy0 < 128u, vy1 = (unsigned)iy1 < 128u;
        bool vx0 = (unsigned)ix0 < 128u, vx1 = (unsigned)ix1 < 128u;
        int cy0 = min(max(iy0, 0), 127), cy1 = min(max(iy1, 0), 127);
        int cx0 = min(max(ix0, 0), 127), cx1 = min(max(ix1, 0), 127);
        float w00 = mk * (1.f - fy) * (1.f - fx) * ((vy0 && vx0) ? 1.f : 0.f);
        float w01 = mk * (1.f - fy) * fx         * ((vy0 && vx1) ? 1.f : 0.f);
        float w10 = mk * fy * (1.f - fx)         * ((vy1 && vx0) ? 1.f : 0.f);
        float w11 = mk * fy * fx                 * ((vy1 && vx1) ? 1.f : 0.f);
        sIdx[t] = make_int4((((cy0 << 7) + cx0) << 7), (((cy0 << 7) + cx1) << 7),
                            (((cy1 << 7) + cx0) << 7), (((cy1 << 7) + cx1) << 7));
        sW[t] = make_float4(w00, w01, w10, w11);
    }
    __syncthreads();
    if (tid == 0) {
        MBAR_EXPECT_TX(mbar0, 32768); bulk_g2s(sb + SM2_B0, g_wB36, 32768, mbar0);
        MBAR_EXPECT_TX(mbar1, 32768); bulk_g2s(sb + SM2_B1, g_wB36 + 8192, 32768, mbar1);
    }

    const float* xb = g_xT + (size_t)b * HW * CC;
    int gm = tid >> 2;            // pixel 0..63
    int cg = tid & 3;             // channel group (8 ch)
    int cg2 = cg << 1;

    auto gather = [&](int ch, uint32_t aslot) {
        int cA = ((ch & 3) << 5) + (cg << 3);
        int t = gm * 9 + (ch >> 2);
        int4 ti = sIdx[t];
        float4 tw = sW[t];
        const float4* P0 = (const float4*)(xb + ti.x + cA);
        const float4* P1 = (const float4*)(xb + ti.y + cA);
        const float4* P2 = (const float4*)(xb + ti.z + cA);
        const float4* P3 = (const float4*)(xb + ti.w + cA);
#pragma unroll
        for (int h = 0; h < 2; h++) {
            float4 a = P0[h], e = P1[h], f = P2[h], g = P3[h];
            float4 r;
            r.x = fmaf(g.x, tw.w, fmaf(f.x, tw.z, fmaf(e.x, tw.y, a.x * tw.x)));
            r.y = fmaf(g.y, tw.w, fmaf(f.y, tw.z, fmaf(e.y, tw.y, a.y * tw.x)));
            r.z = fmaf(g.z, tw.w, fmaf(f.z, tw.z, fmaf(e.z, tw.y, a.z * tw.x)));
            r.w = fmaf(g.w, tw.w, fmaf(f.w, tw.z, fmaf(e.w, tw.y, a.w * tw.x)));
            uint32_t u0 = tf32r(r.x), u1 = tf32r(r.y), u2 = tf32r(r.z), u3 = tf32r(r.w);
            uint32_t ad = aslot + (gm << 7) + (((cg2 + h) ^ (gm & 7)) << 4);
            asm volatile("st.shared.v4.b32 [%0], {%1, %2, %3, %4};"
                         :: "r"(ad), "r"(u0), "r"(u1), "r"(u2), "r"(u3) : "memory");
        }
    };

    float acc[2][8][4];
#pragma unroll
    for (int i = 0; i < 2; i++)
#pragma unroll
        for (int j = 0; j < 8; j++)
#pragma unroll
            for (int q = 0; q < 4; q++) acc[i][j][q] = 0.f;

    int warp_m = wid & 1, warp_n = wid >> 1;
    int l15 = lid & 15, lhi = lid >> 4;

    gather(0, sb + SM2_A0);
    __syncthreads();
    MBAR_WAIT(mbar0, 0);

    for (int j = 0; j < 36; j++) {
        uint32_t Ab = sb + ((j & 1) ? SM2_A1 : SM2_A0);
        uint32_t Bb = sb + ((j & 1) ? SM2_B1 : SM2_B0);
        if (j < 35) gather(j + 1, sb + (((j + 1) & 1) ? SM2_A1 : SM2_A0));
#pragma unroll
        for (int s = 0; s < 4; s++) {
            int u = (s << 1) + lhi;
            uint32_t afr[2][4];
#pragma unroll
            for (int mf = 0; mf < 2; mf++) {
                int r = (warp_m << 5) + (mf << 4) + l15;
                uint32_t ad = Ab + (r << 7) + ((u ^ (r & 7)) << 4);
                ldsm_x4(afr[mf][0], afr[mf][1], afr[mf][2], afr[mf][3], ad);
            }
            uint32_t bfr[4][4];
#pragma unroll
            for (int g = 0; g < 4; g++) {
                int r = (warp_n << 6) + (g << 4) + l15;
                uint32_t bd = Bb + (r << 7) + ((u ^ (r & 7)) << 4);
                ldsm_x4(bfr[g][0], bfr[g][1], bfr[g][2], bfr[g][3], bd);
            }
#pragma unroll
            for (int mf = 0; mf < 2; mf++)
#pragma unroll
                for (int g = 0; g < 4; g++) {
                    mma_tf32(acc[mf][2 * g],     afr[mf], bfr[g][0], bfr[g][2]);
                    mma_tf32(acc[mf][2 * g + 1], afr[mf], bfr[g][1], bfr[g][3]);
                }
        }
        __syncthreads();
        if (j + 2 < 36 && tid == 0) {
            uint32_t mb = (j & 1) ? mbar1 : mbar0;
            MBAR_EXPECT_TX(mb, 32768);
            bulk_g2s(sb + ((j & 1) ? SM2_B1 : SM2_B0), g_wB36 + (size_t)(j + 2) * 8192, 32768, mb);
        }
        if (j < 35) {
            uint32_t mb = ((j + 1) & 1) ? mbar1 : mbar0;
            MBAR_WAIT(mb, (uint32_t)(((j + 1) >> 1) & 1));
        }
    }

    // epilogue: direct STG
    int grp = lid >> 2, tig = lid & 3;
#pragma unroll
    for (int mf = 0; mf < 2; mf++) {
#pragma unroll
        for (int nb = 0; nb < 8; nb++) {
            int mrow = (warp_m << 5) + (mf << 4) + grp;
            int n = (warp_n << 6) + (nb << 3) + (tig << 1);
            size_t o0 = ((size_t)(b * OO + n)) * HW + (ho << 7) + wo0;
            out[o0 + mrow]           = acc[mf][nb][0];
            out[o0 + HW + mrow]      = acc[mf][nb][1];
            out[o0 + mrow + 8]       = acc[mf][nb][2];
            out[o0 + HW + mrow + 8]  = acc[mf][nb][3];
        }
    }
}

// ---------------- host ----------------
extern "C" void kernel_launch(void* const* d_in, const int* in_sizes, int n_in,
                              void* d_out, int out_size) {
    (void)in_sizes; (void)n_in; (void)out_size;
    const float* x  = (const float*)d_in[0];
    const float* ow = (const float*)d_in[1];
    const float* ob = (const float*)d_in[2];
    const float* mw = (const float*)d_in[3];
    const float* mb = (const float*)d_in[4];
    const float* w  = (const float*)d_in[5];
    float* out = (float*)d_out;

    cudaFuncSetAttribute(k_stage1t, cudaFuncAttributeMaxDynamicSharedMemorySize, S1_TOTAL);
    cudaFuncSetAttribute(k_stage2, cudaFuncAttributeMaxDynamicSharedMemorySize, SM2_TOTAL);

    k_tx<<<dim3(HW / 32, CC / 32, BB), dim3(32, 8)>>>(x);
    k_prep<<<512, 256>>>(ow, mw, w);
    k_stage1t<<<BB * HH, 256, S1_TOTAL>>>(ob, mb);
    k_stage2<<<BB * HH * 2, 256, SM2_TOTAL>>>(out);
}

// round 9
// speedup vs baseline: 3.4711x; 1.0231x over previous
#include <cuda_runtime.h>
#include <cuda_bf16.h>
#include <cstdint>

#define BB 4
#define CC 128
#define HH 128
#define WW 128
#define OO 256
#define KKK 9
#define KDIM 1152
#define HW 16384

typedef unsigned long long ull;

__device__ float g_xT[BB * HW * CC];                    // NHWC x
__device__ __align__(1024) float g_wB36[36 * 8192];     // stage2 B frag image (tf32, swizzled)
__device__ __align__(1024) float g_wS1[36 * 1024];      // stage1 B frag image (tf32, swizzled)
__device__ float g_posy[BB * HW * KKK];
__device__ float g_posx[BB * HW * KKK];
__device__ float g_mask[BB * HW * KKK];

__device__ __forceinline__ uint32_t tf32r(float x) {
    uint32_t u; asm("cvt.rna.tf32.f32 %0, %1;" : "=r"(u) : "f"(x)); return u;
}
__device__ __forceinline__ uint32_t smem_u32(const void* p) {
    uint32_t a;
    asm("{ .reg .u64 t; cvta.to.shared.u64 t, %1; cvt.u32.u64 %0, t; }" : "=r"(a) : "l"(p));
    return a;
}

#define MBAR_INIT(mb, c) asm volatile("mbarrier.init.shared.b64 [%0], %1;" :: "r"(mb), "r"((uint32_t)(c)) : "memory")
#define MBAR_EXPECT_TX(mb, by) asm volatile("mbarrier.arrive.expect_tx.shared.b64 _, [%0], %1;" :: "r"(mb), "r"((uint32_t)(by)) : "memory")
#define MBAR_WAIT(mb, par) do {                                                   \
    uint32_t _m = (mb); uint32_t _p = (par); uint32_t _d;                         \
    asm volatile("{\n\t.reg .pred p;\n\t"                                         \
        "mbarrier.try_wait.parity.acquire.cta.shared::cta.b64 p, [%1], %2;\n\t"   \
        "selp.b32 %0, 1, 0, p;\n\t}" : "=r"(_d) : "r"(_m), "r"(_p) : "memory");   \
    if (!_d) {                                                                    \
        asm volatile("{\n\t.reg .pred P1;\n\t"                                    \
            "WL_%=:\n\t"                                                          \
            "mbarrier.try_wait.parity.acquire.cta.shared::cta.b64 P1, [%0], %1, 0x989680;\n\t" \
            "@P1 bra.uni WD_%=;\n\t"                                              \
            "bra.uni WL_%=;\n\t"                                                  \
            "WD_%=:\n\t}" :: "r"(_m), "r"(_p) : "memory");                        \
    }                                                                             \
} while (0)

__device__ __forceinline__ void bulk_g2s(uint32_t dst, const void* src, uint32_t bytes, uint32_t mb) {
    uint64_t g = (uint64_t)__cvta_generic_to_global(src);
    asm volatile("cp.async.bulk.shared::cta.global.mbarrier::complete_tx::bytes [%0], [%1], %2, [%3];"
                 :: "r"(dst), "l"(g), "r"(bytes), "r"(mb) : "memory");
}
__device__ __forceinline__ void ldsm_x4(uint32_t& r0, uint32_t& r1, uint32_t& r2, uint32_t& r3, uint32_t addr) {
    asm volatile("ldmatrix.sync.aligned.m8n8.x4.shared.b16 {%0,%1,%2,%3}, [%4];"
                 : "=r"(r0), "=r"(r1), "=r"(r2), "=r"(r3) : "r"(addr));
}
__device__ __forceinline__ void mma_tf32(float* c, const uint32_t* a, uint32_t b0, uint32_t b1) {
    asm volatile("mma.sync.aligned.m16n8k8.row.col.f32.tf32.tf32.f32 "
                 "{%0,%1,%2,%3}, {%4,%5,%6,%7}, {%8,%9}, {%0,%1,%2,%3};"
                 : "+f"(c[0]), "+f"(c[1]), "+f"(c[2]), "+f"(c[3])
                 : "r"(a[0]), "r"(a[1]), "r"(a[2]), "r"(a[3]), "r"(b0), "r"(b1));
}
__device__ __forceinline__ float4 ldg128(const float* p) {
    float4 v;
    asm volatile("ld.global.nc.v4.f32 {%0,%1,%2,%3}, [%4];"
                 : "=f"(v.x), "=f"(v.y), "=f"(v.z), "=f"(v.w) : "l"(p));
    return v;
}

// ---------------- K0: NCHW -> NHWC ----------------
__global__ void k_tx(const float* __restrict__ x) {
    __shared__ float t[32][33];
    int b = blockIdx.z, c0 = blockIdx.y * 32, p0 = blockIdx.x * 32;
    int tx = threadIdx.x, ty = threadIdx.y;
#pragma unroll
    for (int i = 0; i < 32; i += 8)
        t[ty + i][tx] = x[(size_t)(b * CC + c0 + ty + i) * HW + p0 + tx];
    __syncthreads();
#pragma unroll
    for (int i = 0; i < 32; i += 8)
        g_xT[(size_t)(b * HW + p0 + ty + i) * CC + c0 + tx] = t[tx][ty + i];
}

// ---------------- K0b: weight prep ----------------
__global__ void k_prep(const float* __restrict__ ow, const float* __restrict__ mw,
                       const float* __restrict__ w) {
    int stride = gridDim.x * blockDim.x;
    for (int i = blockIdx.x * blockDim.x + threadIdx.x; i < 36 * 8192; i += stride) {
        int ch = i >> 13, r = i & 8191;
        int n = r >> 5, kl = r & 31;
        int kk = ch >> 2;
        int c = ((ch & 3) << 5) + kl;
        float v = w[(n * CC + c) * KKK + kk];
        int fidx = (ch << 13) + (n << 5) + ((((kl >> 2) ^ (n & 7))) << 2) + (kl & 3);
        g_wB36[fidx] = __uint_as_float(tf32r(v));
    }
    for (int i = blockIdx.x * blockDim.x + threadIdx.x; i < 36 * 1024; i += stride) {
        int ch = i >> 10, r = i & 1023;
        int n = r >> 5, kl = r & 31;
        int kk = ch >> 2;
        int c = ((ch & 3) << 5) + kl;
        float v = 0.f;
        if (n < 18)      v = ow[n * KDIM + c * KKK + kk];
        else if (n < 27) v = mw[(n - 18) * KDIM + c * KKK + kk];
        int fidx = (ch << 10) + (n << 5) + ((((kl >> 2) ^ (n & 7))) << 2) + (kl & 3);
        g_wS1[fidx] = __uint_as_float(tf32r(v));
    }
}

// ---------------- K1: tensorized offset/modulator conv (unchanged) ----------------
#define S1_B    0
#define S1_A0   147456
#define S1_A1   163840
#define S1_OUT  180224
#define S1_MBAR 197120
#define S1_TOTAL 197152

__global__ void __launch_bounds__(256, 1) k_stage1t(const float* __restrict__ ob_,
                                                    const float* __restrict__ mb_) {
    extern __shared__ __align__(16) char smem[];
    uint32_t sb = smem_u32(smem);
    int tid = threadIdx.x, wid = tid >> 5, lid = tid & 31;
    int bi = blockIdx.x, b = bi >> 7, ho = bi & 127;

    uint32_t mbar = sb + S1_MBAR;
    if (tid == 0) MBAR_INIT(mbar, 1);
    __syncthreads();
    if (tid == 0) { MBAR_EXPECT_TX(mbar, 147456); bulk_g2s(sb + S1_B, g_wS1, 147456, mbar); }

    const float* xb = g_xT + (size_t)b * HW * CC;
    int l15 = lid & 15, lhi = lid >> 4;
    int uu = lid & 7;
    int rsub = lid >> 3;

    auto gather1 = [&](int ch, uint32_t aslot) {
        int kk = ch >> 2;
        int ky = kk / 3, kx = kk - ky * 3;
        int c0 = (ch & 3) << 5;
        int hy = ho - 1 + ky;
        bool rowok = (unsigned)hy < 128u;
#pragma unroll
        for (int it = 0; it < 4; it++) {
            int m = (wid << 4) + (it << 2) + rsub;
            int wx = m - 1 + kx;
            bool ok = rowok && ((unsigned)wx < 128u);
            float4 v = make_float4(0.f, 0.f, 0.f, 0.f);
            if (ok) v = *(const float4*)(xb + (((hy << 7) + wx) << 7) + c0 + (uu << 2));
            uint32_t u0 = tf32r(v.x), u1 = tf32r(v.y), u2 = tf32r(v.z), u3 = tf32r(v.w);
            uint32_t ad = aslot + (m << 7) + ((uu ^ (m & 7)) << 4);
            asm volatile("st.shared.v4.b32 [%0], {%1, %2, %3, %4};"
                         :: "r"(ad), "r"(u0), "r"(u1), "r"(u2), "r"(u3) : "memory");
        }
    };

    float acc[4][4];
#pragma unroll
    for (int i = 0; i < 4; i++)
#pragma unroll
        for (int q = 0; q < 4; q++) acc[i][q] = 0.f;

    gather1(0, sb + S1_A0);
    __syncthreads();
    MBAR_WAIT(mbar, 0);

    for (int j = 0; j < 36; j++) {
        uint32_t Ab = sb + ((j & 1) ? S1_A1 : S1_A0);
        uint32_t Bb = sb + S1_B + (j << 12);
        if (j < 35) gather1(j + 1, sb + (((j + 1) & 1) ? S1_A1 : S1_A0));
#pragma unroll
        for (int s = 0; s < 4; s++) {
            int u = (s << 1) + lhi;
            uint32_t afr[4];
            {
                int r = (wid << 4) + l15;
                uint32_t ad = Ab + (r << 7) + ((u ^ (r & 7)) << 4);
                ldsm_x4(afr[0], afr[1], afr[2], afr[3], ad);
            }
            uint32_t bfr[2][4];
#pragma unroll
            for (int g = 0; g < 2; g++) {
                int r = (g << 4) + l15;
                uint32_t bd = Bb + (r << 7) + ((u ^ (r & 7)) << 4);
                ldsm_x4(bfr[g][0], bfr[g][1], bfr[g][2], bfr[g][3], bd);
            }
            mma_tf32(acc[0], afr, bfr[0][0], bfr[0][2]);
            mma_tf32(acc[1], afr, bfr[0][1], bfr[0][3]);
            mma_tf32(acc[2], afr, bfr[1][0], bfr[1][2]);
            mma_tf32(acc[3], afr, bfr[1][1], bfr[1][3]);
        }
        __syncthreads();
    }

    float* sOut = (float*)(smem + S1_OUT);
    int grp = lid >> 2, tig = lid & 3;
    int row0 = (wid << 4) + grp;
#pragma unroll
    for (int nb = 0; nb < 4; nb++) {
        int nb8 = nb << 3;
        sOut[(nb8 + (tig << 1)) * 132 + row0]         = acc[nb][0];
        sOut[(nb8 + (tig << 1) + 1) * 132 + row0]     = acc[nb][1];
        sOut[(nb8 + (tig << 1)) * 132 + row0 + 8]     = acc[nb][2];
        sOut[(nb8 + (tig << 1) + 1) * 132 + row0 + 8] = acc[nb][3];
    }
    __syncthreads();
    if (tid < 128) {
        int m = tid;
        int pixbase = (bi << 7) * 9 + m * 9;
#pragma unroll
        for (int kk = 0; kk < 9; kk++) {
            int ky = kk / 3, kx = kk - ky * 3;
            float vy = sOut[(2 * kk) * 132 + m] + ob_[2 * kk];
            float vx = sOut[(2 * kk + 1) * 132 + m] + ob_[2 * kk + 1];
            float vm = sOut[(18 + kk) * 132 + m] + mb_[kk];
            vm = 2.0f / (1.0f + expf(-vm));
            g_posy[pixbase + kk] = (float)(ho - 1 + ky) + vy;
            g_posx[pixbase + kk] = (float)(m - 1 + kx) + vx;
            g_mask[pixbase + kk] = vm;
        }
    }
}

// ---------------- K2: mma.sync tf32 deformable GEMM, M=64 tile, 2 CTAs/SM ----------------
// 8-lane-per-pixel gather + software prefetch of next chunk's pass-0 loads.
#define SM2_A0   0
#define SM2_A1   8192
#define SM2_B0   16384
#define SM2_B1   49152
#define SM2_TAP  81920                // int4[576] + float4[576]
#define SM2_MBAR 100352
#define SM2_TOTAL 100416

struct G4 { float4 a, e, f, g; };

__global__ void __launch_bounds__(256, 2) k_stage2(float* __restrict__ out) {
    extern __shared__ __align__(16) char smem[];
    uint32_t sb = smem_u32(smem);
    int tid = threadIdx.x, wid = tid >> 5, lid = tid & 31;
    int bi = blockIdx.x;
    int b = bi >> 8, ho = (bi >> 1) & 127, wo0 = (bi & 1) << 6;

    uint32_t mbar0 = sb + SM2_MBAR, mbar1 = sb + SM2_MBAR + 8;
    if (tid == 0) { MBAR_INIT(mbar0, 1); MBAR_INIT(mbar1, 1); }

    int4*   sIdx = (int4*)(smem + SM2_TAP);
    float4* sW   = (float4*)(smem + SM2_TAP + 9216);
    for (int t = tid; t < 576; t += 256) {
        int m = t / 9, kk = t - m * 9;
        int wo = wo0 + m;
        int pix = ((b * HH + ho) * WW + wo) * KKK + kk;
        float py = g_posy[pix], px = g_posx[pix], mk = g_mask[pix];
        float y0f = floorf(py), x0f = floorf(px);
        float fy = py - y0f, fx = px - x0f;
        int iy0 = (int)y0f, ix0 = (int)x0f;
        int iy1 = iy0 + 1, ix1 = ix0 + 1;
        bool vy0 = (unsigned)iy0 < 128u, vy1 = (unsigned)iy1 < 128u;
        bool vx0 = (unsigned)ix0 < 128u, vx1 = (unsigned)ix1 < 128u;
        int cy0 = min(max(iy0, 0), 127), cy1 = min(max(iy1, 0), 127);
        int cx0 = min(max(ix0, 0), 127), cx1 = min(max(ix1, 0), 127);
        float w00 = mk * (1.f - fy) * (1.f - fx) * ((vy0 && vx0) ? 1.f : 0.f);
        float w01 = mk * (1.f - fy) * fx         * ((vy0 && vx1) ? 1.f : 0.f);
        float w10 = mk * fy * (1.f - fx)         * ((vy1 && vx0) ? 1.f : 0.f);
        float w11 = mk * fy * fx                 * ((vy1 && vx1) ? 1.f : 0.f);
        sIdx[t] = make_int4((((cy0 << 7) + cx0) << 7), (((cy0 << 7) + cx1) << 7),
                            (((cy1 << 7) + cx0) << 7), (((cy1 << 7) + cx1) << 7));
        sW[t] = make_float4(w00, w01, w10, w11);
    }
    __syncthreads();
    if (tid == 0) {
        MBAR_EXPECT_TX(mbar0, 32768); bulk_g2s(sb + SM2_B0, g_wB36, 32768, mbar0);
        MBAR_EXPECT_TX(mbar1, 32768); bulk_g2s(sb + SM2_B1, g_wB36 + 8192, 32768, mbar1);
    }

    const float* xb = g_xT + (size_t)b * HW * CC;
    int u8 = lid & 7;                 // 16B unit in 128B row
    int pq = lid >> 3;                // pixel-in-quad 0..3

    // issue pass-p corner loads of chunk ch
    auto g_issue = [&](int ch, int p, G4& r) {
        int m = (wid << 3) + (p << 2) + pq;
        int t = m * 9 + (ch >> 2);
        int4 ti = sIdx[t];
        int cA = ((ch & 3) << 5) + (u8 << 2);
        r.a = ldg128(xb + ti.x + cA);
        r.e = ldg128(xb + ti.y + cA);
        r.f = ldg128(xb + ti.z + cA);
        r.g = ldg128(xb + ti.w + cA);
    };
    // combine + swizzled STS
    auto g_store = [&](int ch, int p, const G4& d, uint32_t aslot) {
        int m = (wid << 3) + (p << 2) + pq;
        int t = m * 9 + (ch >> 2);
        float4 tw = sW[t];
        float4 r;
        r.x = fmaf(d.g.x, tw.w, fmaf(d.f.x, tw.z, fmaf(d.e.x, tw.y, d.a.x * tw.x)));
        r.y = fmaf(d.g.y, tw.w, fmaf(d.f.y, tw.z, fmaf(d.e.y, tw.y, d.a.y * tw.x)));
        r.z = fmaf(d.g.z, tw.w, fmaf(d.f.z, tw.z, fmaf(d.e.z, tw.y, d.a.z * tw.x)));
        r.w = fmaf(d.g.w, tw.w, fmaf(d.f.w, tw.z, fmaf(d.e.w, tw.y, d.a.w * tw.x)));
        uint32_t u0 = tf32r(r.x), u1 = tf32r(r.y), u2 = tf32r(r.z), u3 = tf32r(r.w);
        uint32_t ad = aslot + (m << 7) + ((u8 ^ (m & 7)) << 4);
        asm volatile("st.shared.v4.b32 [%0], {%1, %2, %3, %4};"
                     :: "r"(ad), "r"(u0), "r"(u1), "r"(u2), "r"(u3) : "memory");
    };

    float acc[2][8][4];
#pragma unroll
    for (int i = 0; i < 2; i++)
#pragma unroll
        for (int j = 0; j < 8; j++)
#pragma unroll
            for (int q = 0; q < 4; q++) acc[i][j][q] = 0.f;

    int warp_m = wid & 1, warp_n = wid >> 1;
    int l15 = lid & 15, lhi = lid >> 4;

    {   // prologue: chunk 0 both passes
        G4 r0, r1;
        g_issue(0, 0, r0); g_issue(0, 1, r1);
        g_store(0, 0, r0, sb + SM2_A0); g_store(0, 1, r1, sb + SM2_A0);
    }
    __syncthreads();
    MBAR_WAIT(mbar0, 0);

    G4 pre;
    for (int j = 0; j < 36; j++) {
        uint32_t Ab = sb + ((j & 1) ? SM2_A1 : SM2_A0);
        uint32_t Bb = sb + ((j & 1) ? SM2_B1 : SM2_B0);
        uint32_t An = sb + (((j + 1) & 1) ? SM2_A1 : SM2_A0);
        if (j < 35) g_issue(j + 1, 0, pre);        // prefetch pass 0 (asm-volatile: issues before mma)
#pragma unroll
        for (int s = 0; s < 4; s++) {
            int u = (s << 1) + lhi;
            uint32_t afr[2][4];
#pragma unroll
            for (int mf = 0; mf < 2; mf++) {
                int r = (warp_m << 5) + (mf << 4) + l15;
                uint32_t ad = Ab + (r << 7) + ((u ^ (r & 7)) << 4);
                ldsm_x4(afr[mf][0], afr[mf][1], afr[mf][2], afr[mf][3], ad);
            }
            uint32_t bfr[4][4];
#pragma unroll
            for (int g = 0; g < 4; g++) {
                int r = (warp_n << 6) + (g << 4) + l15;
                uint32_t bd = Bb + (r << 7) + ((u ^ (r & 7)) << 4);
                ldsm_x4(bfr[g][0], bfr[g][1], bfr[g][2], bfr[g][3], bd);
            }
#pragma unroll
            for (int mf = 0; mf < 2; mf++)
#pragma unroll
                for (int g = 0; g < 4; g++) {
                    mma_tf32(acc[mf][2 * g],     afr[mf], bfr[g][0], bfr[g][2]);
                    mma_tf32(acc[mf][2 * g + 1], afr[mf], bfr[g][1], bfr[g][3]);
                }
        }
        if (j < 35) {
            g_store(j + 1, 0, pre, An);
            G4 r1;
            g_issue(j + 1, 1, r1);
            g_store(j + 1, 1, r1, An);
        }
        __syncthreads();
        if (j + 2 < 36 && tid == 0) {
            uint32_t mb = (j & 1) ? mbar1 : mbar0;
            MBAR_EXPECT_TX(mb, 32768);
            bulk_g2s(sb + ((j & 1) ? SM2_B1 : SM2_B0), g_wB36 + (size_t)(j + 2) * 8192, 32768, mb);
        }
        if (j < 35) {
            uint32_t mb = ((j + 1) & 1) ? mbar1 : mbar0;
            MBAR_WAIT(mb, (uint32_t)(((j + 1) >> 1) & 1));
        }
    }

    // epilogue: direct STG
    int grp = lid >> 2, tig = lid & 3;
#pragma unroll
    for (int mf = 0; mf < 2; mf++) {
#pragma unroll
        for (int nb = 0; nb < 8; nb++) {
            int mrow = (warp_m << 5) + (mf << 4) + grp;
            int n = (warp_n << 6) + (nb << 3) + (tig << 1);
            size_t o0 = ((size_t)(b * OO + n)) * HW + (ho << 7) + wo0;
            out[o0 + mrow]           = acc[mf][nb][0];
            out[o0 + HW + mrow]      = acc[mf][nb][1];
            out[o0 + mrow + 8]       = acc[mf][nb][2];
            out[o0 + HW + mrow + 8]  = acc[mf][nb][3];
        }
    }
}

// ---------------- host ----------------
extern "C" void kernel_launch(void* const* d_in, const int* in_sizes, int n_in,
                              void* d_out, int out_size) {
    (void)in_sizes; (void)n_in; (void)out_size;
    const float* x  = (const float*)d_in[0];
    const float* ow = (const float*)d_in[1];
    const float* ob = (const float*)d_in[2];
    const float* mw = (const float*)d_in[3];
    const float* mb = (const float*)d_in[4];
    const float* w  = (const float*)d_in[5];
    float* out = (float*)d_out;

    cudaFuncSetAttribute(k_stage1t, cudaFuncAttributeMaxDynamicSharedMemorySize, S1_TOTAL);
    cudaFuncSetAttribute(k_stage2, cudaFuncAttributeMaxDynamicSharedMemorySize, SM2_TOTAL);

    k_tx<<<dim3(HW / 32, CC / 32, BB), dim3(32, 8)>>>(x);
    k_prep<<<512, 256>>>(ow, mw, w);
    k_stage1t<<<BB * HH, 256, S1_TOTAL>>>(ob, mb);
    k_stage2<<<BB * HH * 2, 256, SM2_TOTAL>>>(out);
}

// round 10
// speedup vs baseline: 5.0534x; 1.4559x over previous
#include <cuda_runtime.h>
#include <cuda_bf16.h>
#include <cuda_fp16.h>
#include <cstdint>
#include <cstring>

#define BB 4
#define CC 128
#define HH 128
#define WW 128
#define OO 256
#define KKK 9
#define KDIM 1152
#define HW 16384

typedef unsigned long long ull;

__device__ float g_xT[BB * HW * CC];                      // NHWC x (fp32)
__device__ __align__(1024) uint32_t g_wBh[36 * 4096];     // stage2 B half image: [chunk][256n][32k]
__device__ __align__(1024) uint32_t g_wS1h[36 * 512];     // stage1 B half image: [chunk][32n][32k]
__device__ float g_posy[BB * HW * KKK];
__device__ float g_posx[BB * HW * KKK];
__device__ float g_mask[BB * HW * KKK];

__device__ __forceinline__ uint32_t swz(uint32_t o) { return o ^ ((o >> 3) & 0x70); }
__device__ __forceinline__ uint32_t smem_u32(const void* p) {
    uint32_t a;
    asm("{ .reg .u64 t; cvta.to.shared.u64 t, %1; cvt.u32.u64 %0, t; }" : "=r"(a) : "l"(p));
    return a;
}
__device__ __forceinline__ uint32_t h2pack(float a, float b) {
    __half2 h = __floats2half2_rn(a, b);
    uint32_t u; memcpy(&u, &h, 4); return u;
}

#define MBAR_INIT(mb, c) asm volatile("mbarrier.init.shared.b64 [%0], %1;" :: "r"(mb), "r"((uint32_t)(c)) : "memory")
#define MBAR_EXPECT_TX(mb, by) asm volatile("mbarrier.arrive.expect_tx.shared.b64 _, [%0], %1;" :: "r"(mb), "r"((uint32_t)(by)) : "memory")
#define MBAR_WAIT(mb, par) do {                                                   \
    uint32_t _m = (mb); uint32_t _p = (par); uint32_t _d;                         \
    asm volatile("{\n\t.reg .pred p;\n\t"                                         \
        "mbarrier.try_wait.parity.acquire.cta.shared::cta.b64 p, [%1], %2;\n\t"   \
        "selp.b32 %0, 1, 0, p;\n\t}" : "=r"(_d) : "r"(_m), "r"(_p) : "memory");   \
    if (!_d) {                                                                    \
        asm volatile("{\n\t.reg .pred P1;\n\t"                                    \
            "WL_%=:\n\t"                                                          \
            "mbarrier.try_wait.parity.acquire.cta.shared::cta.b64 P1, [%0], %1, 0x989680;\n\t" \
            "@P1 bra.uni WD_%=;\n\t"                                              \
            "bra.uni WL_%=;\n\t"                                                  \
            "WD_%=:\n\t}" :: "r"(_m), "r"(_p) : "memory");                        \
    }                                                                             \
} while (0)

__device__ __forceinline__ void bulk_g2s(uint32_t dst, const void* src, uint32_t bytes, uint32_t mb) {
    uint64_t g = (uint64_t)__cvta_generic_to_global(src);
    asm volatile("cp.async.bulk.shared::cta.global.mbarrier::complete_tx::bytes [%0], [%1], %2, [%3];"
                 :: "r"(dst), "l"(g), "r"(bytes), "r"(mb) : "memory");
}
__device__ __forceinline__ void ldsm_x4(uint32_t& r0, uint32_t& r1, uint32_t& r2, uint32_t& r3, uint32_t addr) {
    asm volatile("ldmatrix.sync.aligned.m8n8.x4.shared.b16 {%0,%1,%2,%3}, [%4];"
                 : "=r"(r0), "=r"(r1), "=r"(r2), "=r"(r3) : "r"(addr));
}
__device__ __forceinline__ void mma_f16(float* c, const uint32_t* a, uint32_t b0, uint32_t b1) {
    asm volatile("mma.sync.aligned.m16n8k16.row.col.f32.f16.f16.f32 "
                 "{%0,%1,%2,%3}, {%4,%5,%6,%7}, {%8,%9}, {%0,%1,%2,%3};"
                 : "+f"(c[0]), "+f"(c[1]), "+f"(c[2]), "+f"(c[3])
                 : "r"(a[0]), "r"(a[1]), "r"(a[2]), "r"(a[3]), "r"(b0), "r"(b1));
}
__device__ __forceinline__ float4 ldg128(const float* p) {
    float4 v;
    asm volatile("ld.global.nc.v4.f32 {%0,%1,%2,%3}, [%4];"
                 : "=f"(v.x), "=f"(v.y), "=f"(v.z), "=f"(v.w) : "l"(p));
    return v;
}

// ---------------- K0: NCHW -> NHWC ----------------
__global__ void k_tx(const float* __restrict__ x) {
    __shared__ float t[32][33];
    int b = blockIdx.z, c0 = blockIdx.y * 32, p0 = blockIdx.x * 32;
    int tx = threadIdx.x, ty = threadIdx.y;
#pragma unroll
    for (int i = 0; i < 32; i += 8)
        t[ty + i][tx] = x[(size_t)(b * CC + c0 + ty + i) * HW + p0 + tx];
    __syncthreads();
#pragma unroll
    for (int i = 0; i < 32; i += 8)
        g_xT[(size_t)(b * HW + p0 + ty + i) * CC + c0 + tx] = t[tx][ty + i];
}

// ---------------- K0b: weight prep (fp16 images, swizzled 64B rows) ----------------
__global__ void k_prep(const float* __restrict__ ow, const float* __restrict__ mw,
                       const float* __restrict__ w) {
    int stride = gridDim.x * blockDim.x;
    // stage2: chunk ch (kk=ch>>2), rows n=0..255, k-halves pairs
    for (int i = blockIdx.x * blockDim.x + threadIdx.x; i < 36 * 4096; i += stride) {
        int ch = i >> 12, r = i & 4095;
        int n = r >> 4, k2 = (r & 15) << 1;
        int kk = ch >> 2;
        int c = ((ch & 3) << 5) + k2;
        float v0 = w[(n * CC + c) * KKK + kk];
        float v1 = w[(n * CC + c + 1) * KKK + kk];
        uint32_t phys = swz((uint32_t)((n << 6) + ((k2 >> 3) << 4))) + ((k2 & 7) << 1);
        g_wBh[(ch << 12) + (phys >> 2)] = h2pack(v0, v1);
    }
    // stage1: rows n=0..31 (27 used)
    for (int i = blockIdx.x * blockDim.x + threadIdx.x; i < 36 * 512; i += stride) {
        int ch = i >> 9, r = i & 511;
        int n = r >> 4, k2 = (r & 15) << 1;
        int kk = ch >> 2;
        int c = ((ch & 3) << 5) + k2;
        float v0 = 0.f, v1 = 0.f;
        if (n < 18)      { v0 = ow[n * KDIM + c * KKK + kk]; v1 = ow[n * KDIM + (c + 1) * KKK + kk]; }
        else if (n < 27) { v0 = mw[(n - 18) * KDIM + c * KKK + kk]; v1 = mw[(n - 18) * KDIM + (c + 1) * KKK + kk]; }
        uint32_t phys = swz((uint32_t)((n << 6) + ((k2 >> 3) << 4))) + ((k2 & 7) << 1);
        g_wS1h[(ch << 9) + (phys >> 2)] = h2pack(v0, v1);
    }
}

// ---------------- K1: fp16 tensorized offset/modulator conv ----------------
// CTA = one (b,ho) row: M=128, N=32 (27 used), K=1152 in 36 chunks of 32. 2 CTAs/SM.
#define S1_B    0
#define S1_A0   73728
#define S1_A1   81920
#define S1_OUT  90112
#define S1_MBAR 107008
#define S1_TOTAL 107072

__global__ void __launch_bounds__(256, 2) k_stage1t(const float* __restrict__ ob_,
                                                    const float* __restrict__ mb_) {
    extern __shared__ __align__(16) char smem[];
    uint32_t sb = smem_u32(smem);
    int tid = threadIdx.x, wid = tid >> 5, lid = tid & 31;
    int bi = blockIdx.x, b = bi >> 7, ho = bi & 127;

    uint32_t mbar = sb + S1_MBAR;
    if (tid == 0) MBAR_INIT(mbar, 1);
    __syncthreads();
    if (tid == 0) { MBAR_EXPECT_TX(mbar, 73728); bulk_g2s(sb + S1_B, g_wS1h, 73728, mbar); }

    const float* xb = g_xT + (size_t)b * HW * CC;
    int l15 = lid & 15, lhi = lid >> 4;
    int u8 = tid & 7, mp = tid >> 3;     // 8 lanes per pixel, 32 pixels per pass

    auto gather1 = [&](int ch, uint32_t aslot) {
        int kk = ch >> 2;
        int ky = kk / 3, kx = kk - ky * 3;
        int c0 = (ch & 3) << 5;
        int hy = ho - 1 + ky;
        bool rowok = (unsigned)hy < 128u;
#pragma unroll
        for (int p = 0; p < 4; p++) {
            int m = (p << 5) + mp;
            int wx = m - 1 + kx;
            bool ok = rowok && ((unsigned)wx < 128u);
            float4 v = make_float4(0.f, 0.f, 0.f, 0.f);
            if (ok) v = *(const float4*)(xb + (((hy << 7) + wx) << 7) + c0 + (u8 << 2));
            uint32_t w0 = h2pack(v.x, v.y), w1 = h2pack(v.z, v.w);
            uint32_t ad = aslot + swz((uint32_t)((m << 6) + ((u8 >> 1) << 4))) + ((u8 & 1) << 3);
            asm volatile("st.shared.v2.b32 [%0], {%1, %2};" :: "r"(ad), "r"(w0), "r"(w1) : "memory");
        }
    };

    float acc[4][4];
#pragma unroll
    for (int i = 0; i < 4; i++)
#pragma unroll
        for (int q = 0; q < 4; q++) acc[i][q] = 0.f;

    gather1(0, sb + S1_A0);
    __syncthreads();
    MBAR_WAIT(mbar, 0);

    for (int j = 0; j < 36; j++) {
        uint32_t Ab = sb + ((j & 1) ? S1_A1 : S1_A0);
        uint32_t Bb = sb + S1_B + (j << 11);
        if (j < 35) gather1(j + 1, sb + (((j + 1) & 1) ? S1_A1 : S1_A0));
#pragma unroll
        for (int s = 0; s < 2; s++) {
            int u = (s << 1) + lhi;
            uint32_t afr[4];
            {
                int r = (wid << 4) + l15;
                ldsm_x4(afr[0], afr[1], afr[2], afr[3], Ab + swz((uint32_t)((r << 6) + (u << 4))));
            }
            uint32_t bfr[2][4];
#pragma unroll
            for (int g = 0; g < 2; g++) {
                int r = (g << 4) + l15;
                ldsm_x4(bfr[g][0], bfr[g][1], bfr[g][2], bfr[g][3], Bb + swz((uint32_t)((r << 6) + (u << 4))));
            }
            mma_f16(acc[0], afr, bfr[0][0], bfr[0][2]);
            mma_f16(acc[1], afr, bfr[0][1], bfr[0][3]);
            mma_f16(acc[2], afr, bfr[1][0], bfr[1][2]);
            mma_f16(acc[3], afr, bfr[1][1], bfr[1][3]);
        }
        __syncthreads();
    }

    float* sOut = (float*)(smem + S1_OUT);
    int grp = lid >> 2, tig = lid & 3;
    int row0 = (wid << 4) + grp;
#pragma unroll
    for (int nb = 0; nb < 4; nb++) {
        int nb8 = nb << 3;
        sOut[(nb8 + (tig << 1)) * 132 + row0]         = acc[nb][0];
        sOut[(nb8 + (tig << 1) + 1) * 132 + row0]     = acc[nb][1];
        sOut[(nb8 + (tig << 1)) * 132 + row0 + 8]     = acc[nb][2];
        sOut[(nb8 + (tig << 1) + 1) * 132 + row0 + 8] = acc[nb][3];
    }
    __syncthreads();
    if (tid < 128) {
        int m = tid;
        int pixbase = (bi << 7) * 9 + m * 9;
#pragma unroll
        for (int kk = 0; kk < 9; kk++) {
            int ky = kk / 3, kx = kk - ky * 3;
            float vy = sOut[(2 * kk) * 132 + m] + ob_[2 * kk];
            float vx = sOut[(2 * kk + 1) * 132 + m] + ob_[2 * kk + 1];
            float vm = sOut[(18 + kk) * 132 + m] + mb_[kk];
            vm = 2.0f / (1.0f + expf(-vm));
            g_posy[pixbase + kk] = (float)(ho - 1 + ky) + vy;
            g_posx[pixbase + kk] = (float)(m - 1 + kx) + vx;
            g_mask[pixbase + kk] = vm;
        }
    }
}

// ---------------- K2: fp16 mma deformable GEMM, M=64 tile, 2 CTAs/SM ----------------
#define SM2_A0   0
#define SM2_A1   4096
#define SM2_B0   8192
#define SM2_B1   24576
#define SM2_TAP  40960               // int4[576] + float4[576] = 18432
#define SM2_MBAR 59392
#define SM2_TOTAL 59456

struct G4 { float4 a, e, f, g; };

__global__ void __launch_bounds__(256, 2) k_stage2(float* __restrict__ out) {
    extern __shared__ __align__(16) char smem[];
    uint32_t sb = smem_u32(smem);
    int tid = threadIdx.x, wid = tid >> 5, lid = tid & 31;
    int bi = blockIdx.x;
    int b = bi >> 8, ho = (bi >> 1) & 127, wo0 = (bi & 1) << 6;

    uint32_t mbar0 = sb + SM2_MBAR, mbar1 = sb + SM2_MBAR + 8;
    if (tid == 0) { MBAR_INIT(mbar0, 1); MBAR_INIT(mbar1, 1); }

    int4*   sIdx = (int4*)(smem + SM2_TAP);
    float4* sW   = (float4*)(smem + SM2_TAP + 9216);
    for (int t = tid; t < 576; t += 256) {
        int m = t / 9, kk = t - m * 9;
        int wo = wo0 + m;
        int pix = ((b * HH + ho) * WW + wo) * KKK + kk;
        float py = g_posy[pix], px = g_posx[pix], mk = g_mask[pix];
        float y0f = floorf(py), x0f = floorf(px);
        float fy = py - y0f, fx = px - x0f;
        int iy0 = (int)y0f, ix0 = (int)x0f;
        int iy1 = iy0 + 1, ix1 = ix0 + 1;
        bool vy0 = (unsigned)iy0 < 128u, vy1 = (unsigned)iy1 < 128u;
        bool vx0 = (unsigned)ix0 < 128u, vx1 = (unsigned)ix1 < 128u;
        int cy0 = min(max(iy0, 0), 127), cy1 = min(max(iy1, 0), 127);
        int cx0 = min(max(ix0, 0), 127), cx1 = min(max(ix1, 0), 127);
        float w00 = mk * (1.f - fy) * (1.f - fx) * ((vy0 && vx0) ? 1.f : 0.f);
        float w01 = mk * (1.f - fy) * fx         * ((vy0 && vx1) ? 1.f : 0.f);
        float w10 = mk * fy * (1.f - fx)         * ((vy1 && vx0) ? 1.f : 0.f);
        float w11 = mk * fy * fx                 * ((vy1 && vx1) ? 1.f : 0.f);
        sIdx[t] = make_int4((((cy0 << 7) + cx0) << 7), (((cy0 << 7) + cx1) << 7),
                            (((cy1 << 7) + cx0) << 7), (((cy1 << 7) + cx1) << 7));
        sW[t] = make_float4(w00, w01, w10, w11);
    }
    __syncthreads();
    if (tid == 0) {
        MBAR_EXPECT_TX(mbar0, 16384); bulk_g2s(sb + SM2_B0, g_wBh, 16384, mbar0);
        MBAR_EXPECT_TX(mbar1, 16384); bulk_g2s(sb + SM2_B1, g_wBh + 4096, 16384, mbar1);
    }

    const float* xb = g_xT + (size_t)b * HW * CC;
    int u8 = lid & 7;                 // 16B unit of fp32 source row
    int pq = lid >> 3;                // pixel-in-quad

    auto g_issue = [&](int ch, int p, G4& r) {
        int m = (wid << 3) + (p << 2) + pq;
        int t = m * 9 + (ch >> 2);
        int4 ti = sIdx[t];
        int cA = ((ch & 3) << 5) + (u8 << 2);
        r.a = ldg128(xb + ti.x + cA);
        r.e = ldg128(xb + ti.y + cA);
        r.f = ldg128(xb + ti.z + cA);
        r.g = ldg128(xb + ti.w + cA);
    };
    auto g_store = [&](int ch, int p, const G4& d, uint32_t aslot) {
        int m = (wid << 3) + (p << 2) + pq;
        int t = m * 9 + (ch >> 2);
        float4 tw = sW[t];
        float4 r;
        r.x = fmaf(d.g.x, tw.w, fmaf(d.f.x, tw.z, fmaf(d.e.x, tw.y, d.a.x * tw.x)));
        r.y = fmaf(d.g.y, tw.w, fmaf(d.f.y, tw.z, fmaf(d.e.y, tw.y, d.a.y * tw.x)));
        r.z = fmaf(d.g.z, tw.w, fmaf(d.f.z, tw.z, fmaf(d.e.z, tw.y, d.a.z * tw.x)));
        r.w = fmaf(d.g.w, tw.w, fmaf(d.f.w, tw.z, fmaf(d.e.w, tw.y, d.a.w * tw.x)));
        uint32_t w0 = h2pack(r.x, r.y), w1 = h2pack(r.z, r.w);
        uint32_t ad = aslot + swz((uint32_t)((m << 6) + ((u8 >> 1) << 4))) + ((u8 & 1) << 3);
        asm volatile("st.shared.v2.b32 [%0], {%1, %2};" :: "r"(ad), "r"(w0), "r"(w1) : "memory");
    };

    float acc[2][8][4];
#pragma unroll
    for (int i = 0; i < 2; i++)
#pragma unroll
        for (int j = 0; j < 8; j++)
#pragma unroll
            for (int q = 0; q < 4; q++) acc[i][j][q] = 0.f;

    int warp_m = wid & 1, warp_n = wid >> 1;
    int l15 = lid & 15, lhi = lid >> 4;

    {   // prologue: chunk 0 both passes
        G4 r0, r1;
        g_issue(0, 0, r0); g_issue(0, 1, r1);
        g_store(0, 0, r0, sb + SM2_A0); g_store(0, 1, r1, sb + SM2_A0);
    }
    __syncthreads();
    MBAR_WAIT(mbar0, 0);

    G4 pre;
    for (int j = 0; j < 36; j++) {
        uint32_t Ab = sb + ((j & 1) ? SM2_A1 : SM2_A0);
        uint32_t Bb = sb + ((j & 1) ? SM2_B1 : SM2_B0);
        uint32_t An = sb + (((j + 1) & 1) ? SM2_A1 : SM2_A0);
        if (j < 35) g_issue(j + 1, 0, pre);
#pragma unroll
        for (int s = 0; s < 2; s++) {
            int u = (s << 1) + lhi;
            uint32_t afr[2][4];
#pragma unroll
            for (int mf = 0; mf < 2; mf++) {
                int r = (warp_m << 5) + (mf << 4) + l15;
                ldsm_x4(afr[mf][0], afr[mf][1], afr[mf][2], afr[mf][3],
                        Ab + swz((uint32_t)((r << 6) + (u << 4))));
            }
            uint32_t bfr[4][4];
#pragma unroll
            for (int g = 0; g < 4; g++) {
                int r = (warp_n << 6) + (g << 4) + l15;
                ldsm_x4(bfr[g][0], bfr[g][1], bfr[g][2], bfr[g][3],
                        Bb + swz((uint32_t)((r << 6) + (u << 4))));
            }
#pragma unroll
            for (int mf = 0; mf < 2; mf++)
#pragma unroll
                for (int g = 0; g < 4; g++) {
                    mma_f16(acc[mf][2 * g],     afr[mf], bfr[g][0], bfr[g][2]);
                    mma_f16(acc[mf][2 * g + 1], afr[mf], bfr[g][1], bfr[g][3]);
                }
        }
        if (j < 35) {
            g_store(j + 1, 0, pre, An);
            G4 r1;
            g_issue(j + 1, 1, r1);
            g_store(j + 1, 1, r1, An);
        }
        __syncthreads();
        if (j + 2 < 36 && tid == 0) {
            uint32_t mb = (j & 1) ? mbar1 : mbar0;
            MBAR_EXPECT_TX(mb, 16384);
            bulk_g2s(sb + ((j & 1) ? SM2_B1 : SM2_B0), g_wBh + (size_t)(j + 2) * 4096, 16384, mb);
        }
        if (j < 35) {
            uint32_t mb = ((j + 1) & 1) ? mbar1 : mbar0;
            MBAR_WAIT(mb, (uint32_t)(((j + 1) >> 1) & 1));
        }
    }

    // epilogue: direct STG
    int grp = lid >> 2, tig = lid & 3;
#pragma unroll
    for (int mf = 0; mf < 2; mf++) {
#pragma unroll
        for (int nb = 0; nb < 8; nb++) {
            int mrow = (warp_m << 5) + (mf << 4) + grp;
            int n = (warp_n << 6) + (nb << 3) + (tig << 1);
            size_t o0 = ((size_t)(b * OO + n)) * HW + (ho << 7) + wo0;
            out[o0 + mrow]           = acc[mf][nb][0];
            out[o0 + HW + mrow]      = acc[mf][nb][1];
            out[o0 + mrow + 8]       = acc[mf][nb][2];
            out[o0 + HW + mrow + 8]  = acc[mf][nb][3];
        }
    }
}

// ---------------- host ----------------
extern "C" void kernel_launch(void* const* d_in, const int* in_sizes, int n_in,
                              void* d_out, int out_size) {
    (void)in_sizes; (void)n_in; (void)out_size;
    const float* x  = (const float*)d_in[0];
    const float* ow = (const float*)d_in[1];
    const float* ob = (const float*)d_in[2];
    const float* mw = (const float*)d_in[3];
    const float* mb = (const float*)d_in[4];
    const float* w  = (const float*)d_in[5];
    float* out = (float*)d_out;

    cudaFuncSetAttribute(k_stage1t, cudaFuncAttributeMaxDynamicSharedMemorySize, S1_TOTAL);
    cudaFuncSetAttribute(k_stage2, cudaFuncAttributeMaxDynamicSharedMemorySize, SM2_TOTAL);

    k_tx<<<dim3(HW / 32, CC / 32, BB), dim3(32, 8)>>>(x);
    k_prep<<<512, 256>>>(ow, mw, w);
    k_stage1t<<<BB * HH, 256, S1_TOTAL>>>(ob, mb);
    k_stage2<<<BB * HH * 2, 256, SM2_TOTAL>>>(out);
}

// round 11
// speedup vs baseline: 5.2380x; 1.0365x over previous
#include <cuda_runtime.h>
#include <cuda_bf16.h>
#include <cuda_fp16.h>
#include <cstdint>
#include <cstring>

#define BB 4
#define CC 128
#define HH 128
#define WW 128
#define OO 256
#define KKK 9
#define KDIM 1152
#define HW 16384

typedef unsigned long long ull;

__device__ __half g_xTh[BB * HW * CC];                    // NHWC x (fp16), 16.8 MB
__device__ __align__(1024) uint32_t g_wBh[36 * 4096];     // stage2 B half image
__device__ __align__(1024) uint32_t g_wS1h[36 * 512];     // stage1 B half image
__device__ float g_posy[BB * HW * KKK];
__device__ float g_posx[BB * HW * KKK];
__device__ float g_mask[BB * HW * KKK];

__device__ __forceinline__ uint32_t swz(uint32_t o) { return o ^ ((o >> 3) & 0x70); }
__device__ __forceinline__ uint32_t smem_u32(const void* p) {
    uint32_t a;
    asm("{ .reg .u64 t; cvta.to.shared.u64 t, %1; cvt.u32.u64 %0, t; }" : "=r"(a) : "l"(p));
    return a;
}
__device__ __forceinline__ uint32_t h2pack(float a, float b) {
    __half2 h = __floats2half2_rn(a, b);
    uint32_t u; memcpy(&u, &h, 4); return u;
}
__device__ __forceinline__ void h4tof(uint2 u, float2& lo, float2& hi) {
    __half2 h0, h1; memcpy(&h0, &u.x, 4); memcpy(&h1, &u.y, 4);
    lo = __half22float2(h0); hi = __half22float2(h1);
}

#define MBAR_INIT(mb, c) asm volatile("mbarrier.init.shared.b64 [%0], %1;" :: "r"(mb), "r"((uint32_t)(c)) : "memory")
#define MBAR_EXPECT_TX(mb, by) asm volatile("mbarrier.arrive.expect_tx.shared.b64 _, [%0], %1;" :: "r"(mb), "r"((uint32_t)(by)) : "memory")
#define MBAR_WAIT(mb, par) do {                                                   \
    uint32_t _m = (mb); uint32_t _p = (par); uint32_t _d;                         \
    asm volatile("{\n\t.reg .pred p;\n\t"                                         \
        "mbarrier.try_wait.parity.acquire.cta.shared::cta.b64 p, [%1], %2;\n\t"   \
        "selp.b32 %0, 1, 0, p;\n\t}" : "=r"(_d) : "r"(_m), "r"(_p) : "memory");   \
    if (!_d) {                                                                    \
        asm volatile("{\n\t.reg .pred P1;\n\t"                                    \
            "WL_%=:\n\t"                                                          \
            "mbarrier.try_wait.parity.acquire.cta.shared::cta.b64 P1, [%0], %1, 0x989680;\n\t" \
            "@P1 bra.uni WD_%=;\n\t"                                              \
            "bra.uni WL_%=;\n\t"                                                  \
            "WD_%=:\n\t}" :: "r"(_m), "r"(_p) : "memory");                        \
    }                                                                             \
} while (0)

__device__ __forceinline__ void bulk_g2s(uint32_t dst, const void* src, uint32_t bytes, uint32_t mb) {
    uint64_t g = (uint64_t)__cvta_generic_to_global(src);
    asm volatile("cp.async.bulk.shared::cta.global.mbarrier::complete_tx::bytes [%0], [%1], %2, [%3];"
                 :: "r"(dst), "l"(g), "r"(bytes), "r"(mb) : "memory");
}
__device__ __forceinline__ void ldsm_x4(uint32_t& r0, uint32_t& r1, uint32_t& r2, uint32_t& r3, uint32_t addr) {
    asm volatile("ldmatrix.sync.aligned.m8n8.x4.shared.b16 {%0,%1,%2,%3}, [%4];"
                 : "=r"(r0), "=r"(r1), "=r"(r2), "=r"(r3) : "r"(addr));
}
__device__ __forceinline__ void mma_f16(float* c, const uint32_t* a, uint32_t b0, uint32_t b1) {
    asm volatile("mma.sync.aligned.m16n8k16.row.col.f32.f16.f16.f32 "
                 "{%0,%1,%2,%3}, {%4,%5,%6,%7}, {%8,%9}, {%0,%1,%2,%3};"
                 : "+f"(c[0]), "+f"(c[1]), "+f"(c[2]), "+f"(c[3])
                 : "r"(a[0]), "r"(a[1]), "r"(a[2]), "r"(a[3]), "r"(b0), "r"(b1));
}
__device__ __forceinline__ uint2 ldg64u(const void* p) {
    uint2 v;
    asm volatile("ld.global.nc.v2.u32 {%0,%1}, [%2];" : "=r"(v.x), "=r"(v.y) : "l"(p));
    return v;
}

// ---------------- K0: NCHW fp32 -> NHWC fp16 ----------------
__global__ void k_tx(const float* __restrict__ x) {
    __shared__ float t[32][33];
    int b = blockIdx.z, c0 = blockIdx.y * 32, p0 = blockIdx.x * 32;
    int tx = threadIdx.x, ty = threadIdx.y;
#pragma unroll
    for (int i = 0; i < 32; i += 8)
        t[ty + i][tx] = x[(size_t)(b * CC + c0 + ty + i) * HW + p0 + tx];
    __syncthreads();
#pragma unroll
    for (int i = 0; i < 32; i += 8)
        g_xTh[(size_t)(b * HW + p0 + ty + i) * CC + c0 + tx] = __float2half(t[tx][ty + i]);
}

// ---------------- K0b: weight prep (fp16 images, swizzled 64B rows) ----------------
__global__ void k_prep(const float* __restrict__ ow, const float* __restrict__ mw,
                       const float* __restrict__ w) {
    int stride = gridDim.x * blockDim.x;
    for (int i = blockIdx.x * blockDim.x + threadIdx.x; i < 36 * 4096; i += stride) {
        int ch = i >> 12, r = i & 4095;
        int n = r >> 4, k2 = (r & 15) << 1;
        int kk = ch >> 2;
        int c = ((ch & 3) << 5) + k2;
        float v0 = w[(n * CC + c) * KKK + kk];
        float v1 = w[(n * CC + c + 1) * KKK + kk];
        uint32_t phys = swz((uint32_t)((n << 6) + ((k2 >> 3) << 4))) + ((k2 & 7) << 1);
        g_wBh[(ch << 12) + (phys >> 2)] = h2pack(v0, v1);
    }
    for (int i = blockIdx.x * blockDim.x + threadIdx.x; i < 36 * 512; i += stride) {
        int ch = i >> 9, r = i & 511;
        int n = r >> 4, k2 = (r & 15) << 1;
        int kk = ch >> 2;
        int c = ((ch & 3) << 5) + k2;
        float v0 = 0.f, v1 = 0.f;
        if (n < 18)      { v0 = ow[n * KDIM + c * KKK + kk]; v1 = ow[n * KDIM + (c + 1) * KKK + kk]; }
        else if (n < 27) { v0 = mw[(n - 18) * KDIM + c * KKK + kk]; v1 = mw[(n - 18) * KDIM + (c + 1) * KKK + kk]; }
        uint32_t phys = swz((uint32_t)((n << 6) + ((k2 >> 3) << 4))) + ((k2 & 7) << 1);
        g_wS1h[(ch << 9) + (phys >> 2)] = h2pack(v0, v1);
    }
}

// ---------------- K1: fp16 tensorized offset/modulator conv ----------------
#define S1_B    0
#define S1_A0   73728
#define S1_A1   81920
#define S1_OUT  90112
#define S1_MBAR 107008
#define S1_TOTAL 107072

__global__ void __launch_bounds__(256, 2) k_stage1t(const float* __restrict__ ob_,
                                                    const float* __restrict__ mb_) {
    extern __shared__ __align__(16) char smem[];
    uint32_t sb = smem_u32(smem);
    int tid = threadIdx.x, wid = tid >> 5, lid = tid & 31;
    int bi = blockIdx.x, b = bi >> 7, ho = bi & 127;

    uint32_t mbar = sb + S1_MBAR;
    if (tid == 0) MBAR_INIT(mbar, 1);
    __syncthreads();
    if (tid == 0) { MBAR_EXPECT_TX(mbar, 73728); bulk_g2s(sb + S1_B, g_wS1h, 73728, mbar); }

    const __half* xb = g_xTh + (size_t)b * HW * CC;
    int l15 = lid & 15, lhi = lid >> 4;
    int u8 = tid & 7, mp = tid >> 3;     // 8 lanes per pixel, 32 pixels per pass

    auto gather1 = [&](int ch, uint32_t aslot) {
        int kk = ch >> 2;
        int ky = kk / 3, kx = kk - ky * 3;
        int c0 = (ch & 3) << 5;
        int hy = ho - 1 + ky;
        bool rowok = (unsigned)hy < 128u;
#pragma unroll
        for (int p = 0; p < 4; p++) {
            int m = (p << 5) + mp;
            int wx = m - 1 + kx;
            bool ok = rowok && ((unsigned)wx < 128u);
            uint2 v = make_uint2(0u, 0u);
            if (ok) v = *(const uint2*)(xb + (((hy << 7) + wx) << 7) + c0 + (u8 << 2));
            uint32_t ad = aslot + swz((uint32_t)((m << 6) + ((u8 >> 1) << 4))) + ((u8 & 1) << 3);
            asm volatile("st.shared.v2.b32 [%0], {%1, %2};" :: "r"(ad), "r"(v.x), "r"(v.y) : "memory");
        }
    };

    float acc[4][4];
#pragma unroll
    for (int i = 0; i < 4; i++)
#pragma unroll
        for (int q = 0; q < 4; q++) acc[i][q] = 0.f;

    gather1(0, sb + S1_A0);
    __syncthreads();
    MBAR_WAIT(mbar, 0);

    for (int j = 0; j < 36; j++) {
        uint32_t Ab = sb + ((j & 1) ? S1_A1 : S1_A0);
        uint32_t Bb = sb + S1_B + (j << 11);
        if (j < 35) gather1(j + 1, sb + (((j + 1) & 1) ? S1_A1 : S1_A0));
#pragma unroll
        for (int s = 0; s < 2; s++) {
            int u = (s << 1) + lhi;
            uint32_t afr[4];
            {
                int r = (wid << 4) + l15;
                ldsm_x4(afr[0], afr[1], afr[2], afr[3], Ab + swz((uint32_t)((r << 6) + (u << 4))));
            }
            uint32_t bfr[2][4];
#pragma unroll
            for (int g = 0; g < 2; g++) {
                int r = (g << 4) + l15;
                ldsm_x4(bfr[g][0], bfr[g][1], bfr[g][2], bfr[g][3], Bb + swz((uint32_t)((r << 6) + (u << 4))));
            }
            mma_f16(acc[0], afr, bfr[0][0], bfr[0][2]);
            mma_f16(acc[1], afr, bfr[0][1], bfr[0][3]);
            mma_f16(acc[2], afr, bfr[1][0], bfr[1][2]);
            mma_f16(acc[3], afr, bfr[1][1], bfr[1][3]);
        }
        __syncthreads();
    }

    float* sOut = (float*)(smem + S1_OUT);
    int grp = lid >> 2, tig = lid & 3;
    int row0 = (wid << 4) + grp;
#pragma unroll
    for (int nb = 0; nb < 4; nb++) {
        int nb8 = nb << 3;
        sOut[(nb8 + (tig << 1)) * 132 + row0]         = acc[nb][0];
        sOut[(nb8 + (tig << 1) + 1) * 132 + row0]     = acc[nb][1];
        sOut[(nb8 + (tig << 1)) * 132 + row0 + 8]     = acc[nb][2];
        sOut[(nb8 + (tig << 1) + 1) * 132 + row0 + 8] = acc[nb][3];
    }
    __syncthreads();
    if (tid < 128) {
        int m = tid;
        int pixbase = (bi << 7) * 9 + m * 9;
#pragma unroll
        for (int kk = 0; kk < 9; kk++) {
            int ky = kk / 3, kx = kk - ky * 3;
            float vy = sOut[(2 * kk) * 132 + m] + ob_[2 * kk];
            float vx = sOut[(2 * kk + 1) * 132 + m] + ob_[2 * kk + 1];
            float vm = sOut[(18 + kk) * 132 + m] + mb_[kk];
            vm = 2.0f / (1.0f + expf(-vm));
            g_posy[pixbase + kk] = (float)(ho - 1 + ky) + vy;
            g_posx[pixbase + kk] = (float)(m - 1 + kx) + vx;
            g_mask[pixbase + kk] = vm;
        }
    }
}

// ---------------- K2: fp16 mma deformable GEMM, M=64 tile, 2 CTAs/SM ----------------
#define SM2_A0   0
#define SM2_A1   4096
#define SM2_B0   8192
#define SM2_B1   24576
#define SM2_TAP  40960
#define SM2_MBAR 59392
#define SM2_TOTAL 59456

struct G4 { uint2 a, e, f, g; };

__global__ void __launch_bounds__(256, 2) k_stage2(float* __restrict__ out) {
    extern __shared__ __align__(16) char smem[];
    uint32_t sb = smem_u32(smem);
    int tid = threadIdx.x, wid = tid >> 5, lid = tid & 31;
    int bi = blockIdx.x;
    int b = bi >> 8, ho = (bi >> 1) & 127, wo0 = (bi & 1) << 6;

    uint32_t mbar0 = sb + SM2_MBAR, mbar1 = sb + SM2_MBAR + 8;
    if (tid == 0) { MBAR_INIT(mbar0, 1); MBAR_INIT(mbar1, 1); }

    int4*   sIdx = (int4*)(smem + SM2_TAP);
    float4* sW   = (float4*)(smem + SM2_TAP + 9216);
    for (int t = tid; t < 576; t += 256) {
        int m = t / 9, kk = t - m * 9;
        int wo = wo0 + m;
        int pix = ((b * HH + ho) * WW + wo) * KKK + kk;
        float py = g_posy[pix], px = g_posx[pix], mk = g_mask[pix];
        float y0f = floorf(py), x0f = floorf(px);
        float fy = py - y0f, fx = px - x0f;
        int iy0 = (int)y0f, ix0 = (int)x0f;
        int iy1 = iy0 + 1, ix1 = ix0 + 1;
        bool vy0 = (unsigned)iy0 < 128u, vy1 = (unsigned)iy1 < 128u;
        bool vx0 = (unsigned)ix0 < 128u, vx1 = (unsigned)ix1 < 128u;
        int cy0 = min(max(iy0, 0), 127), cy1 = min(max(iy1, 0), 127);
        int cx0 = min(max(ix0, 0), 127), cx1 = min(max(ix1, 0), 127);
        float w00 = mk * (1.f - fy) * (1.f - fx) * ((vy0 && vx0) ? 1.f : 0.f);
        float w01 = mk * (1.f - fy) * fx         * ((vy0 && vx1) ? 1.f : 0.f);
        float w10 = mk * fy * (1.f - fx)         * ((vy1 && vx0) ? 1.f : 0.f);
        float w11 = mk * fy * fx                 * ((vy1 && vx1) ? 1.f : 0.f);
        sIdx[t] = make_int4((((cy0 << 7) + cx0) << 7), (((cy0 << 7) + cx1) << 7),
                            (((cy1 << 7) + cx0) << 7), (((cy1 << 7) + cx1) << 7));
        sW[t] = make_float4(w00, w01, w10, w11);
    }
    __syncthreads();
    if (tid == 0) {
        MBAR_EXPECT_TX(mbar0, 16384); bulk_g2s(sb + SM2_B0, g_wBh, 16384, mbar0);
        MBAR_EXPECT_TX(mbar1, 16384); bulk_g2s(sb + SM2_B1, g_wBh + 4096, 16384, mbar1);
    }

    const __half* xb = g_xTh + (size_t)b * HW * CC;
    int u8 = lid & 7;                 // 8B unit (4 halves) of 64B chunk-row
    int pq = lid >> 3;

    auto g_issue = [&](int ch, int p, G4& r) {
        int m = (wid << 3) + (p << 2) + pq;
        int t = m * 9 + (ch >> 2);
        int4 ti = sIdx[t];
        int cA = ((ch & 3) << 5) + (u8 << 2);
        r.a = ldg64u(xb + ti.x + cA);
        r.e = ldg64u(xb + ti.y + cA);
        r.f = ldg64u(xb + ti.z + cA);
        r.g = ldg64u(xb + ti.w + cA);
    };
    auto g_store = [&](int ch, int p, const G4& d, uint32_t aslot) {
        int m = (wid << 3) + (p << 2) + pq;
        int t = m * 9 + (ch >> 2);
        float4 tw = sW[t];
        float2 a01, a23, e01, e23, f01, f23, q01, q23;
        h4tof(d.a, a01, a23);
        h4tof(d.e, e01, e23);
        h4tof(d.f, f01, f23);
        h4tof(d.g, q01, q23);
        float r0 = fmaf(q01.x, tw.w, fmaf(f01.x, tw.z, fmaf(e01.x, tw.y, a01.x * tw.x)));
        float r1 = fmaf(q01.y, tw.w, fmaf(f01.y, tw.z, fmaf(e01.y, tw.y, a01.y * tw.x)));
        float r2 = fmaf(q23.x, tw.w, fmaf(f23.x, tw.z, fmaf(e23.x, tw.y, a23.x * tw.x)));
        float r3 = fmaf(q23.y, tw.w, fmaf(f23.y, tw.z, fmaf(e23.y, tw.y, a23.y * tw.x)));
        uint32_t w0 = h2pack(r0, r1), w1 = h2pack(r2, r3);
        uint32_t ad = aslot + swz((uint32_t)((m << 6) + ((u8 >> 1) << 4))) + ((u8 & 1) << 3);
        asm volatile("st.shared.v2.b32 [%0], {%1, %2};" :: "r"(ad), "r"(w0), "r"(w1) : "memory");
    };

    float acc[2][8][4];
#pragma unroll
    for (int i = 0; i < 2; i++)
#pragma unroll
        for (int j = 0; j < 8; j++)
#pragma unroll
            for (int q = 0; q < 4; q++) acc[i][j][q] = 0.f;

    int warp_m = wid & 1, warp_n = wid >> 1;
    int l15 = lid & 15, lhi = lid >> 4;

    {   // prologue: chunk 0 both passes
        G4 r0, r1;
        g_issue(0, 0, r0); g_issue(0, 1, r1);
        g_store(0, 0, r0, sb + SM2_A0); g_store(0, 1, r1, sb + SM2_A0);
    }
    __syncthreads();
    MBAR_WAIT(mbar0, 0);

    G4 pre;
    for (int j = 0; j < 36; j++) {
        uint32_t Ab = sb + ((j & 1) ? SM2_A1 : SM2_A0);
        uint32_t Bb = sb + ((j & 1) ? SM2_B1 : SM2_B0);
        uint32_t An = sb + (((j + 1) & 1) ? SM2_A1 : SM2_A0);
        if (j < 35) g_issue(j + 1, 0, pre);
#pragma unroll
        for (int s = 0; s < 2; s++) {
            int u = (s << 1) + lhi;
            uint32_t afr[2][4];
#pragma unroll
            for (int mf = 0; mf < 2; mf++) {
                int r = (warp_m << 5) + (mf << 4) + l15;
                ldsm_x4(afr[mf][0], afr[mf][1], afr[mf][2], afr[mf][3],
                        Ab + swz((uint32_t)((r << 6) + (u << 4))));
            }
            uint32_t bfr[4][4];
#pragma unroll
            for (int g = 0; g < 4; g++) {
                int r = (warp_n << 6) + (g << 4) + l15;
                ldsm_x4(bfr[g][0], bfr[g][1], bfr[g][2], bfr[g][3],
                        Bb + swz((uint32_t)((r << 6) + (u << 4))));
            }
#pragma unroll
            for (int mf = 0; mf < 2; mf++)
#pragma unroll
                for (int g = 0; g < 4; g++) {
                    mma_f16(acc[mf][2 * g],     afr[mf], bfr[g][0], bfr[g][2]);
                    mma_f16(acc[mf][2 * g + 1], afr[mf], bfr[g][1], bfr[g][3]);
                }
        }
        if (j < 35) {
            g_store(j + 1, 0, pre, An);
            G4 r1;
            g_issue(j + 1, 1, r1);
            g_store(j + 1, 1, r1, An);
        }
        __syncthreads();
        if (j + 2 < 36 && tid == 0) {
            uint32_t mb = (j & 1) ? mbar1 : mbar0;
            MBAR_EXPECT_TX(mb, 16384);
            bulk_g2s(sb + ((j & 1) ? SM2_B1 : SM2_B0), g_wBh + (size_t)(j + 2) * 4096, 16384, mb);
        }
        if (j < 35) {
            uint32_t mb = ((j + 1) & 1) ? mbar1 : mbar0;
            MBAR_WAIT(mb, (uint32_t)(((j + 1) >> 1) & 1));
        }
    }

    // epilogue: direct STG
    int grp = lid >> 2, tig = lid & 3;
#pragma unroll
    for (int mf = 0; mf < 2; mf++) {
#pragma unroll
        for (int nb = 0; nb < 8; nb++) {
            int mrow = (warp_m << 5) + (mf << 4) + grp;
            int n = (warp_n << 6) + (nb << 3) + (tig << 1);
            size_t o0 = ((size_t)(b * OO + n)) * HW + (ho << 7) + wo0;
            out[o0 + mrow]           = acc[mf][nb][0];
            out[o0 + HW + mrow]      = acc[mf][nb][1];
            out[o0 + mrow + 8]       = acc[mf][nb][2];
            out[o0 + HW + mrow + 8]  = acc[mf][nb][3];
        }
    }
}

// ---------------- host ----------------
extern "C" void kernel_launch(void* const* d_in, const int* in_sizes, int n_in,
                              void* d_out, int out_size) {
    (void)in_sizes; (void)n_in; (void)out_size;
    const float* x  = (const float*)d_in[0];
    const float* ow = (const float*)d_in[1];
    const float* ob = (const float*)d_in[2];
    const float* mw = (const float*)d_in[3];
    const float* mb = (const float*)d_in[4];
    const float* w  = (const float*)d_in[5];
    float* out = (float*)d_out;

    cudaFuncSetAttribute(k_stage1t, cudaFuncAttributeMaxDynamicSharedMemorySize, S1_TOTAL);
    cudaFuncSetAttribute(k_stage2, cudaFuncAttributeMaxDynamicSharedMemorySize, SM2_TOTAL);

    k_tx<<<dim3(HW / 32, CC / 32, BB), dim3(32, 8)>>>(x);
    k_prep<<<512, 256>>>(ow, mw, w);
    k_stage1t<<<BB * HH, 256, S1_TOTAL>>>(ob, mb);
    k_stage2<<<BB * HH * 2, 256, SM2_TOTAL>>>(out);
}

// round 12
// speedup vs baseline: 5.5903x; 1.0672x over previous
#include <cuda_runtime.h>
#include <cuda_bf16.h>
#include <cuda_fp16.h>
#include <cstdint>
#include <cstring>

#define BB 4
#define CC 128
#define HH 128
#define WW 128
#define OO 256
#define KKK 9
#define KDIM 1152
#define HW 16384

typedef unsigned long long ull;

__device__ __half g_xTh[BB * HW * CC];                    // NHWC x (fp16)
__device__ __align__(1024) uint32_t g_wBh[36 * 4096];     // stage2 B half image
__device__ __align__(1024) uint32_t g_wS1h[36 * 512];     // stage1 B half image
__device__ float g_posy[BB * HW * KKK];
__device__ float g_posx[BB * HW * KKK];
__device__ float g_mask[BB * HW * KKK];

__device__ __forceinline__ uint32_t swz(uint32_t o) { return o ^ ((o >> 3) & 0x70); }
__device__ __forceinline__ uint32_t smem_u32(const void* p) {
    uint32_t a;
    asm("{ .reg .u64 t; cvta.to.shared.u64 t, %1; cvt.u32.u64 %0, t; }" : "=r"(a) : "l"(p));
    return a;
}
__device__ __forceinline__ uint32_t h2pack(float a, float b) {
    __half2 h = __floats2half2_rn(a, b);
    uint32_t u; memcpy(&u, &h, 4); return u;
}
__device__ __forceinline__ void h8tof(uint4 u, float* o) {
    __half2 h0, h1, h2, h3;
    memcpy(&h0, &u.x, 4); memcpy(&h1, &u.y, 4); memcpy(&h2, &u.z, 4); memcpy(&h3, &u.w, 4);
    float2 f0 = __half22float2(h0), f1 = __half22float2(h1);
    float2 f2 = __half22float2(h2), f3 = __half22float2(h3);
    o[0] = f0.x; o[1] = f0.y; o[2] = f1.x; o[3] = f1.y;
    o[4] = f2.x; o[5] = f2.y; o[6] = f3.x; o[7] = f3.y;
}

#define MBAR_INIT(mb, c) asm volatile("mbarrier.init.shared.b64 [%0], %1;" :: "r"(mb), "r"((uint32_t)(c)) : "memory")
#define MBAR_EXPECT_TX(mb, by) asm volatile("mbarrier.arrive.expect_tx.shared.b64 _, [%0], %1;" :: "r"(mb), "r"((uint32_t)(by)) : "memory")
#define MBAR_WAIT(mb, par) do {                                                   \
    uint32_t _m = (mb); uint32_t _p = (par); uint32_t _d;                         \
    asm volatile("{\n\t.reg .pred p;\n\t"                                         \
        "mbarrier.try_wait.parity.acquire.cta.shared::cta.b64 p, [%1], %2;\n\t"   \
        "selp.b32 %0, 1, 0, p;\n\t}" : "=r"(_d) : "r"(_m), "r"(_p) : "memory");   \
    if (!_d) {                                                                    \
        asm volatile("{\n\t.reg .pred P1;\n\t"                                    \
            "WL_%=:\n\t"                                                          \
            "mbarrier.try_wait.parity.acquire.cta.shared::cta.b64 P1, [%0], %1, 0x989680;\n\t" \
            "@P1 bra.uni WD_%=;\n\t"                                              \
            "bra.uni WL_%=;\n\t"                                                  \
            "WD_%=:\n\t}" :: "r"(_m), "r"(_p) : "memory");                        \
    }                                                                             \
} while (0)

__device__ __forceinline__ void bulk_g2s(uint32_t dst, const void* src, uint32_t bytes, uint32_t mb) {
    uint64_t g = (uint64_t)__cvta_generic_to_global(src);
    asm volatile("cp.async.bulk.shared::cta.global.mbarrier::complete_tx::bytes [%0], [%1], %2, [%3];"
                 :: "r"(dst), "l"(g), "r"(bytes), "r"(mb) : "memory");
}
__device__ __forceinline__ void ldsm_x4(uint32_t& r0, uint32_t& r1, uint32_t& r2, uint32_t& r3, uint32_t addr) {
    asm volatile("ldmatrix.sync.aligned.m8n8.x4.shared.b16 {%0,%1,%2,%3}, [%4];"
                 : "=r"(r0), "=r"(r1), "=r"(r2), "=r"(r3) : "r"(addr));
}
__device__ __forceinline__ void mma_f16(float* c, const uint32_t* a, uint32_t b0, uint32_t b1) {
    asm volatile("mma.sync.aligned.m16n8k16.row.col.f32.f16.f16.f32 "
                 "{%0,%1,%2,%3}, {%4,%5,%6,%7}, {%8,%9}, {%0,%1,%2,%3};"
                 : "+f"(c[0]), "+f"(c[1]), "+f"(c[2]), "+f"(c[3])
                 : "r"(a[0]), "r"(a[1]), "r"(a[2]), "r"(a[3]), "r"(b0), "r"(b1));
}
__device__ __forceinline__ uint4 ldg128u(const void* p) {
    uint4 v;
    asm volatile("ld.global.nc.v4.u32 {%0,%1,%2,%3}, [%4];"
                 : "=r"(v.x), "=r"(v.y), "=r"(v.z), "=r"(v.w) : "l"(p));
    return v;
}

// ---------------- K0: NCHW fp32 -> NHWC fp16 ----------------
__global__ void k_tx(const float* __restrict__ x) {
    __shared__ float t[32][33];
    int b = blockIdx.z, c0 = blockIdx.y * 32, p0 = blockIdx.x * 32;
    int tx = threadIdx.x, ty = threadIdx.y;
#pragma unroll
    for (int i = 0; i < 32; i += 8)
        t[ty + i][tx] = x[(size_t)(b * CC + c0 + ty + i) * HW + p0 + tx];
    __syncthreads();
#pragma unroll
    for (int i = 0; i < 32; i += 8)
        g_xTh[(size_t)(b * HW + p0 + ty + i) * CC + c0 + tx] = __float2half(t[tx][ty + i]);
}

// ---------------- K0b: weight prep ----------------
__global__ void k_prep(const float* __restrict__ ow, const float* __restrict__ mw,
                       const float* __restrict__ w) {
    int stride = gridDim.x * blockDim.x;
    for (int i = blockIdx.x * blockDim.x + threadIdx.x; i < 36 * 4096; i += stride) {
        int ch = i >> 12, r = i & 4095;
        int n = r >> 4, k2 = (r & 15) << 1;
        int kk = ch >> 2;
        int c = ((ch & 3) << 5) + k2;
        float v0 = w[(n * CC + c) * KKK + kk];
        float v1 = w[(n * CC + c + 1) * KKK + kk];
        uint32_t phys = swz((uint32_t)((n << 6) + ((k2 >> 3) << 4))) + ((k2 & 7) << 1);
        g_wBh[(ch << 12) + (phys >> 2)] = h2pack(v0, v1);
    }
    for (int i = blockIdx.x * blockDim.x + threadIdx.x; i < 36 * 512; i += stride) {
        int ch = i >> 9, r = i & 511;
        int n = r >> 4, k2 = (r & 15) << 1;
        int kk = ch >> 2;
        int c = ((ch & 3) << 5) + k2;
        float v0 = 0.f, v1 = 0.f;
        if (n < 18)      { v0 = ow[n * KDIM + c * KKK + kk]; v1 = ow[n * KDIM + (c + 1) * KKK + kk]; }
        else if (n < 27) { v0 = mw[(n - 18) * KDIM + c * KKK + kk]; v1 = mw[(n - 18) * KDIM + (c + 1) * KKK + kk]; }
        uint32_t phys = swz((uint32_t)((n << 6) + ((k2 >> 3) << 4))) + ((k2 & 7) << 1);
        g_wS1h[(ch << 9) + (phys >> 2)] = h2pack(v0, v1);
    }
}

// ---------------- K1: fp16 tensorized offset/modulator conv ----------------
#define S1_B    0
#define S1_A0   73728
#define S1_A1   81920
#define S1_OUT  90112
#define S1_MBAR 107008
#define S1_TOTAL 107072

__global__ void __launch_bounds__(256, 2) k_stage1t(const float* __restrict__ ob_,
                                                    const float* __restrict__ mb_) {
    extern __shared__ __align__(16) char smem[];
    uint32_t sb = smem_u32(smem);
    int tid = threadIdx.x, wid = tid >> 5, lid = tid & 31;
    int bi = blockIdx.x, b = bi >> 7, ho = bi & 127;

    uint32_t mbar = sb + S1_MBAR;
    if (tid == 0) MBAR_INIT(mbar, 1);
    __syncthreads();
    if (tid == 0) { MBAR_EXPECT_TX(mbar, 73728); bulk_g2s(sb + S1_B, g_wS1h, 73728, mbar); }

    const __half* xb = g_xTh + (size_t)b * HW * CC;
    int l15 = lid & 15, lhi = lid >> 4;
    int u4 = tid & 3, mp = tid >> 2;     // 4 lanes per pixel, 64 pixels per pass

    auto gather1 = [&](int ch, uint32_t aslot) {
        int kk = ch >> 2;
        int ky = kk / 3, kx = kk - ky * 3;
        int c0 = (ch & 3) << 5;
        int hy = ho - 1 + ky;
        bool rowok = (unsigned)hy < 128u;
#pragma unroll
        for (int p = 0; p < 2; p++) {
            int m = (p << 6) + mp;
            int wx = m - 1 + kx;
            bool ok = rowok && ((unsigned)wx < 128u);
            uint4 v = make_uint4(0u, 0u, 0u, 0u);
            if (ok) v = *(const uint4*)(xb + (((hy << 7) + wx) << 7) + c0 + (u4 << 3));
            uint32_t ad = aslot + swz((uint32_t)((m << 6) + (u4 << 4)));
            asm volatile("st.shared.v4.b32 [%0], {%1, %2, %3, %4};"
                         :: "r"(ad), "r"(v.x), "r"(v.y), "r"(v.z), "r"(v.w) : "memory");
        }
    };

    float acc[4][4];
#pragma unroll
    for (int i = 0; i < 4; i++)
#pragma unroll
        for (int q = 0; q < 4; q++) acc[i][q] = 0.f;

    gather1(0, sb + S1_A0);
    __syncthreads();
    MBAR_WAIT(mbar, 0);

    for (int j = 0; j < 36; j++) {
        uint32_t Ab = sb + ((j & 1) ? S1_A1 : S1_A0);
        uint32_t Bb = sb + S1_B + (j << 11);
        if (j < 35) gather1(j + 1, sb + (((j + 1) & 1) ? S1_A1 : S1_A0));
#pragma unroll
        for (int s = 0; s < 2; s++) {
            int u = (s << 1) + lhi;
            uint32_t afr[4];
            {
                int r = (wid << 4) + l15;
                ldsm_x4(afr[0], afr[1], afr[2], afr[3], Ab + swz((uint32_t)((r << 6) + (u << 4))));
            }
            uint32_t bfr[2][4];
#pragma unroll
            for (int g = 0; g < 2; g++) {
                int r = (g << 4) + l15;
                ldsm_x4(bfr[g][0], bfr[g][1], bfr[g][2], bfr[g][3], Bb + swz((uint32_t)((r << 6) + (u << 4))));
            }
            mma_f16(acc[0], afr, bfr[0][0], bfr[0][2]);
            mma_f16(acc[1], afr, bfr[0][1], bfr[0][3]);
            mma_f16(acc[2], afr, bfr[1][0], bfr[1][2]);
            mma_f16(acc[3], afr, bfr[1][1], bfr[1][3]);
        }
        __syncthreads();
    }

    float* sOut = (float*)(smem + S1_OUT);
    int grp = lid >> 2, tig = lid & 3;
    int row0 = (wid << 4) + grp;
#pragma unroll
    for (int nb = 0; nb < 4; nb++) {
        int nb8 = nb << 3;
        sOut[(nb8 + (tig << 1)) * 132 + row0]         = acc[nb][0];
        sOut[(nb8 + (tig << 1) + 1) * 132 + row0]     = acc[nb][1];
        sOut[(nb8 + (tig << 1)) * 132 + row0 + 8]     = acc[nb][2];
        sOut[(nb8 + (tig << 1) + 1) * 132 + row0 + 8] = acc[nb][3];
    }
    __syncthreads();
    if (tid < 128) {
        int m = tid;
        int pixbase = (bi << 7) * 9 + m * 9;
#pragma unroll
        for (int kk = 0; kk < 9; kk++) {
            int ky = kk / 3, kx = kk - ky * 3;
            float vy = sOut[(2 * kk) * 132 + m] + ob_[2 * kk];
            float vx = sOut[(2 * kk + 1) * 132 + m] + ob_[2 * kk + 1];
            float vm = sOut[(18 + kk) * 132 + m] + mb_[kk];
            vm = 2.0f / (1.0f + expf(-vm));
            g_posy[pixbase + kk] = (float)(ho - 1 + ky) + vy;
            g_posx[pixbase + kk] = (float)(m - 1 + kx) + vx;
            g_mask[pixbase + kk] = vm;
        }
    }
}

// ---------------- K2: fp16 mma deformable GEMM, single-pass 16B gather ----------------
#define SM2_A0   0
#define SM2_A1   4096
#define SM2_B0   8192
#define SM2_B1   24576
#define SM2_TAP  40960
#define SM2_MBAR 59392
#define SM2_TOTAL 59456

struct G4q { uint4 a, e, f, g; };

__global__ void __launch_bounds__(256, 2) k_stage2(float* __restrict__ out) {
    extern __shared__ __align__(16) char smem[];
    uint32_t sb = smem_u32(smem);
    int tid = threadIdx.x, wid = tid >> 5, lid = tid & 31;
    int bi = blockIdx.x;
    int b = bi >> 8, ho = (bi >> 1) & 127, wo0 = (bi & 1) << 6;

    uint32_t mbar0 = sb + SM2_MBAR, mbar1 = sb + SM2_MBAR + 8;
    if (tid == 0) { MBAR_INIT(mbar0, 1); MBAR_INIT(mbar1, 1); }

    int4*   sIdx = (int4*)(smem + SM2_TAP);
    float4* sW   = (float4*)(smem + SM2_TAP + 9216);
    for (int t = tid; t < 576; t += 256) {
        int m = t / 9, kk = t - m * 9;
        int wo = wo0 + m;
        int pix = ((b * HH + ho) * WW + wo) * KKK + kk;
        float py = g_posy[pix], px = g_posx[pix], mk = g_mask[pix];
        float y0f = floorf(py), x0f = floorf(px);
        float fy = py - y0f, fx = px - x0f;
        int iy0 = (int)y0f, ix0 = (int)x0f;
        int iy1 = iy0 + 1, ix1 = ix0 + 1;
        bool vy0 = (unsigned)iy0 < 128u, vy1 = (unsigned)iy1 < 128u;
        bool vx0 = (unsigned)ix0 < 128u, vx1 = (unsigned)ix1 < 128u;
        int cy0 = min(max(iy0, 0), 127), cy1 = min(max(iy1, 0), 127);
        int cx0 = min(max(ix0, 0), 127), cx1 = min(max(ix1, 0), 127);
        float w00 = mk * (1.f - fy) * (1.f - fx) * ((vy0 && vx0) ? 1.f : 0.f);
        float w01 = mk * (1.f - fy) * fx         * ((vy0 && vx1) ? 1.f : 0.f);
        float w10 = mk * fy * (1.f - fx)         * ((vy1 && vx0) ? 1.f : 0.f);
        float w11 = mk * fy * fx                 * ((vy1 && vx1) ? 1.f : 0.f);
        sIdx[t] = make_int4((((cy0 << 7) + cx0) << 7), (((cy0 << 7) + cx1) << 7),
                            (((cy1 << 7) + cx0) << 7), (((cy1 << 7) + cx1) << 7));
        sW[t] = make_float4(w00, w01, w10, w11);
    }
    __syncthreads();
    if (tid == 0) {
        MBAR_EXPECT_TX(mbar0, 16384); bulk_g2s(sb + SM2_B0, g_wBh, 16384, mbar0);
        MBAR_EXPECT_TX(mbar1, 16384); bulk_g2s(sb + SM2_B1, g_wBh + 4096, 16384, mbar1);
    }

    const __half* xb = g_xTh + (size_t)b * HW * CC;
    int u4 = lid & 3;                  // 16B unit (8 halves) of 64B chunk-row
    int gm = (wid << 3) + (lid >> 2);  // pixel 0..63, one pass covers all

    auto g_issue = [&](int ch, G4q& r) {
        int t = gm * 9 + (ch >> 2);
        int4 ti = sIdx[t];
        int cA = ((ch & 3) << 5) + (u4 << 3);
        r.a = ldg128u(xb + ti.x + cA);
        r.e = ldg128u(xb + ti.y + cA);
        r.f = ldg128u(xb + ti.z + cA);
        r.g = ldg128u(xb + ti.w + cA);
    };
    auto g_store = [&](int ch, const G4q& d, uint32_t aslot) {
        int t = gm * 9 + (ch >> 2);
        float4 tw = sW[t];
        float av[8], ev[8], fv[8], qv[8];
        h8tof(d.a, av); h8tof(d.e, ev); h8tof(d.f, fv); h8tof(d.g, qv);
        float rv[8];
#pragma unroll
        for (int i = 0; i < 8; i++)
            rv[i] = fmaf(qv[i], tw.w, fmaf(fv[i], tw.z, fmaf(ev[i], tw.y, av[i] * tw.x)));
        uint32_t w0 = h2pack(rv[0], rv[1]), w1 = h2pack(rv[2], rv[3]);
        uint32_t w2 = h2pack(rv[4], rv[5]), w3 = h2pack(rv[6], rv[7]);
        uint32_t ad = aslot + swz((uint32_t)((gm << 6) + (u4 << 4)));
        asm volatile("st.shared.v4.b32 [%0], {%1, %2, %3, %4};"
                     :: "r"(ad), "r"(w0), "r"(w1), "r"(w2), "r"(w3) : "memory");
    };

    float acc[2][8][4];
#pragma unroll
    for (int i = 0; i < 2; i++)
#pragma unroll
        for (int j = 0; j < 8; j++)
#pragma unroll
            for (int q = 0; q < 4; q++) acc[i][j][q] = 0.f;

    int warp_m = wid & 1, warp_n = wid >> 1;
    int l15 = lid & 15, lhi = lid >> 4;

    {   // prologue: chunk 0
        G4q r0;
        g_issue(0, r0);
        g_store(0, r0, sb + SM2_A0);
    }
    __syncthreads();
    MBAR_WAIT(mbar0, 0);

    G4q pre;
    for (int j = 0; j < 36; j++) {
        uint32_t Ab = sb + ((j & 1) ? SM2_A1 : SM2_A0);
        uint32_t Bb = sb + ((j & 1) ? SM2_B1 : SM2_B0);
        uint32_t An = sb + (((j + 1) & 1) ? SM2_A1 : SM2_A0);
        if (j < 35) g_issue(j + 1, pre);          // ALL next-chunk loads issued before MMAs
#pragma unroll
        for (int s = 0; s < 2; s++) {
            int u = (s << 1) + lhi;
            uint32_t afr[2][4];
#pragma unroll
            for (int mf = 0; mf < 2; mf++) {
                int r = (warp_m << 5) + (mf << 4) + l15;
                ldsm_x4(afr[mf][0], afr[mf][1], afr[mf][2], afr[mf][3],
                        Ab + swz((uint32_t)((r << 6) + (u << 4))));
            }
            uint32_t bfr[4][4];
#pragma unroll
            for (int g = 0; g < 4; g++) {
                int r = (warp_n << 6) + (g << 4) + l15;
                ldsm_x4(bfr[g][0], bfr[g][1], bfr[g][2], bfr[g][3],
                        Bb + swz((uint32_t)((r << 6) + (u << 4))));
            }
#pragma unroll
            for (int mf = 0; mf < 2; mf++)
#pragma unroll
                for (int g = 0; g < 4; g++) {
                    mma_f16(acc[mf][2 * g],     afr[mf], bfr[g][0], bfr[g][2]);
                    mma_f16(acc[mf][2 * g + 1], afr[mf], bfr[g][1], bfr[g][3]);
                }
        }
        if (j < 35) g_store(j + 1, pre, An);
        __syncthreads();
        if (j + 2 < 36 && tid == 0) {
            uint32_t mb = (j & 1) ? mbar1 : mbar0;
            MBAR_EXPECT_TX(mb, 16384);
            bulk_g2s(sb + ((j & 1) ? SM2_B1 : SM2_B0), g_wBh + (size_t)(j + 2) * 4096, 16384, mb);
        }
        if (j < 35) {
            uint32_t mb = ((j + 1) & 1) ? mbar1 : mbar0;
            MBAR_WAIT(mb, (uint32_t)(((j + 1) >> 1) & 1));
        }
    }

    // epilogue: direct STG
    int grp = lid >> 2, tig = lid & 3;
#pragma unroll
    for (int mf = 0; mf < 2; mf++) {
#pragma unroll
        for (int nb = 0; nb < 8; nb++) {
            int mrow = (warp_m << 5) + (mf << 4) + grp;
            int n = (warp_n << 6) + (nb << 3) + (tig << 1);
            size_t o0 = ((size_t)(b * OO + n)) * HW + (ho << 7) + wo0;
            out[o0 + mrow]           = acc[mf][nb][0];
            out[o0 + HW + mrow]      = acc[mf][nb][1];
            out[o0 + mrow + 8]       = acc[mf][nb][2];
            out[o0 + HW + mrow + 8]  = acc[mf][nb][3];
        }
    }
}

// ---------------- host ----------------
extern "C" void kernel_launch(void* const* d_in, const int* in_sizes, int n_in,
                              void* d_out, int out_size) {
    (void)in_sizes; (void)n_in; (void)out_size;
    const float* x  = (const float*)d_in[0];
    const float* ow = (const float*)d_in[1];
    const float* ob = (const float*)d_in[2];
    const float* mw = (const float*)d_in[3];
    const float* mb = (const float*)d_in[4];
    const float* w  = (const float*)d_in[5];
    float* out = (float*)d_out;

    cudaFuncSetAttribute(k_stage1t, cudaFuncAttributeMaxDynamicSharedMemorySize, S1_TOTAL);
    cudaFuncSetAttribute(k_stage2, cudaFuncAttributeMaxDynamicSharedMemorySize, SM2_TOTAL);

    k_tx<<<dim3(HW / 32, CC / 32, BB), dim3(32, 8)>>>(x);
    k_prep<<<512, 256>>>(ow, mw, w);
    k_stage1t<<<BB * HH, 256, S1_TOTAL>>>(ob, mb);
    k_stage2<<<BB * HH * 2, 256, SM2_TOTAL>>>(out);
}

// round 16
// speedup vs baseline: 5.6868x; 1.0173x over previous
#include <cuda_runtime.h>
#include <cuda_bf16.h>
#include <cuda_fp16.h>
#include <cstdint>
#include <cstring>

#define BB 4
#define CC 128
#define HH 128
#define WW 128
#define OO 256
#define KKK 9
#define KDIM 1152
#define HW 16384

typedef unsigned long long ull;

__device__ __half g_xTh[BB * HW * CC];                    // NHWC x (fp16)
__device__ __align__(1024) uint32_t g_wBh[36 * 4096];     // stage2 B half image
__device__ __align__(1024) uint32_t g_wS1h[36 * 512];     // stage1 B half image
__device__ float g_posy[BB * HW * KKK];
__device__ float g_posx[BB * HW * KKK];
__device__ float g_mask[BB * HW * KKK];

__device__ __forceinline__ uint32_t swz(uint32_t o) { return o ^ ((o >> 3) & 0x70); }
__device__ __forceinline__ uint32_t smem_u32(const void* p) {
    uint32_t a;
    asm("{ .reg .u64 t; cvta.to.shared.u64 t, %1; cvt.u32.u64 %0, t; }" : "=r"(a) : "l"(p));
    return a;
}
__device__ __forceinline__ uint32_t h2pack(float a, float b) {
    __half2 h = __floats2half2_rn(a, b);
    uint32_t u; memcpy(&u, &h, 4); return u;
}
__device__ __forceinline__ void h8tof(uint4 u, float* o) {
    __half2 h0, h1, h2, h3;
    memcpy(&h0, &u.x, 4); memcpy(&h1, &u.y, 4); memcpy(&h2, &u.z, 4); memcpy(&h3, &u.w, 4);
    float2 f0 = __half22float2(h0), f1 = __half22float2(h1);
    float2 f2 = __half22float2(h2), f3 = __half22float2(h3);
    o[0] = f0.x; o[1] = f0.y; o[2] = f1.x; o[3] = f1.y;
    o[4] = f2.x; o[5] = f2.y; o[6] = f3.x; o[7] = f3.y;
}

#define MBAR_INIT(mb, c) asm volatile("mbarrier.init.shared.b64 [%0], %1;" :: "r"(mb), "r"((uint32_t)(c)) : "memory")
#define MBAR_EXPECT_TX(mb, by) asm volatile("mbarrier.arrive.expect_tx.shared.b64 _, [%0], %1;" :: "r"(mb), "r"((uint32_t)(by)) : "memory")
#define MBAR_WAIT(mb, par) do {                                                   \
    uint32_t _m = (mb); uint32_t _p = (par); uint32_t _d;                         \
    asm volatile("{\n\t.reg .pred p;\n\t"                                         \
        "mbarrier.try_wait.parity.acquire.cta.shared::cta.b64 p, [%1], %2;\n\t"   \
        "selp.b32 %0, 1, 0, p;\n\t}" : "=r"(_d) : "r"(_m), "r"(_p) : "memory");   \
    if (!_d) {                                                                    \
        asm volatile("{\n\t.reg .pred P1;\n\t"                                    \
            "WL_%=:\n\t"                                                          \
            "mbarrier.try_wait.parity.acquire.cta.shared::cta.b64 P1, [%0], %1, 0x989680;\n\t" \
            "@P1 bra.uni WD_%=;\n\t"                                              \
            "bra.uni WL_%=;\n\t"                                                  \
            "WD_%=:\n\t}" :: "r"(_m), "r"(_p) : "memory");                        \
    }                                                                             \
} while (0)

__device__ __forceinline__ void bulk_g2s(uint32_t dst, const void* src, uint32_t bytes, uint32_t mb) {
    uint64_t g = (uint64_t)__cvta_generic_to_global(src);
    asm volatile("cp.async.bulk.shared::cta.global.mbarrier::complete_tx::bytes [%0], [%1], %2, [%3];"
                 :: "r"(dst), "l"(g), "r"(bytes), "r"(mb) : "memory");
}
__device__ __forceinline__ void ldsm_x4(uint32_t& r0, uint32_t& r1, uint32_t& r2, uint32_t& r3, uint32_t addr) {
    asm volatile("ldmatrix.sync.aligned.m8n8.x4.shared.b16 {%0,%1,%2,%3}, [%4];"
                 : "=r"(r0), "=r"(r1), "=r"(r2), "=r"(r3) : "r"(addr));
}
__device__ __forceinline__ void mma_f16(float* c, const uint32_t* a, uint32_t b0, uint32_t b1) {
    asm volatile("mma.sync.aligned.m16n8k16.row.col.f32.f16.f16.f32 "
                 "{%0,%1,%2,%3}, {%4,%5,%6,%7}, {%8,%9}, {%0,%1,%2,%3};"
                 : "+f"(c[0]), "+f"(c[1]), "+f"(c[2]), "+f"(c[3])
                 : "r"(a[0]), "r"(a[1]), "r"(a[2]), "r"(a[3]), "r"(b0), "r"(b1));
}
__device__ __forceinline__ uint4 ldg128u(const void* p) {
    uint4 v;
    asm volatile("ld.global.nc.v4.u32 {%0,%1,%2,%3}, [%4];"
                 : "=r"(v.x), "=r"(v.y), "=r"(v.z), "=r"(v.w) : "l"(p));
    return v;
}

// ---------------- K0: NCHW fp32 -> NHWC fp16 ----------------
__global__ void k_tx(const float* __restrict__ x) {
    __shared__ float t[32][33];
    int b = blockIdx.z, c0 = blockIdx.y * 32, p0 = blockIdx.x * 32;
    int tx = threadIdx.x, ty = threadIdx.y;
#pragma unroll
    for (int i = 0; i < 32; i += 8)
        t[ty + i][tx] = x[(size_t)(b * CC + c0 + ty + i) * HW + p0 + tx];
    __syncthreads();
#pragma unroll
    for (int i = 0; i < 32; i += 8)
        g_xTh[(size_t)(b * HW + p0 + ty + i) * CC + c0 + tx] = __float2half(t[tx][ty + i]);
}

// ---------------- K0b: weight prep ----------------
__global__ void k_prep(const float* __restrict__ ow, const float* __restrict__ mw,
                       const float* __restrict__ w) {
    int stride = gridDim.x * blockDim.x;
    for (int i = blockIdx.x * blockDim.x + threadIdx.x; i < 36 * 4096; i += stride) {
        int ch = i >> 12, r = i & 4095;
        int n = r >> 4, k2 = (r & 15) << 1;
        int kk = ch >> 2;
        int c = ((ch & 3) << 5) + k2;
        float v0 = w[(n * CC + c) * KKK + kk];
        float v1 = w[(n * CC + c + 1) * KKK + kk];
        uint32_t phys = swz((uint32_t)((n << 6) + ((k2 >> 3) << 4))) + ((k2 & 7) << 1);
        g_wBh[(ch << 12) + (phys >> 2)] = h2pack(v0, v1);
    }
    for (int i = blockIdx.x * blockDim.x + threadIdx.x; i < 36 * 512; i += stride) {
        int ch = i >> 9, r = i & 511;
        int n = r >> 4, k2 = (r & 15) << 1;
        int kk = ch >> 2;
        int c = ((ch & 3) << 5) + k2;
        float v0 = 0.f, v1 = 0.f;
        if (n < 18)      { v0 = ow[n * KDIM + c * KKK + kk]; v1 = ow[n * KDIM + (c + 1) * KKK + kk]; }
        else if (n < 27) { v0 = mw[(n - 18) * KDIM + c * KKK + kk]; v1 = mw[(n - 18) * KDIM + (c + 1) * KKK + kk]; }
        uint32_t phys = swz((uint32_t)((n << 6) + ((k2 >> 3) << 4))) + ((k2 & 7) << 1);
        g_wS1h[(ch << 9) + (phys >> 2)] = h2pack(v0, v1);
    }
}

// ---------------- K1: fp16 tensorized offset/modulator conv ----------------
#define S1_B    0
#define S1_A0   73728
#define S1_A1   81920
#define S1_OUT  90112
#define S1_MBAR 107008
#define S1_TOTAL 107072

__global__ void __launch_bounds__(256, 2) k_stage1t(const float* __restrict__ ob_,
                                                    const float* __restrict__ mb_) {
    extern __shared__ __align__(16) char smem[];
    uint32_t sb = smem_u32(smem);
    int tid = threadIdx.x, wid = tid >> 5, lid = tid & 31;
    int bi = blockIdx.x, b = bi >> 7, ho = bi & 127;

    uint32_t mbar = sb + S1_MBAR;
    if (tid == 0) MBAR_INIT(mbar, 1);
    __syncthreads();
    if (tid == 0) { MBAR_EXPECT_TX(mbar, 73728); bulk_g2s(sb + S1_B, g_wS1h, 73728, mbar); }

    const __half* xb = g_xTh + (size_t)b * HW * CC;
    int l15 = lid & 15, lhi = lid >> 4;
    int u4 = tid & 3, mp = tid >> 2;     // 4 lanes per pixel, 64 pixels per pass

    // hoisted ldsm offsets: A[s], B[s][g]
    uint32_t offA1[2], offB1[2][2];
#pragma unroll
    for (int s = 0; s < 2; s++) {
        int u = (s << 1) + lhi;
        offA1[s] = swz((uint32_t)((((wid << 4) + l15) << 6) + (u << 4)));
#pragma unroll
        for (int g = 0; g < 2; g++)
            offB1[s][g] = swz((uint32_t)((((g << 4) + l15) << 6) + (u << 4)));
    }
    uint32_t stsOff1 = swz((uint32_t)((mp << 6) + (u4 << 4)));   // pass 0 (m=mp); pass1 = +64<<6

    auto gather1 = [&](int ch, uint32_t aslot) {
        int kk = ch >> 2;
        int ky = kk / 3, kx = kk - ky * 3;
        int c0 = (ch & 3) << 5;
        int hy = ho - 1 + ky;
        bool rowok = (unsigned)hy < 128u;
#pragma unroll
        for (int p = 0; p < 2; p++) {
            int m = (p << 6) + mp;
            int wx = m - 1 + kx;
            bool ok = rowok && ((unsigned)wx < 128u);
            uint4 v = make_uint4(0u, 0u, 0u, 0u);
            if (ok) v = *(const uint4*)(xb + (((hy << 7) + wx) << 7) + c0 + (u4 << 3));
            uint32_t ad = aslot + stsOff1 + (p << 12);
            asm volatile("st.shared.v4.b32 [%0], {%1, %2, %3, %4};"
                         :: "r"(ad), "r"(v.x), "r"(v.y), "r"(v.z), "r"(v.w) : "memory");
        }
    };

    float acc[4][4];
#pragma unroll
    for (int i = 0; i < 4; i++)
#pragma unroll
        for (int q = 0; q < 4; q++) acc[i][q] = 0.f;

    gather1(0, sb + S1_A0);
    __syncthreads();
    MBAR_WAIT(mbar, 0);

    for (int j = 0; j < 36; j++) {
        uint32_t Ab = sb + ((j & 1) ? S1_A1 : S1_A0);
        uint32_t Bb = sb + S1_B + (j << 11);
        if (j < 35) gather1(j + 1, sb + (((j + 1) & 1) ? S1_A1 : S1_A0));
#pragma unroll
        for (int s = 0; s < 2; s++) {
            uint32_t afr[4];
            ldsm_x4(afr[0], afr[1], afr[2], afr[3], Ab + offA1[s]);
            uint32_t bfr[2][4];
#pragma unroll
            for (int g = 0; g < 2; g++)
                ldsm_x4(bfr[g][0], bfr[g][1], bfr[g][2], bfr[g][3], Bb + offB1[s][g]);
            mma_f16(acc[0], afr, bfr[0][0], bfr[0][2]);
            mma_f16(acc[1], afr, bfr[0][1], bfr[0][3]);
            mma_f16(acc[2], afr, bfr[1][0], bfr[1][2]);
            mma_f16(acc[3], afr, bfr[1][1], bfr[1][3]);
        }
        __syncthreads();
    }

    float* sOut = (float*)(smem + S1_OUT);
    int grp = lid >> 2, tig = lid & 3;
    int row0 = (wid << 4) + grp;
#pragma unroll
    for (int nb = 0; nb < 4; nb++) {
        int nb8 = nb << 3;
        sOut[(nb8 + (tig << 1)) * 132 + row0]         = acc[nb][0];
        sOut[(nb8 + (tig << 1) + 1) * 132 + row0]     = acc[nb][1];
        sOut[(nb8 + (tig << 1)) * 132 + row0 + 8]     = acc[nb][2];
        sOut[(nb8 + (tig << 1) + 1) * 132 + row0 + 8] = acc[nb][3];
    }
    __syncthreads();
    if (tid < 128) {
        int m = tid;
        int pixbase = (bi << 7) * 9 + m * 9;
#pragma unroll
        for (int kk = 0; kk < 9; kk++) {
            int ky = kk / 3, kx = kk - ky * 3;
            float vy = sOut[(2 * kk) * 132 + m] + ob_[2 * kk];
            float vx = sOut[(2 * kk + 1) * 132 + m] + ob_[2 * kk + 1];
            float vm = sOut[(18 + kk) * 132 + m] + mb_[kk];
            vm = 2.0f / (1.0f + expf(-vm));
            g_posy[pixbase + kk] = (float)(ho - 1 + ky) + vy;
            g_posx[pixbase + kk] = (float)(m - 1 + kx) + vx;
            g_mask[pixbase + kk] = vm;
        }
    }
}

// ---------------- K2: fp16 mma deformable GEMM, hoisted addressing ----------------
#define SM2_A0   0
#define SM2_A1   4096
#define SM2_B0   8192
#define SM2_B1   24576
#define SM2_TAP  40960
#define SM2_MBAR 59392
#define SM2_TOTAL 59456

struct G4q { uint4 a, e, f, g; };

__global__ void __launch_bounds__(256, 2) k_stage2(float* __restrict__ out) {
    extern __shared__ __align__(16) char smem[];
    uint32_t sb = smem_u32(smem);
    int tid = threadIdx.x, wid = tid >> 5, lid = tid & 31;
    int bi = blockIdx.x;
    int b = bi >> 8, ho = (bi >> 1) & 127, wo0 = (bi & 1) << 6;

    uint32_t mbar0 = sb + SM2_MBAR, mbar1 = sb + SM2_MBAR + 8;
    if (tid == 0) { MBAR_INIT(mbar0, 1); MBAR_INIT(mbar1, 1); }

    int4*   sIdx = (int4*)(smem + SM2_TAP);
    float4* sW   = (float4*)(smem + SM2_TAP + 9216);
    for (int t = tid; t < 576; t += 256) {
        int m = t / 9, kk = t - m * 9;
        int wo = wo0 + m;
        int pix = ((b * HH + ho) * WW + wo) * KKK + kk;
        float py = g_posy[pix], px = g_posx[pix], mk = g_mask[pix];
        float y0f = floorf(py), x0f = floorf(px);
        float fy = py - y0f, fx = px - x0f;
        int iy0 = (int)y0f, ix0 = (int)x0f;
        int iy1 = iy0 + 1, ix1 = ix0 + 1;
        bool vy0 = (unsigned)iy0 < 128u, vy1 = (unsigned)iy1 < 128u;
        bool vx0 = (unsigned)ix0 < 128u, vx1 = (unsigned)ix1 < 128u;
        int cy0 = min(max(iy0, 0), 127), cy1 = min(max(iy1, 0), 127);
        int cx0 = min(max(ix0, 0), 127), cx1 = min(max(ix1, 0), 127);
        float w00 = mk * (1.f - fy) * (1.f - fx) * ((vy0 && vx0) ? 1.f : 0.f);
        float w01 = mk * (1.f - fy) * fx         * ((vy0 && vx1) ? 1.f : 0.f);
        float w10 = mk * fy * (1.f - fx)         * ((vy1 && vx0) ? 1.f : 0.f);
        float w11 = mk * fy * fx                 * ((vy1 && vx1) ? 1.f : 0.f);
        sIdx[t] = make_int4((((cy0 << 7) + cx0) << 7), (((cy0 << 7) + cx1) << 7),
                            (((cy1 << 7) + cx0) << 7), (((cy1 << 7) + cx1) << 7));
        sW[t] = make_float4(w00, w01, w10, w11);
    }
    __syncthreads();
    if (tid == 0) {
        MBAR_EXPECT_TX(mbar0, 16384); bulk_g2s(sb + SM2_B0, g_wBh, 16384, mbar0);
        MBAR_EXPECT_TX(mbar1, 16384); bulk_g2s(sb + SM2_B1, g_wBh + 4096, 16384, mbar1);
    }

    const __half* xb = g_xTh + (size_t)b * HW * CC;
    int u4 = lid & 3;
    int gm = (wid << 3) + (lid >> 2);
    int warp_m = wid & 1, warp_n = wid >> 1;
    int l15 = lid & 15, lhi = lid >> 4;

    // ---- hoisted ldsm offsets: A[s][mf], B[s][g] ----
    uint32_t offA[2][2], offB[2][4];
#pragma unroll
    for (int s = 0; s < 2; s++) {
        int u = (s << 1) + lhi;
#pragma unroll
        for (int mf = 0; mf < 2; mf++) {
            int r = (warp_m << 5) + (mf << 4) + l15;
            offA[s][mf] = swz((uint32_t)((r << 6) + (u << 4)));
        }
#pragma unroll
        for (int g = 0; g < 4; g++) {
            int r = (warp_n << 6) + (g << 4) + l15;
            offB[s][g] = swz((uint32_t)((r << 6) + (u << 4)));
        }
    }
    uint32_t stsOff = swz((uint32_t)((gm << 6) + (u4 << 4)));

    // ---- hoisted gather tap state (per kk) ----
    const __half *pa, *pe, *pf, *pg;
    float4 twc;
    auto load_tap = [&](int kkv) {
        int t = gm * 9 + kkv;
        int4 ti = sIdx[t];
        twc = sW[t];
        const __half* basep = xb + (u4 << 3);
        pa = basep + ti.x; pe = basep + ti.y; pf = basep + ti.z; pg = basep + ti.w;
    };
    auto g_issue = [&](int ch, G4q& r) {
        int off = (ch & 3) << 5;       // +32 channels per sub-chunk
        r.a = ldg128u(pa + off);
        r.e = ldg128u(pe + off);
        r.f = ldg128u(pf + off);
        r.g = ldg128u(pg + off);
    };
    auto g_store = [&](const G4q& d, uint32_t aslot) {
        float av[8], ev[8], fv[8], qv[8];
        h8tof(d.a, av); h8tof(d.e, ev); h8tof(d.f, fv); h8tof(d.g, qv);
        float rv[8];
#pragma unroll
        for (int i = 0; i < 8; i++)
            rv[i] = fmaf(qv[i], twc.w, fmaf(fv[i], twc.z, fmaf(ev[i], twc.y, av[i] * twc.x)));
        uint32_t w0 = h2pack(rv[0], rv[1]), w1 = h2pack(rv[2], rv[3]);
        uint32_t w2 = h2pack(rv[4], rv[5]), w3 = h2pack(rv[6], rv[7]);
        asm volatile("st.shared.v4.b32 [%0], {%1, %2, %3, %4};"
                     :: "r"(aslot + stsOff), "r"(w0), "r"(w1), "r"(w2), "r"(w3) : "memory");
    };

    float acc[2][8][4];
#pragma unroll
    for (int i = 0; i < 2; i++)
#pragma unroll
        for (int j = 0; j < 8; j++)
#pragma unroll
            for (int q = 0; q < 4; q++) acc[i][j][q] = 0.f;

    {   // prologue: chunk 0
        load_tap(0);
        G4q r0;
        g_issue(0, r0);
        g_store(r0, sb + SM2_A0);
    }
    __syncthreads();
    MBAR_WAIT(mbar0, 0);

    G4q pre;
    float4 twNext;   // weight for in-flight prefetch (tap may advance before store)
    for (int j = 0; j < 36; j++) {
        uint32_t Ab = sb + ((j & 1) ? SM2_A1 : SM2_A0);
        uint32_t Bb = sb + ((j & 1) ? SM2_B1 : SM2_B0);
        uint32_t An = sb + (((j + 1) & 1) ? SM2_A1 : SM2_A0);
        if (j < 35) {
            int ch = j + 1;
            if ((ch & 3) == 0) load_tap(ch >> 2);
            g_issue(ch, pre);
        }
#pragma unroll
        for (int s = 0; s < 2; s++) {
            uint32_t afr[2][4];
#pragma unroll
            for (int mf = 0; mf < 2; mf++)
                ldsm_x4(afr[mf][0], afr[mf][1], afr[mf][2], afr[mf][3], Ab + offA[s][mf]);
            uint32_t bfr[4][4];
#pragma unroll
            for (int g = 0; g < 4; g++)
                ldsm_x4(bfr[g][0], bfr[g][1], bfr[g][2], bfr[g][3], Bb + offB[s][g]);
#pragma unroll
            for (int mf = 0; mf < 2; mf++)
#pragma unroll
                for (int g = 0; g < 4; g++) {
                    mma_f16(acc[mf][2 * g],     afr[mf], bfr[g][0], bfr[g][2]);
                    mma_f16(acc[mf][2 * g + 1], afr[mf], bfr[g][1], bfr[g][3]);
                }
        }
        if (j < 35) g_store(pre, An);
        __syncthreads();
        if (j + 2 < 36 && tid == 0) {
            uint32_t mb = (j & 1) ? mbar1 : mbar0;
            MBAR_EXPECT_TX(mb, 16384);
            bulk_g2s(sb + ((j & 1) ? SM2_B1 : SM2_B0), g_wBh + (size_t)(j + 2) * 4096, 16384, mb);
        }
        if (j < 35) {
            uint32_t mb = ((j + 1) & 1) ? mbar1 : mbar0;
            MBAR_WAIT(mb, (uint32_t)(((j + 1) >> 1) & 1));
        }
    }
    (void)twNext;

    // epilogue: direct STG
    int grp = lid >> 2, tig = lid & 3;
#pragma unroll
    for (int mf = 0; mf < 2; mf++) {
#pragma unroll
        for (int nb = 0; nb < 8; nb++) {
            int mrow = (warp_m << 5) + (mf << 4) + grp;
            int n = (warp_n << 6) + (nb << 3) + (tig << 1);
            size_t o0 = ((size_t)(b * OO + n)) * HW + (ho << 7) + wo0;
            out[o0 + mrow]           = acc[mf][nb][0];
            out[o0 + HW + mrow]      = acc[mf][nb][1];
            out[o0 + mrow + 8]       = acc[mf][nb][2];
            out[o0 + HW + mrow + 8]  = acc[mf][nb][3];
        }
    }
}

// ---------------- host ----------------
extern "C" void kernel_launch(void* const* d_in, const int* in_sizes, int n_in,
                              void* d_out, int out_size) {
    (void)in_sizes; (void)n_in; (void)out_size;
    const float* x  = (const float*)d_in[0];
    const float* ow = (const float*)d_in[1];
    const float* ob = (const float*)d_in[2];
    const float* mw = (const float*)d_in[3];
    const float* mb = (const float*)d_in[4];
    const float* w  = (const float*)d_in[5];
    float* out = (float*)d_out;

    cudaFuncSetAttribute(k_stage1t, cudaFuncAttributeMaxDynamicSharedMemorySize, S1_TOTAL);
    cudaFuncSetAttribute(k_stage2, cudaFuncAttributeMaxDynamicSharedMemorySize, SM2_TOTAL);

    k_tx<<<dim3(HW / 32, CC / 32, BB), dim3(32, 8)>>>(x);
    k_prep<<<512, 256>>>(ow, mw, w);
    k_stage1t<<<BB * HH, 256, S1_TOTAL>>>(ob, mb);
    k_stage2<<<BB * HH * 2, 256, SM2_TOTAL>>>(out);
}

// round 17
// speedup vs baseline: 5.7200x; 1.0058x over previous
#include <cuda_runtime.h>
#include <cuda_bf16.h>
#include <cuda_fp16.h>
#include <cstdint>
#include <cstring>

#define BB 4
#define CC 128
#define HH 128
#define WW 128
#define OO 256
#define KKK 9
#define KDIM 1152
#define HW 16384

typedef unsigned long long ull;

__device__ __half g_xTh[BB * HW * CC];                    // NHWC x (fp16)
__device__ __align__(1024) uint32_t g_wBh[36 * 4096];     // stage2 B half image
__device__ __align__(1024) uint32_t g_wS1h[36 * 512];     // stage1 B half image
__device__ float g_posy[BB * HW * KKK];
__device__ float g_posx[BB * HW * KKK];
__device__ float g_mask[BB * HW * KKK];

__device__ __forceinline__ uint32_t swz(uint32_t o) { return o ^ ((o >> 3) & 0x70); }
__device__ __forceinline__ uint32_t smem_u32(const void* p) {
    uint32_t a;
    asm("{ .reg .u64 t; cvta.to.shared.u64 t, %1; cvt.u32.u64 %0, t; }" : "=r"(a) : "l"(p));
    return a;
}
__device__ __forceinline__ uint32_t h2pack(float a, float b) {
    __half2 h = __floats2half2_rn(a, b);
    uint32_t u; memcpy(&u, &h, 4); return u;
}
__device__ __forceinline__ __half2 u2h2(uint32_t u) {
    __half2 h; memcpy(&h, &u, 4); return h;
}
__device__ __forceinline__ uint32_t h22u(__half2 h) {
    uint32_t u; memcpy(&u, &h, 4); return u;
}

#define MBAR_INIT(mb, c) asm volatile("mbarrier.init.shared.b64 [%0], %1;" :: "r"(mb), "r"((uint32_t)(c)) : "memory")
#define MBAR_EXPECT_TX(mb, by) asm volatile("mbarrier.arrive.expect_tx.shared.b64 _, [%0], %1;" :: "r"(mb), "r"((uint32_t)(by)) : "memory")
#define MBAR_WAIT(mb, par) do {                                                   \
    uint32_t _m = (mb); uint32_t _p = (par); uint32_t _d;                         \
    asm volatile("{\n\t.reg .pred p;\n\t"                                         \
        "mbarrier.try_wait.parity.acquire.cta.shared::cta.b64 p, [%1], %2;\n\t"   \
        "selp.b32 %0, 1, 0, p;\n\t}" : "=r"(_d) : "r"(_m), "r"(_p) : "memory");   \
    if (!_d) {                                                                    \
        asm volatile("{\n\t.reg .pred P1;\n\t"                                    \
            "WL_%=:\n\t"                                                          \
            "mbarrier.try_wait.parity.acquire.cta.shared::cta.b64 P1, [%0], %1, 0x989680;\n\t" \
            "@P1 bra.uni WD_%=;\n\t"                                              \
            "bra.uni WL_%=;\n\t"                                                  \
            "WD_%=:\n\t}" :: "r"(_m), "r"(_p) : "memory");                        \
    }                                                                             \
} while (0)

__device__ __forceinline__ void bulk_g2s(uint32_t dst, const void* src, uint32_t bytes, uint32_t mb) {
    uint64_t g = (uint64_t)__cvta_generic_to_global(src);
    asm volatile("cp.async.bulk.shared::cta.global.mbarrier::complete_tx::bytes [%0], [%1], %2, [%3];"
                 :: "r"(dst), "l"(g), "r"(bytes), "r"(mb) : "memory");
}
__device__ __forceinline__ void ldsm_x4(uint32_t& r0, uint32_t& r1, uint32_t& r2, uint32_t& r3, uint32_t addr) {
    asm volatile("ldmatrix.sync.aligned.m8n8.x4.shared.b16 {%0,%1,%2,%3}, [%4];"
                 : "=r"(r0), "=r"(r1), "=r"(r2), "=r"(r3) : "r"(addr));
}
__device__ __forceinline__ void mma_f16(float* c, const uint32_t* a, uint32_t b0, uint32_t b1) {
    asm volatile("mma.sync.aligned.m16n8k16.row.col.f32.f16.f16.f32 "
                 "{%0,%1,%2,%3}, {%4,%5,%6,%7}, {%8,%9}, {%0,%1,%2,%3};"
                 : "+f"(c[0]), "+f"(c[1]), "+f"(c[2]), "+f"(c[3])
                 : "r"(a[0]), "r"(a[1]), "r"(a[2]), "r"(a[3]), "r"(b0), "r"(b1));
}
__device__ __forceinline__ uint4 ldg128u(const void* p) {
    uint4 v;
    asm volatile("ld.global.nc.v4.u32 {%0,%1,%2,%3}, [%4];"
                 : "=r"(v.x), "=r"(v.y), "=r"(v.z), "=r"(v.w) : "l"(p));
    return v;
}

// ---------------- K0: NCHW fp32 -> NHWC fp16 ----------------
__global__ void k_tx(const float* __restrict__ x) {
    __shared__ float t[32][33];
    int b = blockIdx.z, c0 = blockIdx.y * 32, p0 = blockIdx.x * 32;
    int tx = threadIdx.x, ty = threadIdx.y;
#pragma unroll
    for (int i = 0; i < 32; i += 8)
        t[ty + i][tx] = x[(size_t)(b * CC + c0 + ty + i) * HW + p0 + tx];
    __syncthreads();
#pragma unroll
    for (int i = 0; i < 32; i += 8)
        g_xTh[(size_t)(b * HW + p0 + ty + i) * CC + c0 + tx] = __float2half(t[tx][ty + i]);
}

// ---------------- K0b: weight prep ----------------
__global__ void k_prep(const float* __restrict__ ow, const float* __restrict__ mw,
                       const float* __restrict__ w) {
    int stride = gridDim.x * blockDim.x;
    for (int i = blockIdx.x * blockDim.x + threadIdx.x; i < 36 * 4096; i += stride) {
        int ch = i >> 12, r = i & 4095;
        int n = r >> 4, k2 = (r & 15) << 1;
        int kk = ch >> 2;
        int c = ((ch & 3) << 5) + k2;
        float v0 = w[(n * CC + c) * KKK + kk];
        float v1 = w[(n * CC + c + 1) * KKK + kk];
        uint32_t phys = swz((uint32_t)((n << 6) + ((k2 >> 3) << 4))) + ((k2 & 7) << 1);
        g_wBh[(ch << 12) + (phys >> 2)] = h2pack(v0, v1);
    }
    for (int i = blockIdx.x * blockDim.x + threadIdx.x; i < 36 * 512; i += stride) {
        int ch = i >> 9, r = i & 511;
        int n = r >> 4, k2 = (r & 15) << 1;
        int kk = ch >> 2;
        int c = ((ch & 3) << 5) + k2;
        float v0 = 0.f, v1 = 0.f;
        if (n < 18)      { v0 = ow[n * KDIM + c * KKK + kk]; v1 = ow[n * KDIM + (c + 1) * KKK + kk]; }
        else if (n < 27) { v0 = mw[(n - 18) * KDIM + c * KKK + kk]; v1 = mw[(n - 18) * KDIM + (c + 1) * KKK + kk]; }
        uint32_t phys = swz((uint32_t)((n << 6) + ((k2 >> 3) << 4))) + ((k2 & 7) << 1);
        g_wS1h[(ch << 9) + (phys >> 2)] = h2pack(v0, v1);
    }
}

// ---------------- K1: fp16 tensorized offset/modulator conv ----------------
#define S1_B    0
#define S1_A0   73728
#define S1_A1   81920
#define S1_OUT  90112
#define S1_MBAR 107008
#define S1_TOTAL 107072

__global__ void __launch_bounds__(256, 2) k_stage1t(const float* __restrict__ ob_,
                                                    const float* __restrict__ mb_) {
    extern __shared__ __align__(16) char smem[];
    uint32_t sb = smem_u32(smem);
    int tid = threadIdx.x, wid = tid >> 5, lid = tid & 31;
    int bi = blockIdx.x, b = bi >> 7, ho = bi & 127;

    uint32_t mbar = sb + S1_MBAR;
    if (tid == 0) MBAR_INIT(mbar, 1);
    __syncthreads();
    if (tid == 0) { MBAR_EXPECT_TX(mbar, 73728); bulk_g2s(sb + S1_B, g_wS1h, 73728, mbar); }

    const __half* xb = g_xTh + (size_t)b * HW * CC;
    int l15 = lid & 15, lhi = lid >> 4;
    int u4 = tid & 3, mp = tid >> 2;

    uint32_t offA1[2], offB1[2][2];
#pragma unroll
    for (int s = 0; s < 2; s++) {
        int u = (s << 1) + lhi;
        offA1[s] = swz((uint32_t)((((wid << 4) + l15) << 6) + (u << 4)));
#pragma unroll
        for (int g = 0; g < 2; g++)
            offB1[s][g] = swz((uint32_t)((((g << 4) + l15) << 6) + (u << 4)));
    }
    uint32_t stsOff1 = swz((uint32_t)((mp << 6) + (u4 << 4)));

    auto gather1 = [&](int ch, uint32_t aslot) {
        int kk = ch >> 2;
        int ky = kk / 3, kx = kk - ky * 3;
        int c0 = (ch & 3) << 5;
        int hy = ho - 1 + ky;
        bool rowok = (unsigned)hy < 128u;
#pragma unroll
        for (int p = 0; p < 2; p++) {
            int m = (p << 6) + mp;
            int wx = m - 1 + kx;
            bool ok = rowok && ((unsigned)wx < 128u);
            uint4 v = make_uint4(0u, 0u, 0u, 0u);
            if (ok) v = *(const uint4*)(xb + (((hy << 7) + wx) << 7) + c0 + (u4 << 3));
            uint32_t ad = aslot + stsOff1 + (p << 12);
            asm volatile("st.shared.v4.b32 [%0], {%1, %2, %3, %4};"
                         :: "r"(ad), "r"(v.x), "r"(v.y), "r"(v.z), "r"(v.w) : "memory");
        }
    };

    float acc[4][4];
#pragma unroll
    for (int i = 0; i < 4; i++)
#pragma unroll
        for (int q = 0; q < 4; q++) acc[i][q] = 0.f;

    gather1(0, sb + S1_A0);
    __syncthreads();
    MBAR_WAIT(mbar, 0);

    for (int j = 0; j < 36; j++) {
        uint32_t Ab = sb + ((j & 1) ? S1_A1 : S1_A0);
        uint32_t Bb = sb + S1_B + (j << 11);
        if (j < 35) gather1(j + 1, sb + (((j + 1) & 1) ? S1_A1 : S1_A0));
#pragma unroll
        for (int s = 0; s < 2; s++) {
            uint32_t afr[4];
            ldsm_x4(afr[0], afr[1], afr[2], afr[3], Ab + offA1[s]);
            uint32_t bfr[2][4];
#pragma unroll
            for (int g = 0; g < 2; g++)
                ldsm_x4(bfr[g][0], bfr[g][1], bfr[g][2], bfr[g][3], Bb + offB1[s][g]);
            mma_f16(acc[0], afr, bfr[0][0], bfr[0][2]);
            mma_f16(acc[1], afr, bfr[0][1], bfr[0][3]);
            mma_f16(acc[2], afr, bfr[1][0], bfr[1][2]);
            mma_f16(acc[3], afr, bfr[1][1], bfr[1][3]);
        }
        __syncthreads();
    }

    float* sOut = (float*)(smem + S1_OUT);
    int grp = lid >> 2, tig = lid & 3;
    int row0 = (wid << 4) + grp;
#pragma unroll
    for (int nb = 0; nb < 4; nb++) {
        int nb8 = nb << 3;
        sOut[(nb8 + (tig << 1)) * 132 + row0]         = acc[nb][0];
        sOut[(nb8 + (tig << 1) + 1) * 132 + row0]     = acc[nb][1];
        sOut[(nb8 + (tig << 1)) * 132 + row0 + 8]     = acc[nb][2];
        sOut[(nb8 + (tig << 1) + 1) * 132 + row0 + 8] = acc[nb][3];
    }
    __syncthreads();
    if (tid < 128) {
        int m = tid;
        int pixbase = (bi << 7) * 9 + m * 9;
#pragma unroll
        for (int kk = 0; kk < 9; kk++) {
            int ky = kk / 3, kx = kk - ky * 3;
            float vy = sOut[(2 * kk) * 132 + m] + ob_[2 * kk];
            float vx = sOut[(2 * kk + 1) * 132 + m] + ob_[2 * kk + 1];
            float vm = sOut[(18 + kk) * 132 + m] + mb_[kk];
            vm = 2.0f / (1.0f + expf(-vm));
            g_posy[pixbase + kk] = (float)(ho - 1 + ky) + vy;
            g_posx[pixbase + kk] = (float)(m - 1 + kx) + vx;
            g_mask[pixbase + kk] = vm;
        }
    }
}

// ---------------- K2: fp16 mma deformable GEMM, HFMA2 interp ----------------
#define SM2_A0   0
#define SM2_A1   4096
#define SM2_B0   8192
#define SM2_B1   24576
#define SM2_TAP  40960
#define SM2_MBAR 59392
#define SM2_TOTAL 59456

struct G4q { uint4 a, e, f, g; };

__global__ void __launch_bounds__(256, 2) k_stage2(float* __restrict__ out) {
    extern __shared__ __align__(16) char smem[];
    uint32_t sb = smem_u32(smem);
    int tid = threadIdx.x, wid = tid >> 5, lid = tid & 31;
    int bi = blockIdx.x;
    int b = bi >> 8, ho = (bi >> 1) & 127, wo0 = (bi & 1) << 6;

    uint32_t mbar0 = sb + SM2_MBAR, mbar1 = sb + SM2_MBAR + 8;
    if (tid == 0) { MBAR_INIT(mbar0, 1); MBAR_INIT(mbar1, 1); }

    int4*   sIdx = (int4*)(smem + SM2_TAP);
    float4* sW   = (float4*)(smem + SM2_TAP + 9216);
    for (int t = tid; t < 576; t += 256) {
        int m = t / 9, kk = t - m * 9;
        int wo = wo0 + m;
        int pix = ((b * HH + ho) * WW + wo) * KKK + kk;
        float py = g_posy[pix], px = g_posx[pix], mk = g_mask[pix];
        float y0f = floorf(py), x0f = floorf(px);
        float fy = py - y0f, fx = px - x0f;
        int iy0 = (int)y0f, ix0 = (int)x0f;
        int iy1 = iy0 + 1, ix1 = ix0 + 1;
        bool vy0 = (unsigned)iy0 < 128u, vy1 = (unsigned)iy1 < 128u;
        bool vx0 = (unsigned)ix0 < 128u, vx1 = (unsigned)ix1 < 128u;
        int cy0 = min(max(iy0, 0), 127), cy1 = min(max(iy1, 0), 127);
        int cx0 = min(max(ix0, 0), 127), cx1 = min(max(ix1, 0), 127);
        float w00 = mk * (1.f - fy) * (1.f - fx) * ((vy0 && vx0) ? 1.f : 0.f);
        float w01 = mk * (1.f - fy) * fx         * ((vy0 && vx1) ? 1.f : 0.f);
        float w10 = mk * fy * (1.f - fx)         * ((vy1 && vx0) ? 1.f : 0.f);
        float w11 = mk * fy * fx                 * ((vy1 && vx1) ? 1.f : 0.f);
        sIdx[t] = make_int4((((cy0 << 7) + cx0) << 7), (((cy0 << 7) + cx1) << 7),
                            (((cy1 << 7) + cx0) << 7), (((cy1 << 7) + cx1) << 7));
        sW[t] = make_float4(w00, w01, w10, w11);
    }
    __syncthreads();
    if (tid == 0) {
        MBAR_EXPECT_TX(mbar0, 16384); bulk_g2s(sb + SM2_B0, g_wBh, 16384, mbar0);
        MBAR_EXPECT_TX(mbar1, 16384); bulk_g2s(sb + SM2_B1, g_wBh + 4096, 16384, mbar1);
    }

    const __half* xb = g_xTh + (size_t)b * HW * CC;
    int u4 = lid & 3;
    int gm = (wid << 3) + (lid >> 2);
    int warp_m = wid & 1, warp_n = wid >> 1;
    int l15 = lid & 15, lhi = lid >> 4;

    uint32_t offA[2][2], offB[2][4];
#pragma unroll
    for (int s = 0; s < 2; s++) {
        int u = (s << 1) + lhi;
#pragma unroll
        for (int mf = 0; mf < 2; mf++) {
            int r = (warp_m << 5) + (mf << 4) + l15;
            offA[s][mf] = swz((uint32_t)((r << 6) + (u << 4)));
        }
#pragma unroll
        for (int g = 0; g < 4; g++) {
            int r = (warp_n << 6) + (g << 4) + l15;
            offB[s][g] = swz((uint32_t)((r << 6) + (u << 4)));
        }
    }
    uint32_t stsOff = swz((uint32_t)((gm << 6) + (u4 << 4)));

    // ---- hoisted gather tap state (per kk): pointers + HALF2 weights ----
    const __half *pa, *pe, *pf, *pg;
    __half2 hw00, hw01, hw10, hw11;
    auto load_tap = [&](int kkv) {
        int t = gm * 9 + kkv;
        int4 ti = sIdx[t];
        float4 tw = sW[t];
        hw00 = __float2half2_rn(tw.x);
        hw01 = __float2half2_rn(tw.y);
        hw10 = __float2half2_rn(tw.z);
        hw11 = __float2half2_rn(tw.w);
        const __half* basep = xb + (u4 << 3);
        pa = basep + ti.x; pe = basep + ti.y; pf = basep + ti.z; pg = basep + ti.w;
    };
    auto g_issue = [&](int ch, G4q& r) {
        int off = (ch & 3) << 5;
        r.a = ldg128u(pa + off);
        r.e = ldg128u(pe + off);
        r.f = ldg128u(pf + off);
        r.g = ldg128u(pg + off);
    };
    auto g_store = [&](const G4q& d, uint32_t aslot) {
        const uint32_t* au = (const uint32_t*)&d.a;
        const uint32_t* eu = (const uint32_t*)&d.e;
        const uint32_t* fu = (const uint32_t*)&d.f;
        const uint32_t* gu = (const uint32_t*)&d.g;
        uint32_t rv[4];
#pragma unroll
        for (int i = 0; i < 4; i++) {
            __half2 r = __hmul2(u2h2(au[i]), hw00);
            r = __hfma2(u2h2(eu[i]), hw01, r);
            r = __hfma2(u2h2(fu[i]), hw10, r);
            r = __hfma2(u2h2(gu[i]), hw11, r);
            rv[i] = h22u(r);
        }
        asm volatile("st.shared.v4.b32 [%0], {%1, %2, %3, %4};"
                     :: "r"(aslot + stsOff), "r"(rv[0]), "r"(rv[1]), "r"(rv[2]), "r"(rv[3]) : "memory");
    };

    float acc[2][8][4];
#pragma unroll
    for (int i = 0; i < 2; i++)
#pragma unroll
        for (int j = 0; j < 8; j++)
#pragma unroll
            for (int q = 0; q < 4; q++) acc[i][j][q] = 0.f;

    {   // prologue: chunk 0
        load_tap(0);
        G4q r0;
        g_issue(0, r0);
        g_store(r0, sb + SM2_A0);
    }
    __syncthreads();
    MBAR_WAIT(mbar0, 0);

    G4q pre;
    for (int j = 0; j < 36; j++) {
        uint32_t Ab = sb + ((j & 1) ? SM2_A1 : SM2_A0);
        uint32_t Bb = sb + ((j & 1) ? SM2_B1 : SM2_B0);
        uint32_t An = sb + (((j + 1) & 1) ? SM2_A1 : SM2_A0);
        if (j < 35) {
            int ch = j + 1;
            if ((ch & 3) == 0) load_tap(ch >> 2);
            g_issue(ch, pre);
        }
#pragma unroll
        for (int s = 0; s < 2; s++) {
            uint32_t afr[2][4];
#pragma unroll
            for (int mf = 0; mf < 2; mf++)
                ldsm_x4(afr[mf][0], afr[mf][1], afr[mf][2], afr[mf][3], Ab + offA[s][mf]);
            uint32_t bfr[4][4];
#pragma unroll
            for (int g = 0; g < 4; g++)
                ldsm_x4(bfr[g][0], bfr[g][1], bfr[g][2], bfr[g][3], Bb + offB[s][g]);
#pragma unroll
            for (int mf = 0; mf < 2; mf++)
#pragma unroll
                for (int g = 0; g < 4; g++) {
                    mma_f16(acc[mf][2 * g],     afr[mf], bfr[g][0], bfr[g][2]);
                    mma_f16(acc[mf][2 * g + 1], afr[mf], bfr[g][1], bfr[g][3]);
                }
        }
        if (j < 35) g_store(pre, An);
        __syncthreads();
        if (j + 2 < 36 && tid == 0) {
            uint32_t mb = (j & 1) ? mbar1 : mbar0;
            MBAR_EXPECT_TX(mb, 16384);
            bulk_g2s(sb + ((j & 1) ? SM2_B1 : SM2_B0), g_wBh + (size_t)(j + 2) * 4096, 16384, mb);
        }
        if (j < 35) {
            uint32_t mb = ((j + 1) & 1) ? mbar1 : mbar0;
            MBAR_WAIT(mb, (uint32_t)(((j + 1) >> 1) & 1));
        }
    }

    // epilogue: direct STG
    int grp = lid >> 2, tig = lid & 3;
#pragma unroll
    for (int mf = 0; mf < 2; mf++) {
#pragma unroll
        for (int nb = 0; nb < 8; nb++) {
            int mrow = (warp_m << 5) + (mf << 4) + grp;
            int n = (warp_n << 6) + (nb << 3) + (tig << 1);
            size_t o0 = ((size_t)(b * OO + n)) * HW + (ho << 7) + wo0;
            out[o0 + mrow]           = acc[mf][nb][0];
            out[o0 + HW + mrow]      = acc[mf][nb][1];
            out[o0 + mrow + 8]       = acc[mf][nb][2];
            out[o0 + HW + mrow + 8]  = acc[mf][nb][3];
        }
    }
}

// ---------------- host ----------------
extern "C" void kernel_launch(void* const* d_in, const int* in_sizes, int n_in,
                              void* d_out, int out_size) {
    (void)in_sizes; (void)n_in; (void)out_size;
    const float* x  = (const float*)d_in[0];
    const float* ow = (const float*)d_in[1];
    const float* ob = (const float*)d_in[2];
    const float* mw = (const float*)d_in[3];
    const float* mb = (const float*)d_in[4];
    const float* w  = (const float*)d_in[5];
    float* out = (float*)d_out;

    cudaFuncSetAttribute(k_stage1t, cudaFuncAttributeMaxDynamicSharedMemorySize, S1_TOTAL);
    cudaFuncSetAttribute(k_stage2, cudaFuncAttributeMaxDynamicSharedMemorySize, SM2_TOTAL);

    k_tx<<<dim3(HW / 32, CC / 32, BB), dim3(32, 8)>>>(x);
    k_prep<<<512, 256>>>(ow, mw, w);
    k_stage1t<<<BB * HH, 256, S1_TOTAL>>>(ob, mb);
    k_stage2<<<BB * HH * 2, 256, SM2_TOTAL>>>(out);
}